// round 1
// baseline (speedup 1.0000x reference)
#include <cuda_runtime.h>
#include <math.h>

// Problem constants
#define Bb   8
#define Dd   49
#define Cch  512
#define Nn   12
#define Hh   256          // C/2
#define Ee   144          // N*N
#define ND   392          // B*D
#define RQ   4704         // N*B*D
#define SCALE_ 0.0625f    // (C/2)^-0.5
#define EPS_  1e-5f

// ---------------- static device scratch (no allocations allowed) -------------
__device__ float g_h[RQ * Cch];        // h, then f_u in place   layout [(n*8+b)*49+d][c]
__device__ float g_q1[RQ * Hh];
__device__ float g_k1[ND * Hh];        // [(b*49+d)][h]
__device__ float g_v1[ND * Cch];
__device__ float g_feat1[RQ * Cch];
__device__ float g_Q2[RQ * Hh];
__device__ float g_K2[RQ * Hh];
__device__ float g_Vp[RQ * Cch];       // feat1 @ (arm_wv@ep_w) + arm_bv@ep_w
__device__ float g_Wvp[Cch * Cch];
__device__ float g_bvp[Cch];
__device__ float g_fv[Bb * Nn * Cch];  // [(b*12+n)][c]
__device__ float g_zbar[Bb * Ee * Cch];// [(b*144+e)][c]
__device__ float g_ps1[Bb * Ee];
__device__ float g_ps2[Bb * Ee];
__device__ float g_bn1m[Nn * Cch];
__device__ float g_bn1r[Nn * Cch];
__device__ float g_mask[Bb * Ee];
__device__ float g_fe[Bb * Ee * Cch];  // edge features (ed), updated in place
__device__ float g_xa[Bb * Nn * Cch];
__device__ float g_xb[Bb * Nn * Cch];
__device__ float g_xu[Bb * Nn * Cch];
__device__ float g_xvv[Bb * Nn * Cch];
__device__ float g_xw[Bb * Ee * Cch];
__device__ float g_agg[Bb * Ee * Cch];
__device__ float g_msg[Bb * Nn * Cch];
__device__ float g_t[Bb * Nn * Cch];

// ---------------- helpers ----------------------------------------------------
__device__ __forceinline__ float block_reduce_sum(float v, float* sm) {
    int lane = threadIdx.x & 31, w = threadIdx.x >> 5;
#pragma unroll
    for (int o = 16; o; o >>= 1) v += __shfl_xor_sync(0xffffffffu, v, o);
    if (lane == 0) sm[w] = v;
    __syncthreads();
    int nw = (blockDim.x + 31) >> 5;
    float r = 0.f;
    if (threadIdx.x < 32) {
        r = (threadIdx.x < nw) ? sm[threadIdx.x] : 0.f;
#pragma unroll
        for (int o = 16; o; o >>= 1) r += __shfl_xor_sync(0xffffffffu, r, o);
        if (threadIdx.x == 0) sm[0] = r;
    }
    __syncthreads();
    r = sm[0];
    __syncthreads();
    return r;
}

// ---------------- generic tiled GEMM: C = A(MxK) @ B(KxN) + bias -------------
// 64x64 tile, BK=16, 256 threads, 4x4 micro-tile. Optional z-batching via strides.
__global__ void gemm_kernel(const float* __restrict__ A, const float* __restrict__ Bm,
                            const float* __restrict__ bias, float* __restrict__ Cm,
                            int M, int Np, int K,
                            long sA, long sB, long sBias, long sC)
{
    const float* Az = A + (long)blockIdx.z * sA;
    const float* Bz = Bm + (long)blockIdx.z * sB;
    float* Cz = Cm + (long)blockIdx.z * sC;
    __shared__ float As[16][64];
    __shared__ float Bs[16][64];
    int tid = threadIdx.x;
    int tx = tid & 15, ty = tid >> 4;
    int rowBase = blockIdx.y * 64;
    int colBase = blockIdx.x * 64;
    float acc[4][4];
#pragma unroll
    for (int i = 0; i < 4; i++)
#pragma unroll
        for (int j = 0; j < 4; j++) acc[i][j] = 0.f;

    for (int k0 = 0; k0 < K; k0 += 16) {
#pragma unroll
        for (int l = 0; l < 4; l++) {
            int q = tid + l * 256;
            int r = q >> 4, kk = q & 15;
            int gr = rowBase + r;
            As[kk][r] = (gr < M) ? Az[(long)gr * K + k0 + kk] : 0.f;
        }
#pragma unroll
        for (int l = 0; l < 4; l++) {
            int q = tid + l * 256;
            int kk = q >> 6, cx = q & 63;
            int gc = colBase + cx;
            Bs[kk][cx] = (gc < Np) ? Bz[(long)(k0 + kk) * Np + gc] : 0.f;
        }
        __syncthreads();
#pragma unroll
        for (int kk = 0; kk < 16; kk++) {
            float4 a4 = *(const float4*)&As[kk][ty * 4];
            float4 b4 = *(const float4*)&Bs[kk][tx * 4];
            float a[4] = {a4.x, a4.y, a4.z, a4.w};
            float b[4] = {b4.x, b4.y, b4.z, b4.w};
#pragma unroll
            for (int i = 0; i < 4; i++)
#pragma unroll
                for (int j = 0; j < 4; j++) acc[i][j] += a[i] * b[j];
        }
        __syncthreads();
    }
    const float* biasz = bias ? bias + (long)blockIdx.z * sBias : nullptr;
#pragma unroll
    for (int i = 0; i < 4; i++) {
        int gr = rowBase + ty * 4 + i;
        if (gr >= M) continue;
#pragma unroll
        for (int j = 0; j < 4; j++) {
            int gc = colBase + tx * 4 + j;
            if (gc < Np)
                Cz[(long)gr * Np + gc] = acc[i][j] + (biasz ? biasz[gc] : 0.f);
        }
    }
}

// ---------------- BN1: per-(n,c) stats over (b,d) -----------------------------
__global__ void bn1_stats_kernel() {
    int n = blockIdx.x;
    int c = blockIdx.y * 128 + threadIdx.x;
    float s1 = 0.f, s2 = 0.f;
    const float* base = g_h + (long)n * ND * Cch + c;
    for (int r = 0; r < ND; r++) {
        float v = base[(long)r * Cch];
        s1 += v; s2 += v * v;
    }
    float m = s1 / (float)ND;
    float var = s2 / (float)ND - m * m;
    g_bn1m[n * Cch + c] = m;
    g_bn1r[n * Cch + c] = rsqrtf(fmaxf(var, 0.f) + EPS_);
}

// f_u = relu(bn(h)) in place; f_v = mean over d
__global__ void bn1_apply_kernel() {
    int n = blockIdx.x, b = blockIdx.y;
    int tid = threadIdx.x; // 256
#pragma unroll
    for (int cc = 0; cc < 2; cc++) {
        int c = tid + cc * 256;
        float m = g_bn1m[n * Cch + c];
        float r = g_bn1r[n * Cch + c];
        float acc = 0.f;
        long base = ((long)(n * Bb + b) * Dd) * Cch + c;
        for (int d = 0; d < Dd; d++) {
            long idx = base + (long)d * Cch;
            float u = fmaxf((g_h[idx] - m) * r, 0.f);
            g_h[idx] = u;
            acc += u;
        }
        g_fv[(long)(b * Nn + n) * Cch + c] = acc / (float)Dd;
    }
}

// ---------------- first cross-attention --------------------------------------
__global__ void attn1_kernel() {
    int r = blockIdx.x;                 // (n*8+b)*49+d
    int b = (r / Dd) % Bb;
    __shared__ float qs[Hh];
    __shared__ float sc[64];
    __shared__ float red[2];
    int tid = threadIdx.x;              // 128
    qs[tid] = g_q1[(long)r * Hh + tid];
    qs[tid + 128] = g_q1[(long)r * Hh + tid + 128];
    __syncthreads();
    int w = tid >> 5, lane = tid & 31;
    for (int j = w; j < Dd; j += 4) {
        const float* kr = g_k1 + (long)(b * Dd + j) * Hh;
        float dot = 0.f;
        for (int t = lane; t < Hh; t += 32) dot += qs[t] * kr[t];
#pragma unroll
        for (int o = 16; o; o >>= 1) dot += __shfl_xor_sync(0xffffffffu, dot, o);
        if (lane == 0) sc[j] = dot * SCALE_;
    }
    __syncthreads();
    if (tid == 0) { float m = -1e30f; for (int j = 0; j < Dd; j++) m = fmaxf(m, sc[j]); red[0] = m; }
    __syncthreads();
    if (tid < Dd) sc[tid] = expf(sc[tid] - red[0]);
    __syncthreads();
    if (tid == 0) { float s = 0.f; for (int j = 0; j < Dd; j++) s += sc[j]; red[1] = 1.f / s; }
    __syncthreads();
    float inv = red[1];
    int c0 = tid * 4;
    float4 acc = {0.f, 0.f, 0.f, 0.f};
    for (int j = 0; j < Dd; j++) {
        float p = sc[j];
        float4 v = *(const float4*)(g_v1 + (long)(b * Dd + j) * Cch + c0);
        acc.x += p * v.x; acc.y += p * v.y; acc.z += p * v.z; acc.w += p * v.w;
    }
    acc.x *= inv; acc.y *= inv; acc.z *= inv; acc.w *= inv;
    *(float4*)(g_feat1 + (long)r * Cch + c0) = acc;
}

// bvp = arm_bv @ ep_w
__global__ void bvp_kernel(const float* __restrict__ bv, const float* __restrict__ epw) {
    int c = threadIdx.x; // 512
    float s = 0.f;
    for (int k = 0; k < Cch; k++) s += bv[k] * epw[k * Cch + c];
    g_bvp[c] = s;
}

// ---------------- second cross-attention, fused with ep projection -----------
// Per (b, e=i*12+j) block. z[d,c] = softmax(Q2[j,d]·K2[i,:]) @ Vp[i] + ep_b
// Outputs: zbar (mean over d), per-(b,e) sum & sumsq of z over (d,c).
__global__ void attn2_kernel(const float* __restrict__ ep_b) {
    int e = blockIdx.x, b = blockIdx.y;
    int i = e / Nn, j = e % Nn;
    extern __shared__ float sm[];
    float* Ks  = sm;                    // 49*256
    float* Vs  = Ks + Dd * Hh;          // 49*512
    float* qs  = Vs + Dd * Cch;         // 256
    float* sc  = qs + Hh;               // 64
    float* epb = sc + 64;               // 512
    float* red = epb + Cch;             // 64
    int tid = threadIdx.x;              // 256

    const float* Kbase = g_K2 + (long)((i * Bb + b) * Dd) * Hh;
    for (int t = tid; t < Dd * Hh; t += 256) Ks[t] = Kbase[t];
    const float* Vbase = g_Vp + (long)((i * Bb + b) * Dd) * Cch;
    for (int t = tid; t < Dd * Cch; t += 256) Vs[t] = Vbase[t];
    epb[tid] = ep_b[tid];
    epb[tid + 256] = ep_b[tid + 256];

    const float* Qbase = g_Q2 + (long)((j * Bb + b) * Dd) * Hh;
    float zs0 = 0.f, zs1 = 0.f, ls1 = 0.f, ls2 = 0.f;
    int w = tid >> 5, lane = tid & 31;

    for (int d = 0; d < Dd; d++) {
        __syncthreads();
        qs[tid] = Qbase[(long)d * Hh + tid];
        __syncthreads();
        for (int jj = w; jj < Dd; jj += 8) {
            const float* kr = Ks + jj * Hh;
            float dot = 0.f;
            for (int t = lane; t < Hh; t += 32) dot += qs[t] * kr[t];
#pragma unroll
            for (int o = 16; o; o >>= 1) dot += __shfl_xor_sync(0xffffffffu, dot, o);
            if (lane == 0) sc[jj] = dot * SCALE_;
        }
        __syncthreads();
        if (tid == 0) { float m = -1e30f; for (int t = 0; t < Dd; t++) m = fmaxf(m, sc[t]); red[0] = m; }
        __syncthreads();
        if (tid < Dd) sc[tid] = expf(sc[tid] - red[0]);
        __syncthreads();
        if (tid == 0) { float s = 0.f; for (int t = 0; t < Dd; t++) s += sc[t]; red[1] = 1.f / s; }
        __syncthreads();
        float inv = red[1];
        float a0 = 0.f, a1 = 0.f;
        for (int jj = 0; jj < Dd; jj++) {
            float p = sc[jj];
            a0 += p * Vs[jj * Cch + tid];
            a1 += p * Vs[jj * Cch + tid + 256];
        }
        float z0 = a0 * inv + epb[tid];
        float z1 = a1 * inv + epb[tid + 256];
        zs0 += z0; zs1 += z1;
        ls1 += z0 + z1;
        ls2 += z0 * z0 + z1 * z1;
    }
    long zb = (long)(b * Ee + e) * Cch;
    g_zbar[zb + tid]       = zs0 * (1.f / (float)Dd);
    g_zbar[zb + tid + 256] = zs1 * (1.f / (float)Dd);
    __syncthreads();
    float s1 = block_reduce_sum(ls1, red);
    float s2 = block_reduce_sum(ls2, red);
    if (tid == 0) { g_ps1[b * Ee + e] = s1; g_ps2[b * Ee + e] = s2; }
}

// ---------------- cosine adjacency mask --------------------------------------
__global__ void mask_kernel() {
    int b = blockIdx.x;
    __shared__ float sinv[Nn];
    __shared__ float adj[Ee];
    __shared__ float dis[Nn];
    int tid = threadIdx.x; // 256
    if (tid < Nn) {
        const float* f = g_fv + (long)(b * Nn + tid) * Cch;
        float s = 0.f;
        for (int c = 0; c < Cch; c++) s += f[c] * f[c];
        sinv[tid] = 1.f / fmaxf(sqrtf(s), 1e-12f);
    }
    __syncthreads();
    if (tid < Ee) {
        int i = tid / Nn, jn = tid % Nn;
        const float* fi = g_fv + (long)(b * Nn + i) * Cch;
        const float* fj = g_fv + (long)(b * Nn + jn) * Cch;
        float s = 0.f;
        for (int c = 0; c < Cch; c++) s += fi[c] * fj[c];
        adj[tid] = s * sinv[i] * sinv[jn];
    }
    __syncthreads();
    if (tid < Nn) {
        float s = 0.f;
        for (int jn = 0; jn < Nn; jn++) s += adj[tid * Nn + jn];
        dis[tid] = rsqrtf(s);
    }
    __syncthreads();
    if (tid < Ee) {
        int i = tid / Nn, jn = tid % Nn;
        g_mask[b * Ee + tid] = adj[tid] * dis[i] * dis[jn];
    }
}

// ---------------- edge BN (per-edge over b,d,c) + mask ------------------------
__global__ void edge_bn_mask_kernel() {
    int e = blockIdx.x;
    __shared__ float mrs[2];
    int tid = threadIdx.x; // 256
    if (tid == 0) {
        float s1 = 0.f, s2 = 0.f;
        for (int b = 0; b < Bb; b++) { s1 += g_ps1[b * Ee + e]; s2 += g_ps2[b * Ee + e]; }
        float cnt = (float)(Bb * Dd * Cch);
        float m = s1 / cnt;
        float v = s2 / cnt - m * m;
        mrs[0] = m;
        mrs[1] = rsqrtf(fmaxf(v, 0.f) + EPS_);
    }
    __syncthreads();
    float m = mrs[0], r = mrs[1];
    for (int b = 0; b < Bb; b++) {
        float mk = g_mask[b * Ee + e];
        long base = (long)(b * Ee + e) * Cch;
        g_fe[base + tid]       = (g_zbar[base + tid] - m) * r * mk;
        g_fe[base + tid + 256] = (g_zbar[base + tid + 256] - m) * r * mk;
    }
}

// ---------------- GNN layer pieces -------------------------------------------
__global__ void agg_bn_kernel() {
    int e = blockIdx.x;
    int i = e / Nn, jn = e % Nn;
    __shared__ float sm[64];
    __shared__ float mrs[2];
    int tid = threadIdx.x; // 256
    float s1 = 0.f, s2 = 0.f;
    for (int b = 0; b < Bb; b++) {
        long na = (long)(b * Nn + i) * Cch;
        long nb = (long)(b * Nn + jn) * Cch;
        long ne = (long)(b * Ee + e) * Cch;
#pragma unroll
        for (int cc = 0; cc < 2; cc++) {
            int c = tid + cc * 256;
            float v = g_xa[na + c] + g_xb[nb + c] + g_xw[ne + c];
            g_agg[ne + c] = v;
            s1 += v; s2 += v * v;
        }
    }
    s1 = block_reduce_sum(s1, sm);
    s2 = block_reduce_sum(s2, sm);
    if (tid == 0) {
        float cnt = (float)(Bb * Cch);
        float m = s1 / cnt;
        float v = s2 / cnt - m * m;
        mrs[0] = m;
        mrs[1] = rsqrtf(fmaxf(v, 0.f) + EPS_);
    }
    __syncthreads();
    float m = mrs[0], r = mrs[1];
    for (int b = 0; b < Bb; b++) {
        long ne = (long)(b * Ee + e) * Cch;
#pragma unroll
        for (int cc = 0; cc < 2; cc++) {
            int c = tid + cc * 256;
            g_fe[ne + c] += fmaxf((g_agg[ne + c] - m) * r, 0.f);
        }
    }
}

__global__ void softmax_msg_kernel() {
    int bi = blockIdx.x;
    int b = bi / Nn, i = bi % Nn;
    int c = threadIdx.x; // 512
    float v[Nn];
    float mx = -1e30f;
#pragma unroll
    for (int jn = 0; jn < Nn; jn++) {
        float ed = g_fe[((long)(b * Ee + i * Nn + jn)) * Cch + c];
        float s = 1.f / (1.f + expf(-ed));
        v[jn] = s;
        mx = fmaxf(mx, s);
    }
    float sum = 0.f;
#pragma unroll
    for (int jn = 0; jn < Nn; jn++) { v[jn] = expf(v[jn] - mx); sum += v[jn]; }
    float acc = 0.f;
#pragma unroll
    for (int jn = 0; jn < Nn; jn++) acc += v[jn] * g_xvv[(long)(b * Nn + jn) * Cch + c];
    g_msg[(long)(b * Nn + i) * Cch + c] = acc / (sum * (float)Nn);
}

__global__ void node_bn_kernel() {
    int n = blockIdx.x;
    __shared__ float sm[64];
    __shared__ float mrs[2];
    int tid = threadIdx.x; // 256
    float s1 = 0.f, s2 = 0.f;
    for (int b = 0; b < Bb; b++) {
        long base = (long)(b * Nn + n) * Cch;
#pragma unroll
        for (int cc = 0; cc < 2; cc++) {
            int c = tid + cc * 256;
            float t = g_xu[base + c] + g_msg[base + c];
            g_t[base + c] = t;
            s1 += t; s2 += t * t;
        }
    }
    s1 = block_reduce_sum(s1, sm);
    s2 = block_reduce_sum(s2, sm);
    if (tid == 0) {
        float cnt = (float)(Bb * Cch);
        float m = s1 / cnt;
        float v = s2 / cnt - m * m;
        mrs[0] = m;
        mrs[1] = rsqrtf(fmaxf(v, 0.f) + EPS_);
    }
    __syncthreads();
    float m = mrs[0], r = mrs[1];
    for (int b = 0; b < Bb; b++) {
        long base = (long)(b * Nn + n) * Cch;
#pragma unroll
        for (int cc = 0; cc < 2; cc++) {
            int c = tid + cc * 256;
            g_fv[base + c] = fmaxf(g_fv[base + c] + (g_t[base + c] - m) * r, 0.f);
        }
    }
}

// ---------------- classifier heads -------------------------------------------
__global__ void cls_kernel(const float* __restrict__ sc_w, float* __restrict__ out) {
    int bn = blockIdx.x; // b*12+n
    int n = bn % Nn;
    __shared__ float sm[32];
    int tid = threadIdx.x; // 128
    float sf = 0.f, ff = 0.f, ss = 0.f;
    for (int c = tid; c < Cch; c += 128) {
        float f = g_fv[(long)bn * Cch + c];
        float s = fmaxf(sc_w[n * Cch + c], 0.f);
        sf += f * s; ff += f * f; ss += s * s;
    }
    sf = block_reduce_sum(sf, sm);
    ff = block_reduce_sum(ff, sm);
    ss = block_reduce_sum(ss, sm);
    if (tid == 0)
        out[bn] = sf / (fmaxf(sqrtf(ff), 1e-12f) * fmaxf(sqrtf(ss), 1e-12f));
}

__global__ void edgefc_kernel(const float* __restrict__ w, const float* __restrict__ bias,
                              float* __restrict__ out) {
    int row = blockIdx.x; // b*144+e
    int tid = threadIdx.x; // 128
    int k = tid >> 5, lane = tid & 31;
    const float* f = g_fe + (long)row * Cch;
    float dot = 0.f;
    for (int c = lane; c < Cch; c += 32) dot += f[c] * w[c * 4 + k];
#pragma unroll
    for (int o = 16; o; o >>= 1) dot += __shfl_xor_sync(0xffffffffu, dot, o);
    if (lane == 0) out[96 + row * 4 + k] = dot + bias[k];
}

// ---------------- host driver -------------------------------------------------
extern "C" void kernel_launch(void* const* d_in, const int* in_sizes, int n_in,
                              void* d_out, int out_size) {
    const float* x      = (const float*)d_in[0];
    const float* Wc     = (const float*)d_in[1];
    const float* bc     = (const float*)d_in[2];
    const float* fam_wq = (const float*)d_in[3];
    const float* fam_bq = (const float*)d_in[4];
    const float* fam_wk = (const float*)d_in[5];
    const float* fam_bk = (const float*)d_in[6];
    const float* fam_wv = (const float*)d_in[7];
    const float* fam_bv = (const float*)d_in[8];
    const float* arm_wq = (const float*)d_in[9];
    const float* arm_bq = (const float*)d_in[10];
    const float* arm_wk = (const float*)d_in[11];
    const float* arm_bk = (const float*)d_in[12];
    const float* arm_wv = (const float*)d_in[13];
    const float* arm_bv = (const float*)d_in[14];
    const float* ep_w   = (const float*)d_in[15];
    const float* ep_b   = (const float*)d_in[16];
    const float* gw[10];
    for (int t = 0; t < 10; t++) gw[t] = (const float*)d_in[17 + t];
    const float* sc_w   = (const float*)d_in[27];
    const float* efc_w  = (const float*)d_in[28];
    const float* efc_b  = (const float*)d_in[29];
    float* out = (float*)d_out;

    float *p_h, *p_q1, *p_k1, *p_v1, *p_f1, *p_Q2, *p_K2, *p_Vp, *p_Wvp, *p_bvp;
    float *p_fv, *p_xa, *p_xb, *p_xu, *p_xvv, *p_xw, *p_fe;
    cudaGetSymbolAddress((void**)&p_h, g_h);
    cudaGetSymbolAddress((void**)&p_q1, g_q1);
    cudaGetSymbolAddress((void**)&p_k1, g_k1);
    cudaGetSymbolAddress((void**)&p_v1, g_v1);
    cudaGetSymbolAddress((void**)&p_f1, g_feat1);
    cudaGetSymbolAddress((void**)&p_Q2, g_Q2);
    cudaGetSymbolAddress((void**)&p_K2, g_K2);
    cudaGetSymbolAddress((void**)&p_Vp, g_Vp);
    cudaGetSymbolAddress((void**)&p_Wvp, g_Wvp);
    cudaGetSymbolAddress((void**)&p_bvp, g_bvp);
    cudaGetSymbolAddress((void**)&p_fv, g_fv);
    cudaGetSymbolAddress((void**)&p_xa, g_xa);
    cudaGetSymbolAddress((void**)&p_xb, g_xb);
    cudaGetSymbolAddress((void**)&p_xu, g_xu);
    cudaGetSymbolAddress((void**)&p_xvv, g_xvv);
    cudaGetSymbolAddress((void**)&p_xw, g_xw);
    cudaGetSymbolAddress((void**)&p_fe, g_fe);

    const int ATTN2_SMEM = (Dd * Hh + Dd * Cch + Hh + 64 + Cch + 64) * 4;
    cudaFuncSetAttribute(attn2_kernel, cudaFuncAttributeMaxDynamicSharedMemorySize, ATTN2_SMEM);

    // h = x @ Wc[n] + bc[n] for all 12 classes (batched over z)
    gemm_kernel<<<dim3(8, 7, 12), 256>>>(x, Wc, bc, p_h, ND, Cch, Cch,
                                         0, (long)Cch * Cch, Cch, (long)ND * Cch);
    bn1_stats_kernel<<<dim3(12, 4), 128>>>();
    bn1_apply_kernel<<<dim3(12, 8), 256>>>();

    // first attention projections (K/V shared across classes — gf is broadcast x)
    gemm_kernel<<<dim3(4, 7, 1), 256>>>(x, fam_wk, fam_bk, p_k1, ND, Hh, Cch, 0, 0, 0, 0);
    gemm_kernel<<<dim3(8, 7, 1), 256>>>(x, fam_wv, fam_bv, p_v1, ND, Cch, Cch, 0, 0, 0, 0);
    gemm_kernel<<<dim3(4, 74, 1), 256>>>(p_h, fam_wq, fam_bq, p_q1, RQ, Hh, Cch, 0, 0, 0, 0);
    attn1_kernel<<<RQ, 128>>>();

    // fold ep projection into V of second attention: Wvp = arm_wv @ ep_w
    gemm_kernel<<<dim3(8, 8, 1), 256>>>(arm_wv, ep_w, nullptr, p_Wvp, Cch, Cch, Cch, 0, 0, 0, 0);
    bvp_kernel<<<1, 512>>>(arm_bv, ep_w);
    gemm_kernel<<<dim3(4, 74, 1), 256>>>(p_f1, arm_wq, arm_bq, p_Q2, RQ, Hh, Cch, 0, 0, 0, 0);
    gemm_kernel<<<dim3(4, 74, 1), 256>>>(p_f1, arm_wk, arm_bk, p_K2, RQ, Hh, Cch, 0, 0, 0, 0);
    gemm_kernel<<<dim3(8, 74, 1), 256>>>(p_f1, p_Wvp, p_bvp, p_Vp, RQ, Cch, Cch, 0, 0, 0, 0);

    attn2_kernel<<<dim3(Ee, Bb), 256, ATTN2_SMEM>>>(ep_b);
    mask_kernel<<<Bb, 256>>>();
    edge_bn_mask_kernel<<<Ee, 256>>>();

    // two GNN layers
    for (int L = 0; L < 2; L++) {
        const float* wa = gw[L * 5 + 0];
        const float* wb = gw[L * 5 + 1];
        const float* we = gw[L * 5 + 2];
        const float* wu = gw[L * 5 + 3];
        const float* wv = gw[L * 5 + 4];
        gemm_kernel<<<dim3(8, 2, 1), 256>>>(p_fv, wa, nullptr, p_xa, Bb * Nn, Cch, Cch, 0, 0, 0, 0);
        gemm_kernel<<<dim3(8, 2, 1), 256>>>(p_fv, wb, nullptr, p_xb, Bb * Nn, Cch, Cch, 0, 0, 0, 0);
        gemm_kernel<<<dim3(8, 2, 1), 256>>>(p_fv, wu, nullptr, p_xu, Bb * Nn, Cch, Cch, 0, 0, 0, 0);
        gemm_kernel<<<dim3(8, 2, 1), 256>>>(p_fv, wv, nullptr, p_xvv, Bb * Nn, Cch, Cch, 0, 0, 0, 0);
        gemm_kernel<<<dim3(8, 18, 1), 256>>>(p_fe, we, nullptr, p_xw, Bb * Ee, Cch, Cch, 0, 0, 0, 0);
        agg_bn_kernel<<<Ee, 256>>>();
        softmax_msg_kernel<<<Bb * Nn, 512>>>();
        node_bn_kernel<<<Nn, 256>>>();
    }

    cls_kernel<<<Bb * Nn, 128>>>(sc_w, out);
    edgefc_kernel<<<Bb * Ee, 128>>>(efc_w, efc_b, out);
}

// round 2
// speedup vs baseline: 2.3039x; 2.3039x over previous
#include <cuda_runtime.h>
#include <math.h>

// Problem constants
#define Bb   8
#define Dd   49
#define Cch  512
#define Nn   12
#define Hh   256          // C/2
#define Ee   144          // N*N
#define ND   392          // B*D
#define RQ   4704         // N*B*D
#define SQ   588          // N*D (rows per batch in attn2)
#define SCALE_ 0.0625f    // (C/2)^-0.5
#define EPS_  1e-5f

// ---------------- static device scratch -------------------------------------
__device__ float g_h[RQ * Cch];          // h then f_u in place, rows (n*8+b)*49+d
__device__ float g_q1[RQ * Hh];
__device__ float g_k1[ND * Hh];
__device__ float g_v1[ND * Cch];
__device__ float g_feat1[RQ * Cch];      // rows (b*12+n)*49+d  (b-major!)
__device__ float g_QK2[RQ * Cch];        // cols 0-255 = Q2, 256-511 = K2
__device__ float g_Vp[RQ * Cch];         // feat1 @ (arm_wv@ep_w) + arm_bv@ep_w
__device__ float g_Wvp[Cch * Cch];
__device__ float g_bvp[Cch];
__device__ float g_wqk[Cch * Cch];       // packed arm_wq | arm_wk
__device__ float g_bqk[Cch];
__device__ float g_S[Bb * SQ * SQ];      // attn2 raw scores
__device__ float g_MV[Bb * Nn * Dd * Dd];// Vp Gram per (b,i)
__device__ float g_w[Bb * Ee * Dd];      // aggregated attention weights
__device__ float g_gram[Bb * Ee];        // <P^T P, MV>
__device__ float g_fv[Bb * Nn * Cch];
__device__ float g_zbar[Bb * Ee * Cch];
__device__ float g_ps1[Bb * Ee];
__device__ float g_ps2[Bb * Ee];
__device__ float g_bn1m[Nn * Cch];
__device__ float g_bn1r[Nn * Cch];
__device__ float g_mask[Bb * Ee];
__device__ float g_fe[Bb * Ee * Cch];
__device__ float g_wnode[Cch * 2048];    // packed wa|wb|wu|wv
__device__ float g_xnode[Bb * Nn * 2048];
__device__ float g_xw[Bb * Ee * Cch];
__device__ float g_agg[Bb * Ee * Cch];
__device__ float g_msg[Bb * Nn * Cch];
__device__ float g_t[Bb * Nn * Cch];

// ---------------- helpers ----------------------------------------------------
__device__ __forceinline__ float block_reduce_sum(float v, float* sm) {
    int lane = threadIdx.x & 31, w = threadIdx.x >> 5;
#pragma unroll
    for (int o = 16; o; o >>= 1) v += __shfl_xor_sync(0xffffffffu, v, o);
    if (lane == 0) sm[w] = v;
    __syncthreads();
    int nw = (blockDim.x + 31) >> 5;
    float r = 0.f;
    if (threadIdx.x < 32) {
        r = (threadIdx.x < nw) ? sm[threadIdx.x] : 0.f;
#pragma unroll
        for (int o = 16; o; o >>= 1) r += __shfl_xor_sync(0xffffffffu, r, o);
        if (threadIdx.x == 0) sm[0] = r;
    }
    __syncthreads();
    r = sm[0];
    __syncthreads();
    return r;
}

// ---------------- gemm128: C = A(MxK)@B(KxN)+bias, 128x128x16, dbl-buffered --
__global__ __launch_bounds__(256) void gemm128_kernel(
    const float* __restrict__ A, const float* __restrict__ Bm,
    const float* __restrict__ bias, float* __restrict__ Cm,
    int M, int Np, int K, int lda, int ldb, int ldc,
    long sA, long sB, long sC)
{
    const float* Az = A + (long)blockIdx.z * sA;
    const float* Bz = Bm + (long)blockIdx.z * sB;
    float* Cz = Cm + (long)blockIdx.z * sC;
    __shared__ float As[2][16][128];
    __shared__ float Bs[2][16][128];
    int tid = threadIdx.x;
    int tx = tid & 15, ty = tid >> 4;
    int row0 = blockIdx.y * 128, col0 = blockIdx.x * 128;

    int arow = tid >> 1;               // 0..127
    int ak0  = (tid & 1) * 8;          // 0 or 8
    int bkk  = tid >> 4;               // 0..15
    int bn0  = (tid & 15) * 8;         // 0..120

    float acc[8][8];
#pragma unroll
    for (int i = 0; i < 8; i++)
#pragma unroll
        for (int j = 0; j < 8; j++) acc[i][j] = 0.f;

    float4 a0g, a1g, b0g, b1g;
    const float4 z4 = {0.f, 0.f, 0.f, 0.f};

    // initial load (k0 = 0)
    {
        int gr = row0 + arow;
        if (gr < M) {
            const float* p = Az + (long)gr * lda + ak0;
            a0g = *(const float4*)p; a1g = *(const float4*)(p + 4);
        } else { a0g = z4; a1g = z4; }
        int gc = col0 + bn0;
        if (gc < Np) {
            const float* p = Bz + (long)bkk * ldb + gc;
            b0g = *(const float4*)p; b1g = *(const float4*)(p + 4);
        } else { b0g = z4; b1g = z4; }
    }
    As[0][ak0+0][arow]=a0g.x; As[0][ak0+1][arow]=a0g.y; As[0][ak0+2][arow]=a0g.z; As[0][ak0+3][arow]=a0g.w;
    As[0][ak0+4][arow]=a1g.x; As[0][ak0+5][arow]=a1g.y; As[0][ak0+6][arow]=a1g.z; As[0][ak0+7][arow]=a1g.w;
    *(float4*)&Bs[0][bkk][bn0] = b0g;
    *(float4*)&Bs[0][bkk][bn0+4] = b1g;
    __syncthreads();

    int nt = K >> 4;
    for (int t = 0; t < nt; t++) {
        int buf = t & 1;
        if (t + 1 < nt) {
            int k0 = (t + 1) << 4;
            int gr = row0 + arow;
            if (gr < M) {
                const float* p = Az + (long)gr * lda + k0 + ak0;
                a0g = *(const float4*)p; a1g = *(const float4*)(p + 4);
            } else { a0g = z4; a1g = z4; }
            int gc = col0 + bn0;
            if (gc < Np) {
                const float* p = Bz + (long)(k0 + bkk) * ldb + gc;
                b0g = *(const float4*)p; b1g = *(const float4*)(p + 4);
            } else { b0g = z4; b1g = z4; }
        }
#pragma unroll
        for (int kk = 0; kk < 16; kk++) {
            float4 a0 = *(const float4*)&As[buf][kk][ty * 8];
            float4 a1 = *(const float4*)&As[buf][kk][ty * 8 + 4];
            float4 b0 = *(const float4*)&Bs[buf][kk][tx * 8];
            float4 b1 = *(const float4*)&Bs[buf][kk][tx * 8 + 4];
            float a[8] = {a0.x,a0.y,a0.z,a0.w,a1.x,a1.y,a1.z,a1.w};
            float b[8] = {b0.x,b0.y,b0.z,b0.w,b1.x,b1.y,b1.z,b1.w};
#pragma unroll
            for (int i = 0; i < 8; i++)
#pragma unroll
                for (int j = 0; j < 8; j++) acc[i][j] += a[i] * b[j];
        }
        if (t + 1 < nt) {
            int nb = buf ^ 1;
            As[nb][ak0+0][arow]=a0g.x; As[nb][ak0+1][arow]=a0g.y; As[nb][ak0+2][arow]=a0g.z; As[nb][ak0+3][arow]=a0g.w;
            As[nb][ak0+4][arow]=a1g.x; As[nb][ak0+5][arow]=a1g.y; As[nb][ak0+6][arow]=a1g.z; As[nb][ak0+7][arow]=a1g.w;
            *(float4*)&Bs[nb][bkk][bn0] = b0g;
            *(float4*)&Bs[nb][bkk][bn0+4] = b1g;
            __syncthreads();
        }
    }
#pragma unroll
    for (int i = 0; i < 8; i++) {
        int gr = row0 + ty * 8 + i;
        if (gr >= M) continue;
#pragma unroll
        for (int j = 0; j < 8; j++) {
            int gc = col0 + tx * 8 + j;
            if (gc < Np)
                Cz[(long)gr * ldc + gc] = acc[i][j] + (bias ? bias[gc] : 0.f);
        }
    }
}

// ---------------- gemm64: 64x64x16, NN or NT (B row-major NxK) ---------------
__global__ __launch_bounds__(256) void gemm64_kernel(
    const float* __restrict__ A, const float* __restrict__ Bm,
    const float* __restrict__ bias, float* __restrict__ Cm,
    int M, int Np, int K, int lda, int ldb, int ldc,
    long sA, long sB, long sC, int transB)
{
    const float* Az = A + (long)blockIdx.z * sA;
    const float* Bz = Bm + (long)blockIdx.z * sB;
    float* Cz = Cm + (long)blockIdx.z * sC;
    __shared__ float As[16][64];
    __shared__ float Bs[16][64];
    int tid = threadIdx.x;
    int tx = tid & 15, ty = tid >> 4;
    int row0 = blockIdx.y * 64, col0 = blockIdx.x * 64;
    int lr = tid >> 2, lk = (tid & 3) * 4;
    int bkk = tid >> 4, bn = (tid & 15) * 4;
    const float4 z4 = {0.f, 0.f, 0.f, 0.f};
    float acc[4][4];
#pragma unroll
    for (int i = 0; i < 4; i++)
#pragma unroll
        for (int j = 0; j < 4; j++) acc[i][j] = 0.f;

    for (int k0 = 0; k0 < K; k0 += 16) {
        float4 av = z4, bv = z4;
        if (row0 + lr < M) av = *(const float4*)(Az + (long)(row0 + lr) * lda + k0 + lk);
        if (!transB) {
            if (col0 + bn < Np) bv = *(const float4*)(Bz + (long)(k0 + bkk) * ldb + col0 + bn);
        } else {
            if (col0 + lr < Np) bv = *(const float4*)(Bz + (long)(col0 + lr) * ldb + k0 + lk);
        }
        __syncthreads();
        As[lk+0][lr]=av.x; As[lk+1][lr]=av.y; As[lk+2][lr]=av.z; As[lk+3][lr]=av.w;
        if (!transB) {
            *(float4*)&Bs[bkk][bn] = bv;
        } else {
            Bs[lk+0][lr]=bv.x; Bs[lk+1][lr]=bv.y; Bs[lk+2][lr]=bv.z; Bs[lk+3][lr]=bv.w;
        }
        __syncthreads();
#pragma unroll
        for (int kk = 0; kk < 16; kk++) {
            float4 a4 = *(const float4*)&As[kk][ty * 4];
            float4 b4 = *(const float4*)&Bs[kk][tx * 4];
            float a[4] = {a4.x, a4.y, a4.z, a4.w};
            float b[4] = {b4.x, b4.y, b4.z, b4.w};
#pragma unroll
            for (int i = 0; i < 4; i++)
#pragma unroll
                for (int j = 0; j < 4; j++) acc[i][j] += a[i] * b[j];
        }
    }
#pragma unroll
    for (int i = 0; i < 4; i++) {
        int gr = row0 + ty * 4 + i;
        if (gr >= M) continue;
#pragma unroll
        for (int j = 0; j < 4; j++) {
            int gc = col0 + tx * 4 + j;
            if (gc < Np)
                Cz[(long)gr * ldc + gc] = acc[i][j] + (bias ? bias[gc] : 0.f);
        }
    }
}

// ---------------- weight packers ---------------------------------------------
__global__ void pack_qk_kernel(const float* __restrict__ wq, const float* __restrict__ wk,
                               const float* __restrict__ bq, const float* __restrict__ bk) {
    int idx = blockIdx.x * 256 + threadIdx.x;        // 512*512
    int k = idx >> 9, c = idx & 511;
    g_wqk[idx] = (c < 256) ? wq[k * 256 + c] : wk[k * 256 + c - 256];
    if (idx < 512) g_bqk[idx] = (idx < 256) ? bq[idx] : bk[idx - 256];
}

__global__ void pack_node_kernel(const float* __restrict__ wa, const float* __restrict__ wb,
                                 const float* __restrict__ wu, const float* __restrict__ wv) {
    int idx = blockIdx.x * 256 + threadIdx.x;        // 512*2048
    int k = idx >> 11, c = idx & 2047;
    const float* src = (c < 512) ? wa : (c < 1024) ? wb : (c < 1536) ? wu : wv;
    g_wnode[idx] = src[k * 512 + (c & 511)];
}

// ---------------- BN1 ---------------------------------------------------------
__global__ void bn1_stats_kernel() {
    int n = blockIdx.x;
    int c = blockIdx.y * 128 + threadIdx.x;
    float s1 = 0.f, s2 = 0.f;
    const float* base = g_h + (long)n * ND * Cch + c;
    for (int r = 0; r < ND; r++) {
        float v = base[(long)r * Cch];
        s1 += v; s2 += v * v;
    }
    float m = s1 / (float)ND;
    float var = s2 / (float)ND - m * m;
    g_bn1m[n * Cch + c] = m;
    g_bn1r[n * Cch + c] = rsqrtf(fmaxf(var, 0.f) + EPS_);
}

__global__ void bn1_apply_kernel() {
    int n = blockIdx.x, b = blockIdx.y;
    int tid = threadIdx.x; // 256
#pragma unroll
    for (int cc = 0; cc < 2; cc++) {
        int c = tid + cc * 256;
        float m = g_bn1m[n * Cch + c];
        float r = g_bn1r[n * Cch + c];
        float acc = 0.f;
        long base = ((long)(n * Bb + b) * Dd) * Cch + c;
        for (int d = 0; d < Dd; d++) {
            long idx = base + (long)d * Cch;
            float u = fmaxf((g_h[idx] - m) * r, 0.f);
            g_h[idx] = u;
            acc += u;
        }
        g_fv[(long)(b * Nn + n) * Cch + c] = acc / (float)Dd;
    }
}

// ---------------- first cross-attention (writes feat1 b-major) ----------------
__global__ void attn1_kernel() {
    int r = blockIdx.x;                 // n-major: (n*8+b)*49+d
    int d = r % Dd;
    int b = (r / Dd) % Bb;
    int n = r / (Dd * Bb);
    __shared__ float qs[Hh];
    __shared__ float sc[64];
    __shared__ float red[2];
    int tid = threadIdx.x;              // 128
    qs[tid] = g_q1[(long)r * Hh + tid];
    qs[tid + 128] = g_q1[(long)r * Hh + tid + 128];
    __syncthreads();
    int w = tid >> 5, lane = tid & 31;
    for (int j = w; j < Dd; j += 4) {
        const float* kr = g_k1 + (long)(b * Dd + j) * Hh;
        float dot = 0.f;
        for (int t = lane; t < Hh; t += 32) dot += qs[t] * kr[t];
#pragma unroll
        for (int o = 16; o; o >>= 1) dot += __shfl_xor_sync(0xffffffffu, dot, o);
        if (lane == 0) sc[j] = dot * SCALE_;
    }
    __syncthreads();
    if (tid == 0) { float m = -1e30f; for (int j = 0; j < Dd; j++) m = fmaxf(m, sc[j]); red[0] = m; }
    __syncthreads();
    if (tid < Dd) sc[tid] = expf(sc[tid] - red[0]);
    __syncthreads();
    if (tid == 0) { float s = 0.f; for (int j = 0; j < Dd; j++) s += sc[j]; red[1] = 1.f / s; }
    __syncthreads();
    float inv = red[1];
    int c0 = tid * 4;
    float4 acc = {0.f, 0.f, 0.f, 0.f};
    for (int j = 0; j < Dd; j++) {
        float p = sc[j];
        float4 v = *(const float4*)(g_v1 + (long)(b * Dd + j) * Cch + c0);
        acc.x += p * v.x; acc.y += p * v.y; acc.z += p * v.z; acc.w += p * v.w;
    }
    acc.x *= inv; acc.y *= inv; acc.z *= inv; acc.w *= inv;
    long ro = (long)(b * Nn + n) * Dd + d;      // b-major output row
    *(float4*)(g_feat1 + ro * Cch + c0) = acc;
}

// bvp = arm_bv @ ep_w
__global__ void bvp_kernel(const float* __restrict__ bv, const float* __restrict__ epw) {
    int c = threadIdx.x; // 512
    float s = 0.f;
    for (int k = 0; k < Cch; k++) s += bv[k] * epw[k * Cch + c];
    g_bvp[c] = s;
}

// ---------------- attn2: per-(b,e) softmax + aggregated weights + Gram term ---
__global__ void pg_kernel() {
    int e = blockIdx.x, b = blockIdx.y;
    int i = e / Nn, j = e % Nn;
    __shared__ float P[49][50];
    __shared__ float MVs[Dd * Dd];
    __shared__ float gpart[8];
    int tid = threadIdx.x, w = tid >> 5, lane = tid & 31;
    const float* MVg = g_MV + (long)(b * Nn + i) * (Dd * Dd);
    for (int t = tid; t < Dd * Dd; t += 256) MVs[t] = MVg[t];
    const float* Sb = g_S + (long)b * SQ * SQ + (long)(j * Dd) * SQ + i * Dd;
    for (int r = w; r < Dd; r += 8) {
        float v0 = (lane < Dd) ? Sb[r * SQ + lane] * SCALE_ : -1e30f;
        float v1 = (lane + 32 < Dd) ? Sb[r * SQ + lane + 32] * SCALE_ : -1e30f;
        float mx = fmaxf(v0, v1);
#pragma unroll
        for (int o = 16; o; o >>= 1) mx = fmaxf(mx, __shfl_xor_sync(0xffffffffu, mx, o));
        float e0 = (lane < Dd) ? expf(v0 - mx) : 0.f;
        float e1 = (lane + 32 < Dd) ? expf(v1 - mx) : 0.f;
        float s = e0 + e1;
#pragma unroll
        for (int o = 16; o; o >>= 1) s += __shfl_xor_sync(0xffffffffu, s, o);
        float inv = 1.f / s;
        if (lane < Dd) P[r][lane] = e0 * inv;
        if (lane + 32 < Dd) P[r][lane + 32] = e1 * inv;
    }
    __syncthreads();
    if (tid < Dd) {
        float s = 0.f;
        for (int r = 0; r < Dd; r++) s += P[r][tid];
        g_w[((long)b * Ee + e) * Dd + tid] = s * (1.f / (float)Dd);
    }
    // gram = sum_r p_r^T MV p_r
    float acc = 0.f;
    for (int r = w; r < Dd; r += 8) {
        float t0 = 0.f, t1 = 0.f;
        for (int bbk = 0; bbk < Dd; bbk++) {
            float p = P[r][bbk];
            t0 += MVs[lane * Dd + bbk] * p;
            if (lane + 32 < Dd) t1 += MVs[(lane + 32) * Dd + bbk] * p;
        }
        acc += P[r][lane] * t0;
        if (lane + 32 < Dd) acc += P[r][lane + 32] * t1;
    }
#pragma unroll
    for (int o = 16; o; o >>= 1) acc += __shfl_xor_sync(0xffffffffu, acc, o);
    if (lane == 0) gpart[w] = acc;
    __syncthreads();
    if (tid == 0) {
        float s = 0.f;
        for (int q = 0; q < 8; q++) s += gpart[q];
        g_gram[b * Ee + e] = s;
    }
}

// zbar = w^T Vp + epb ; stats s1, s2 via Gram identity
__global__ void zbar_stats_kernel(const float* __restrict__ ep_b) {
    int i = blockIdx.x, b = blockIdx.y;
    __shared__ float ws[Nn * Dd];
    __shared__ float sm[32];
    int tid = threadIdx.x; // 512
    for (int t = tid; t < Nn * Dd; t += 512) {
        int j = t / Dd, d2 = t % Dd;
        ws[t] = g_w[((long)b * Ee + i * Nn + j) * Dd + d2];
    }
    __syncthreads();
    float acc[Nn];
#pragma unroll
    for (int j = 0; j < Nn; j++) acc[j] = 0.f;
    const float* Vb = g_Vp + (long)((b * Nn + i) * Dd) * Cch;
    for (int d2 = 0; d2 < Dd; d2++) {
        float v = Vb[(long)d2 * Cch + tid];
#pragma unroll
        for (int j = 0; j < Nn; j++) acc[j] += ws[j * Dd + d2] * v;
    }
    float eb = ep_b[tid];
    float E = block_reduce_sum(eb * eb, sm);
    for (int j = 0; j < Nn; j++) {
        int e = i * Nn + j;
        float z = acc[j] + eb;
        g_zbar[((long)b * Ee + e) * Cch + tid] = z;
        float S = block_reduce_sum(z, sm);
        float T = block_reduce_sum(eb * z, sm);
        if (tid == 0) {
            g_ps1[b * Ee + e] = 49.f * S;
            g_ps2[b * Ee + e] = g_gram[b * Ee + e] + 98.f * T - 49.f * E;
        }
    }
}

// ---------------- cosine adjacency mask --------------------------------------
__global__ void mask_kernel() {
    int b = blockIdx.x;
    __shared__ float sinv[Nn];
    __shared__ float adj[Ee];
    __shared__ float dis[Nn];
    int tid = threadIdx.x; // 256
    if (tid < Nn) {
        const float* f = g_fv + (long)(b * Nn + tid) * Cch;
        float s = 0.f;
        for (int c = 0; c < Cch; c++) s += f[c] * f[c];
        sinv[tid] = 1.f / fmaxf(sqrtf(s), 1e-12f);
    }
    __syncthreads();
    if (tid < Ee) {
        int i = tid / Nn, jn = tid % Nn;
        const float* fi = g_fv + (long)(b * Nn + i) * Cch;
        const float* fj = g_fv + (long)(b * Nn + jn) * Cch;
        float s = 0.f;
        for (int c = 0; c < Cch; c++) s += fi[c] * fj[c];
        adj[tid] = s * sinv[i] * sinv[jn];
    }
    __syncthreads();
    if (tid < Nn) {
        float s = 0.f;
        for (int jn = 0; jn < Nn; jn++) s += adj[tid * Nn + jn];
        dis[tid] = rsqrtf(s);
    }
    __syncthreads();
    if (tid < Ee) {
        int i = tid / Nn, jn = tid % Nn;
        g_mask[b * Ee + tid] = adj[tid] * dis[i] * dis[jn];
    }
}

// ---------------- edge BN + mask ---------------------------------------------
__global__ void edge_bn_mask_kernel() {
    int e = blockIdx.x;
    __shared__ float mrs[2];
    int tid = threadIdx.x; // 256
    if (tid == 0) {
        float s1 = 0.f, s2 = 0.f;
        for (int b = 0; b < Bb; b++) { s1 += g_ps1[b * Ee + e]; s2 += g_ps2[b * Ee + e]; }
        float cnt = (float)(Bb * Dd * Cch);
        float m = s1 / cnt;
        float v = s2 / cnt - m * m;
        mrs[0] = m;
        mrs[1] = rsqrtf(fmaxf(v, 0.f) + EPS_);
    }
    __syncthreads();
    float m = mrs[0], r = mrs[1];
    for (int b = 0; b < Bb; b++) {
        float mk = g_mask[b * Ee + e];
        long base = (long)(b * Ee + e) * Cch;
        g_fe[base + tid]       = (g_zbar[base + tid] - m) * r * mk;
        g_fe[base + tid + 256] = (g_zbar[base + tid + 256] - m) * r * mk;
    }
}

// ---------------- GNN layer pieces -------------------------------------------
__global__ void agg_bn_kernel() {
    int e = blockIdx.x;
    int i = e / Nn, jn = e % Nn;
    __shared__ float sm[64];
    __shared__ float mrs[2];
    int tid = threadIdx.x; // 256
    float s1 = 0.f, s2 = 0.f;
    for (int b = 0; b < Bb; b++) {
        long na = (long)(b * Nn + i) * 2048;
        long nb = (long)(b * Nn + jn) * 2048;
        long ne = (long)(b * Ee + e) * Cch;
#pragma unroll
        for (int cc = 0; cc < 2; cc++) {
            int c = tid + cc * 256;
            float v = g_xnode[na + c] + g_xnode[nb + 512 + c] + g_xw[ne + c];
            g_agg[ne + c] = v;
            s1 += v; s2 += v * v;
        }
    }
    s1 = block_reduce_sum(s1, sm);
    s2 = block_reduce_sum(s2, sm);
    if (tid == 0) {
        float cnt = (float)(Bb * Cch);
        float m = s1 / cnt;
        float v = s2 / cnt - m * m;
        mrs[0] = m;
        mrs[1] = rsqrtf(fmaxf(v, 0.f) + EPS_);
    }
    __syncthreads();
    float m = mrs[0], r = mrs[1];
    for (int b = 0; b < Bb; b++) {
        long ne = (long)(b * Ee + e) * Cch;
#pragma unroll
        for (int cc = 0; cc < 2; cc++) {
            int c = tid + cc * 256;
            g_fe[ne + c] += fmaxf((g_agg[ne + c] - m) * r, 0.f);
        }
    }
}

__global__ void softmax_msg_kernel() {
    int bi = blockIdx.x;
    int b = bi / Nn, i = bi % Nn;
    int c = threadIdx.x; // 512
    float v[Nn];
    float mx = -1e30f;
#pragma unroll
    for (int jn = 0; jn < Nn; jn++) {
        float ed = g_fe[((long)(b * Ee + i * Nn + jn)) * Cch + c];
        float s = 1.f / (1.f + expf(-ed));
        v[jn] = s;
        mx = fmaxf(mx, s);
    }
    float sum = 0.f;
#pragma unroll
    for (int jn = 0; jn < Nn; jn++) { v[jn] = expf(v[jn] - mx); sum += v[jn]; }
    float acc = 0.f;
#pragma unroll
    for (int jn = 0; jn < Nn; jn++)
        acc += v[jn] * g_xnode[(long)(b * Nn + jn) * 2048 + 1536 + c];
    g_msg[(long)(b * Nn + i) * Cch + c] = acc / (sum * (float)Nn);
}

__global__ void node_bn_kernel() {
    int n = blockIdx.x;
    __shared__ float sm[64];
    __shared__ float mrs[2];
    int tid = threadIdx.x; // 256
    float s1 = 0.f, s2 = 0.f;
    for (int b = 0; b < Bb; b++) {
        long base = (long)(b * Nn + n) * Cch;
        long xub = (long)(b * Nn + n) * 2048 + 1024;
#pragma unroll
        for (int cc = 0; cc < 2; cc++) {
            int c = tid + cc * 256;
            float t = g_xnode[xub + c] + g_msg[base + c];
            g_t[base + c] = t;
            s1 += t; s2 += t * t;
        }
    }
    s1 = block_reduce_sum(s1, sm);
    s2 = block_reduce_sum(s2, sm);
    if (tid == 0) {
        float cnt = (float)(Bb * Cch);
        float m = s1 / cnt;
        float v = s2 / cnt - m * m;
        mrs[0] = m;
        mrs[1] = rsqrtf(fmaxf(v, 0.f) + EPS_);
    }
    __syncthreads();
    float m = mrs[0], r = mrs[1];
    for (int b = 0; b < Bb; b++) {
        long base = (long)(b * Nn + n) * Cch;
#pragma unroll
        for (int cc = 0; cc < 2; cc++) {
            int c = tid + cc * 256;
            g_fv[base + c] = fmaxf(g_fv[base + c] + (g_t[base + c] - m) * r, 0.f);
        }
    }
}

// ---------------- classifier heads -------------------------------------------
__global__ void cls_kernel(const float* __restrict__ sc_w, float* __restrict__ out) {
    int bn = blockIdx.x; // b*12+n
    int n = bn % Nn;
    __shared__ float sm[32];
    int tid = threadIdx.x; // 128
    float sf = 0.f, ff = 0.f, ss = 0.f;
    for (int c = tid; c < Cch; c += 128) {
        float f = g_fv[(long)bn * Cch + c];
        float s = fmaxf(sc_w[n * Cch + c], 0.f);
        sf += f * s; ff += f * f; ss += s * s;
    }
    sf = block_reduce_sum(sf, sm);
    ff = block_reduce_sum(ff, sm);
    ss = block_reduce_sum(ss, sm);
    if (tid == 0)
        out[bn] = sf / (fmaxf(sqrtf(ff), 1e-12f) * fmaxf(sqrtf(ss), 1e-12f));
}

__global__ void edgefc_kernel(const float* __restrict__ w, const float* __restrict__ bias,
                              float* __restrict__ out) {
    int row = blockIdx.x; // b*144+e
    int tid = threadIdx.x; // 128
    int k = tid >> 5, lane = tid & 31;
    const float* f = g_fe + (long)row * Cch;
    float dot = 0.f;
    for (int c = lane; c < Cch; c += 32) dot += f[c] * w[c * 4 + k];
#pragma unroll
    for (int o = 16; o; o >>= 1) dot += __shfl_xor_sync(0xffffffffu, dot, o);
    if (lane == 0) out[96 + row * 4 + k] = dot + bias[k];
}

// ---------------- host driver -------------------------------------------------
extern "C" void kernel_launch(void* const* d_in, const int* in_sizes, int n_in,
                              void* d_out, int out_size) {
    const float* x      = (const float*)d_in[0];
    const float* Wc     = (const float*)d_in[1];
    const float* bc     = (const float*)d_in[2];
    const float* fam_wq = (const float*)d_in[3];
    const float* fam_bq = (const float*)d_in[4];
    const float* fam_wk = (const float*)d_in[5];
    const float* fam_bk = (const float*)d_in[6];
    const float* fam_wv = (const float*)d_in[7];
    const float* fam_bv = (const float*)d_in[8];
    const float* arm_wq = (const float*)d_in[9];
    const float* arm_bq = (const float*)d_in[10];
    const float* arm_wk = (const float*)d_in[11];
    const float* arm_bk = (const float*)d_in[12];
    const float* arm_wv = (const float*)d_in[13];
    const float* arm_bv = (const float*)d_in[14];
    const float* ep_w   = (const float*)d_in[15];
    const float* ep_b   = (const float*)d_in[16];
    const float* gw[10];
    for (int t = 0; t < 10; t++) gw[t] = (const float*)d_in[17 + t];
    const float* sc_w   = (const float*)d_in[27];
    const float* efc_w  = (const float*)d_in[28];
    const float* efc_b  = (const float*)d_in[29];
    float* out = (float*)d_out;

    float *p_h, *p_q1, *p_k1, *p_v1, *p_f1, *p_QK2, *p_Vp, *p_Wvp, *p_bvp;
    float *p_wqk, *p_bqk, *p_S, *p_MV, *p_fv, *p_fe, *p_wnode, *p_xnode, *p_xw;
    cudaGetSymbolAddress((void**)&p_h, g_h);
    cudaGetSymbolAddress((void**)&p_q1, g_q1);
    cudaGetSymbolAddress((void**)&p_k1, g_k1);
    cudaGetSymbolAddress((void**)&p_v1, g_v1);
    cudaGetSymbolAddress((void**)&p_f1, g_feat1);
    cudaGetSymbolAddress((void**)&p_QK2, g_QK2);
    cudaGetSymbolAddress((void**)&p_Vp, g_Vp);
    cudaGetSymbolAddress((void**)&p_Wvp, g_Wvp);
    cudaGetSymbolAddress((void**)&p_bvp, g_bvp);
    cudaGetSymbolAddress((void**)&p_wqk, g_wqk);
    cudaGetSymbolAddress((void**)&p_bqk, g_bqk);
    cudaGetSymbolAddress((void**)&p_S, g_S);
    cudaGetSymbolAddress((void**)&p_MV, g_MV);
    cudaGetSymbolAddress((void**)&p_fv, g_fv);
    cudaGetSymbolAddress((void**)&p_fe, g_fe);
    cudaGetSymbolAddress((void**)&p_wnode, g_wnode);
    cudaGetSymbolAddress((void**)&p_xnode, g_xnode);
    cudaGetSymbolAddress((void**)&p_xw, g_xw);

    // pack arm_wq|arm_wk
    pack_qk_kernel<<<1024, 256>>>(arm_wq, arm_wk, arm_bq, arm_bk);

    // h = x @ Wc[n] + bc[n], z = 12 classes
    gemm128_kernel<<<dim3(4, 4, 12), 256>>>(x, Wc, bc, p_h, ND, Cch, Cch,
                                            Cch, Cch, Cch,
                                            0, (long)Cch * Cch, (long)ND * Cch);
    bn1_stats_kernel<<<dim3(12, 4), 128>>>();
    bn1_apply_kernel<<<dim3(12, 8), 256>>>();

    // first attention projections (K/V shared across classes)
    gemm64_kernel<<<dim3(4, 7, 1), 256>>>(x, fam_wk, fam_bk, p_k1, ND, Hh, Cch,
                                          Cch, Hh, Hh, 0, 0, 0, 0);
    gemm64_kernel<<<dim3(8, 7, 1), 256>>>(x, fam_wv, fam_bv, p_v1, ND, Cch, Cch,
                                          Cch, Cch, Cch, 0, 0, 0, 0);
    gemm128_kernel<<<dim3(2, 37, 1), 256>>>(p_h, fam_wq, fam_bq, p_q1, RQ, Hh, Cch,
                                            Cch, Hh, Hh, 0, 0, 0);
    attn1_kernel<<<RQ, 128>>>();

    // fold ep projection: Wvp = arm_wv @ ep_w, bvp = arm_bv @ ep_w
    gemm64_kernel<<<dim3(8, 8, 1), 256>>>(arm_wv, ep_w, nullptr, p_Wvp, Cch, Cch, Cch,
                                          Cch, Cch, Cch, 0, 0, 0, 0);
    bvp_kernel<<<1, 512>>>(arm_bv, ep_w);

    // Q2|K2 in one GEMM; Vp with folded ep
    gemm128_kernel<<<dim3(4, 37, 1), 256>>>(p_f1, p_wqk, p_bqk, p_QK2, RQ, Cch, Cch,
                                            Cch, Cch, Cch, 0, 0, 0);
    gemm128_kernel<<<dim3(4, 37, 1), 256>>>(p_f1, p_Wvp, p_bvp, p_Vp, RQ, Cch, Cch,
                                            Cch, Cch, Cch, 0, 0, 0);

    // attn2 scores: S[b] = Q2_b @ K2_b^T  (588x588x256, z=8)
    gemm64_kernel<<<dim3(10, 10, 8), 256>>>(p_QK2, p_QK2 + 256, nullptr, p_S,
                                            SQ, SQ, Hh, Cch, Cch, SQ,
                                            (long)SQ * Cch, (long)SQ * Cch, (long)SQ * SQ, 1);
    // MV[b,i] = Vp_bi @ Vp_bi^T (49x49x512, z=96)
    gemm64_kernel<<<dim3(1, 1, 96), 256>>>(p_Vp, p_Vp, nullptr, p_MV,
                                           Dd, Dd, Cch, Cch, Cch, Dd,
                                           (long)Dd * Cch, (long)Dd * Cch, (long)Dd * Dd, 1);
    pg_kernel<<<dim3(Ee, Bb), 256>>>();
    zbar_stats_kernel<<<dim3(Nn, Bb), 512>>>(ep_b);
    mask_kernel<<<Bb, 256>>>();
    edge_bn_mask_kernel<<<Ee, 256>>>();

    // two GNN layers
    for (int L = 0; L < 2; L++) {
        pack_node_kernel<<<4096, 256>>>(gw[L * 5 + 0], gw[L * 5 + 1],
                                        gw[L * 5 + 3], gw[L * 5 + 4]);
        // xnode = fv @ [wa|wb|wu|wv]
        gemm64_kernel<<<dim3(32, 2, 1), 256>>>(p_fv, p_wnode, nullptr, p_xnode,
                                               Bb * Nn, 2048, Cch, Cch, 2048, 2048,
                                               0, 0, 0, 0);
        // xw = fe @ we
        gemm64_kernel<<<dim3(8, 18, 1), 256>>>(p_fe, gw[L * 5 + 2], nullptr, p_xw,
                                               Bb * Ee, Cch, Cch, Cch, Cch, Cch,
                                               0, 0, 0, 0);
        agg_bn_kernel<<<Ee, 256>>>();
        softmax_msg_kernel<<<Bb * Nn, 512>>>();
        node_bn_kernel<<<Nn, 256>>>();
    }

    cls_kernel<<<Bb * Nn, 128>>>(sc_w, out);
    edgefc_kernel<<<Bb * Ee, 128>>>(efc_w, efc_b, out);
}

// round 4
// speedup vs baseline: 2.8828x; 1.2513x over previous
#include <cuda_runtime.h>
#include <math.h>
#include <stdint.h>

// Problem constants
#define Bb   8
#define Dd   49
#define Cch  512
#define Nn   12
#define Hh   256          // C/2
#define Ee   144          // N*N
#define ND   392          // B*D
#define RQ   4704         // N*B*D
#define SQ   588          // N*D (rows per batch in attn2)
#define SCALE_ 0.0625f    // (C/2)^-0.5
#define EPS_  1e-5f

// ---------------- static device scratch -------------------------------------
__device__ float g_h[RQ * Cch];          // h then f_u in place, rows (n*8+b)*49+d
__device__ float g_q1[RQ * Hh];
__device__ float g_k1[ND * Hh];
__device__ float g_v1[(ND + 16) * Cch];  // padded 16 rows (zeros) for K=64 AV gemm
__device__ float g_S1[96 * Dd * Dd];     // attn1 scores per (n,b)
__device__ float g_P[96 * Dd * 64];      // attn1 probs, K-padded to 64
__device__ float g_feat1[RQ * Cch];      // rows (b*12+n)*49+d  (b-major)
__device__ float g_QK2[RQ * Cch];        // cols 0-255 = Q2, 256-511 = K2
__device__ float g_Vp[RQ * Cch];         // feat1 @ (arm_wv@ep_w) + arm_bv@ep_w
__device__ float g_Wvp[Cch * Cch];
__device__ float g_bvp[Cch];
__device__ float g_wqk[Cch * Cch];       // packed arm_wq | arm_wk
__device__ float g_bqk[Cch];
__device__ float g_S[Bb * SQ * SQ];      // attn2 raw scores
__device__ float g_MV[Bb * Nn * Dd * Dd];// Vp Gram per (b,i)
__device__ float g_w[Bb * Ee * Dd];      // aggregated attention weights
__device__ float g_gram[Bb * Ee];        // <P^T P, MV>
__device__ float g_fv[Bb * Nn * Cch];
__device__ float g_zbar[Bb * Ee * Cch];
__device__ float g_ps1[Bb * Ee];
__device__ float g_ps2[Bb * Ee];
__device__ float g_bn1m[Nn * Cch];
__device__ float g_bn1r[Nn * Cch];
__device__ float g_mask[Bb * Ee];
__device__ float g_fe[Bb * Ee * Cch];
__device__ float g_wnode[Cch * 2048];    // packed wa|wb|wu|wv
__device__ float g_xnode[Bb * Nn * 2048];
__device__ float g_xw[Bb * Ee * Cch];
__device__ float g_agg[Bb * Ee * Cch];
__device__ float g_msg[Bb * Nn * Cch];
__device__ float g_t[Bb * Nn * Cch];

// ---------------- helpers ----------------------------------------------------
__device__ __forceinline__ float block_reduce_sum(float v, float* sm) {
    int lane = threadIdx.x & 31, w = threadIdx.x >> 5;
#pragma unroll
    for (int o = 16; o; o >>= 1) v += __shfl_xor_sync(0xffffffffu, v, o);
    if (lane == 0) sm[w] = v;
    __syncthreads();
    int nw = (blockDim.x + 31) >> 5;
    float r = 0.f;
    if (threadIdx.x < 32) {
        r = (threadIdx.x < nw) ? sm[threadIdx.x] : 0.f;
#pragma unroll
        for (int o = 16; o; o >>= 1) r += __shfl_xor_sync(0xffffffffu, r, o);
        if (threadIdx.x == 0) sm[0] = r;
    }
    __syncthreads();
    r = sm[0];
    __syncthreads();
    return r;
}

__device__ __forceinline__ uint32_t f2tf32(float x) {
    uint32_t r;
    asm("cvt.rna.tf32.f32 %0, %1;" : "=r"(r) : "f"(x));
    return r;
}

__device__ __forceinline__ void mma_tf32(float* c, const uint32_t* a, const uint32_t* b) {
    asm volatile(
        "mma.sync.aligned.m16n8k8.row.col.f32.tf32.tf32.f32 "
        "{%0,%1,%2,%3}, {%4,%5,%6,%7}, {%8,%9}, {%0,%1,%2,%3};"
        : "+f"(c[0]), "+f"(c[1]), "+f"(c[2]), "+f"(c[3])
        : "r"(a[0]), "r"(a[1]), "r"(a[2]), "r"(a[3]), "r"(b[0]), "r"(b[1]));
}

// ---------------- gemm_tc: TF32 tensor-core GEMM, 128x128x16 -----------------
// C = A(MxK) @ op(B) + bias.  transB: B is (N x K) row-major.
// z batching: offset = (z/zdiv)*s?1 + (z%zdiv)*s?2 for A, B, C.
__global__ __launch_bounds__(256) void gemm_tc(
    const float* __restrict__ A, const float* __restrict__ Bm,
    const float* __restrict__ bias, float* __restrict__ Cm,
    int M, int Np, int K, int lda, int ldb, int ldc,
    long sA1, long sA2, long sB1, long sB2, long sC1, long sC2,
    int zdiv, int transB)
{
    int z = blockIdx.z;
    int zq = z / zdiv, zr = z % zdiv;
    const float* Az = A + zq * sA1 + (long)zr * sA2;
    const float* Bz = Bm + zq * sB1 + (long)zr * sB2;
    float* Cz = Cm + zq * sC1 + (long)zr * sC2;

    __shared__ float As[2][16][132];
    __shared__ float Bs[2][16][132];
    int tid = threadIdx.x;
    int row0 = blockIdx.y * 128, col0 = blockIdx.x * 128;

    int arow = tid >> 1, ak0 = (tid & 1) * 8;   // A / B-NT loader
    int bkk = tid >> 4, bn0 = (tid & 15) * 8;   // B-NN loader

    int warp = tid >> 5, lane = tid & 31;
    int wm = (warp >> 2) * 64, wn = (warp & 3) * 32;
    int gid = lane >> 2, tig = lane & 3;

    float c[4][4][4];
#pragma unroll
    for (int mi = 0; mi < 4; mi++)
#pragma unroll
        for (int ni = 0; ni < 4; ni++)
#pragma unroll
            for (int q = 0; q < 4; q++) c[mi][ni][q] = 0.f;

    const float4 z4 = {0.f, 0.f, 0.f, 0.f};
    float4 a0g, a1g, b0g, b1g;

#define LOAD_TILE(k0)                                                          \
    {                                                                          \
        int gr = row0 + arow;                                                  \
        if (gr < M) {                                                          \
            const float* p = Az + (long)gr * lda + (k0) + ak0;                 \
            a0g = *(const float4*)p; a1g = *(const float4*)(p + 4);            \
        } else { a0g = z4; a1g = z4; }                                         \
        if (!transB) {                                                         \
            int gc = col0 + bn0;                                               \
            if (gc < Np) {                                                     \
                const float* p = Bz + (long)((k0) + bkk) * ldb + gc;           \
                b0g = *(const float4*)p; b1g = *(const float4*)(p + 4);        \
            } else { b0g = z4; b1g = z4; }                                     \
        } else {                                                               \
            int gn = col0 + arow;                                              \
            if (gn < Np) {                                                     \
                const float* p = Bz + (long)gn * ldb + (k0) + ak0;             \
                b0g = *(const float4*)p; b1g = *(const float4*)(p + 4);        \
            } else { b0g = z4; b1g = z4; }                                     \
        }                                                                      \
    }

#define STORE_TILE(buf)                                                        \
    {                                                                          \
        As[buf][ak0+0][arow]=a0g.x; As[buf][ak0+1][arow]=a0g.y;                \
        As[buf][ak0+2][arow]=a0g.z; As[buf][ak0+3][arow]=a0g.w;                \
        As[buf][ak0+4][arow]=a1g.x; As[buf][ak0+5][arow]=a1g.y;                \
        As[buf][ak0+6][arow]=a1g.z; As[buf][ak0+7][arow]=a1g.w;                \
        if (!transB) {                                                         \
            *(float4*)&Bs[buf][bkk][bn0] = b0g;                                \
            *(float4*)&Bs[buf][bkk][bn0+4] = b1g;                              \
        } else {                                                               \
            Bs[buf][ak0+0][arow]=b0g.x; Bs[buf][ak0+1][arow]=b0g.y;            \
            Bs[buf][ak0+2][arow]=b0g.z; Bs[buf][ak0+3][arow]=b0g.w;            \
            Bs[buf][ak0+4][arow]=b1g.x; Bs[buf][ak0+5][arow]=b1g.y;            \
            Bs[buf][ak0+6][arow]=b1g.z; Bs[buf][ak0+7][arow]=b1g.w;            \
        }                                                                      \
    }

    LOAD_TILE(0);
    STORE_TILE(0);
    __syncthreads();

    int nt = K >> 4;
    for (int t = 0; t < nt; t++) {
        int buf = t & 1;
        if (t + 1 < nt) LOAD_TILE((t + 1) << 4);
#pragma unroll
        for (int k8 = 0; k8 < 16; k8 += 8) {
            uint32_t af[4][4], bf[4][2];
#pragma unroll
            for (int mi = 0; mi < 4; mi++) {
                int mb = wm + mi * 16;
                af[mi][0] = f2tf32(As[buf][k8 + tig][mb + gid]);
                af[mi][1] = f2tf32(As[buf][k8 + tig][mb + gid + 8]);
                af[mi][2] = f2tf32(As[buf][k8 + tig + 4][mb + gid]);
                af[mi][3] = f2tf32(As[buf][k8 + tig + 4][mb + gid + 8]);
            }
#pragma unroll
            for (int ni = 0; ni < 4; ni++) {
                int nb = wn + ni * 8 + gid;
                bf[ni][0] = f2tf32(Bs[buf][k8 + tig][nb]);
                bf[ni][1] = f2tf32(Bs[buf][k8 + tig + 4][nb]);
            }
#pragma unroll
            for (int mi = 0; mi < 4; mi++)
#pragma unroll
                for (int ni = 0; ni < 4; ni++)
                    mma_tf32(c[mi][ni], af[mi], bf[ni]);
        }
        if (t + 1 < nt) {
            STORE_TILE(buf ^ 1);
            __syncthreads();
        }
    }

#pragma unroll
    for (int mi = 0; mi < 4; mi++) {
        int r0 = row0 + wm + mi * 16 + gid;
        int r1 = r0 + 8;
#pragma unroll
        for (int ni = 0; ni < 4; ni++) {
            int cb = col0 + wn + ni * 8 + 2 * tig;
            float bv0 = 0.f, bv1 = 0.f;
            if (bias) {
                if (cb < Np) bv0 = bias[cb];
                if (cb + 1 < Np) bv1 = bias[cb + 1];
            }
            if (r0 < M) {
                if (cb < Np)     Cz[(long)r0 * ldc + cb]     = c[mi][ni][0] + bv0;
                if (cb + 1 < Np) Cz[(long)r0 * ldc + cb + 1] = c[mi][ni][1] + bv1;
            }
            if (r1 < M) {
                if (cb < Np)     Cz[(long)r1 * ldc + cb]     = c[mi][ni][2] + bv0;
                if (cb + 1 < Np) Cz[(long)r1 * ldc + cb + 1] = c[mi][ni][3] + bv1;
            }
        }
    }
#undef LOAD_TILE
#undef STORE_TILE
}

// ---------------- gemm64 (fp32, kept only for the MV Gram) -------------------
__global__ __launch_bounds__(256) void gemm64_kernel(
    const float* __restrict__ A, const float* __restrict__ Bm,
    const float* __restrict__ bias, float* __restrict__ Cm,
    int M, int Np, int K, int lda, int ldb, int ldc,
    long sA, long sB, long sC, int transB)
{
    const float* Az = A + (long)blockIdx.z * sA;
    const float* Bz = Bm + (long)blockIdx.z * sB;
    float* Cz = Cm + (long)blockIdx.z * sC;
    __shared__ float As[16][64];
    __shared__ float Bs[16][64];
    int tid = threadIdx.x;
    int tx = tid & 15, ty = tid >> 4;
    int row0 = blockIdx.y * 64, col0 = blockIdx.x * 64;
    int lr = tid >> 2, lk = (tid & 3) * 4;
    int bkk = tid >> 4, bn = (tid & 15) * 4;
    const float4 z4 = {0.f, 0.f, 0.f, 0.f};
    float acc[4][4];
#pragma unroll
    for (int i = 0; i < 4; i++)
#pragma unroll
        for (int j = 0; j < 4; j++) acc[i][j] = 0.f;

    for (int k0 = 0; k0 < K; k0 += 16) {
        float4 av = z4, bv = z4;
        if (row0 + lr < M) av = *(const float4*)(Az + (long)(row0 + lr) * lda + k0 + lk);
        if (!transB) {
            if (col0 + bn < Np) bv = *(const float4*)(Bz + (long)(k0 + bkk) * ldb + col0 + bn);
        } else {
            if (col0 + lr < Np) bv = *(const float4*)(Bz + (long)(col0 + lr) * ldb + k0 + lk);
        }
        __syncthreads();
        As[lk+0][lr]=av.x; As[lk+1][lr]=av.y; As[lk+2][lr]=av.z; As[lk+3][lr]=av.w;
        if (!transB) {
            *(float4*)&Bs[bkk][bn] = bv;
        } else {
            Bs[lk+0][lr]=bv.x; Bs[lk+1][lr]=bv.y; Bs[lk+2][lr]=bv.z; Bs[lk+3][lr]=bv.w;
        }
        __syncthreads();
#pragma unroll
        for (int kk = 0; kk < 16; kk++) {
            float4 a4 = *(const float4*)&As[kk][ty * 4];
            float4 b4 = *(const float4*)&Bs[kk][tx * 4];
            float a[4] = {a4.x, a4.y, a4.z, a4.w};
            float b[4] = {b4.x, b4.y, b4.z, b4.w};
#pragma unroll
            for (int i = 0; i < 4; i++)
#pragma unroll
                for (int j = 0; j < 4; j++) acc[i][j] += a[i] * b[j];
        }
    }
#pragma unroll
    for (int i = 0; i < 4; i++) {
        int gr = row0 + ty * 4 + i;
        if (gr >= M) continue;
#pragma unroll
        for (int j = 0; j < 4; j++) {
            int gc = col0 + tx * 4 + j;
            if (gc < Np)
                Cz[(long)gr * ldc + gc] = acc[i][j] + (bias ? bias[gc] : 0.f);
        }
    }
}

// ---------------- weight packers / misc --------------------------------------
__global__ void pack_qk_kernel(const float* __restrict__ wq, const float* __restrict__ wk,
                               const float* __restrict__ bq, const float* __restrict__ bk) {
    int idx = blockIdx.x * 256 + threadIdx.x;        // 512*512
    int k = idx >> 9, c = idx & 511;
    g_wqk[idx] = (c < 256) ? wq[k * 256 + c] : wk[k * 256 + c - 256];
    if (idx < 512) g_bqk[idx] = (idx < 256) ? bq[idx] : bk[idx - 256];
}

__global__ void pack_node_kernel(const float* __restrict__ wa, const float* __restrict__ wb,
                                 const float* __restrict__ wu, const float* __restrict__ wv) {
    int idx = blockIdx.x * 256 + threadIdx.x;        // 512*2048
    int k = idx >> 11, c = idx & 2047;
    const float* src = (c < 512) ? wa : (c < 1024) ? wb : (c < 1536) ? wu : wv;
    g_wnode[idx] = src[k * 512 + (c & 511)];
}

__global__ void zero_v1pad_kernel() {
    int i = blockIdx.x * 256 + threadIdx.x;
    if (i < 16 * Cch) g_v1[ND * Cch + i] = 0.f;
}

// ---------------- BN1 ---------------------------------------------------------
__global__ void bn1_stats_kernel() {
    int n = blockIdx.x;
    int c = blockIdx.y * 128 + threadIdx.x;
    float s1 = 0.f, s2 = 0.f;
    const float* base = g_h + (long)n * ND * Cch + c;
    for (int r = 0; r < ND; r++) {
        float v = base[(long)r * Cch];
        s1 += v; s2 += v * v;
    }
    float m = s1 / (float)ND;
    float var = s2 / (float)ND - m * m;
    g_bn1m[n * Cch + c] = m;
    g_bn1r[n * Cch + c] = rsqrtf(fmaxf(var, 0.f) + EPS_);
}

__global__ void bn1_apply_kernel() {
    int n = blockIdx.x, b = blockIdx.y;
    int tid = threadIdx.x; // 256
#pragma unroll
    for (int cc = 0; cc < 2; cc++) {
        int c = tid + cc * 256;
        float m = g_bn1m[n * Cch + c];
        float r = g_bn1r[n * Cch + c];
        float acc = 0.f;
        long base = ((long)(n * Bb + b) * Dd) * Cch + c;
        for (int d = 0; d < Dd; d++) {
            long idx = base + (long)d * Cch;
            float u = fmaxf((g_h[idx] - m) * r, 0.f);
            g_h[idx] = u;
            acc += u;
        }
        g_fv[(long)(b * Nn + n) * Cch + c] = acc / (float)Dd;
    }
}

// ---------------- attn1 softmax (S1 -> P, zero-padded K to 64) ----------------
__global__ void softmaxP_kernel() {
    int z = blockIdx.x;                 // z = n*8+b
    int tid = threadIdx.x, w = tid >> 5, lane = tid & 31;
    const float* Sb = g_S1 + (long)z * Dd * Dd;
    float* Pb = g_P + (long)z * Dd * 64;
    for (int r = w; r < Dd; r += 8) {
        float v0 = (lane < Dd) ? Sb[r * Dd + lane] * SCALE_ : -1e30f;
        float v1 = (lane + 32 < Dd) ? Sb[r * Dd + lane + 32] * SCALE_ : -1e30f;
        float mx = fmaxf(v0, v1);
#pragma unroll
        for (int o = 16; o; o >>= 1) mx = fmaxf(mx, __shfl_xor_sync(0xffffffffu, mx, o));
        float e0 = (lane < Dd) ? expf(v0 - mx) : 0.f;
        float e1 = (lane + 32 < Dd) ? expf(v1 - mx) : 0.f;
        float s = e0 + e1;
#pragma unroll
        for (int o = 16; o; o >>= 1) s += __shfl_xor_sync(0xffffffffu, s, o);
        float inv = 1.f / s;
        if (lane < Dd) Pb[r * 64 + lane] = e0 * inv;
        Pb[r * 64 + lane + 32] = (lane + 32 < Dd) ? e1 * inv : 0.f;
    }
}

// bvp = arm_bv @ ep_w
__global__ void bvp_kernel(const float* __restrict__ bv, const float* __restrict__ epw) {
    int c = threadIdx.x; // 512
    float s = 0.f;
    for (int k = 0; k < Cch; k++) s += bv[k] * epw[k * Cch + c];
    g_bvp[c] = s;
}

// ---------------- attn2: per-(b,e) softmax + aggregated weights + Gram term ---
__global__ void pg_kernel() {
    int e = blockIdx.x, b = blockIdx.y;
    int i = e / Nn, j = e % Nn;
    __shared__ float P[49][50];
    __shared__ float MVs[Dd * Dd];
    __shared__ float gpart[8];
    int tid = threadIdx.x, w = tid >> 5, lane = tid & 31;
    const float* MVg = g_MV + (long)(b * Nn + i) * (Dd * Dd);
    for (int t = tid; t < Dd * Dd; t += 256) MVs[t] = MVg[t];
    const float* Sb = g_S + (long)b * SQ * SQ + (long)(j * Dd) * SQ + i * Dd;
    for (int r = w; r < Dd; r += 8) {
        float v0 = (lane < Dd) ? Sb[r * SQ + lane] * SCALE_ : -1e30f;
        float v1 = (lane + 32 < Dd) ? Sb[r * SQ + lane + 32] * SCALE_ : -1e30f;
        float mx = fmaxf(v0, v1);
#pragma unroll
        for (int o = 16; o; o >>= 1) mx = fmaxf(mx, __shfl_xor_sync(0xffffffffu, mx, o));
        float e0 = (lane < Dd) ? expf(v0 - mx) : 0.f;
        float e1 = (lane + 32 < Dd) ? expf(v1 - mx) : 0.f;
        float s = e0 + e1;
#pragma unroll
        for (int o = 16; o; o >>= 1) s += __shfl_xor_sync(0xffffffffu, s, o);
        float inv = 1.f / s;
        if (lane < Dd) P[r][lane] = e0 * inv;
        if (lane + 32 < Dd) P[r][lane + 32] = e1 * inv;
    }
    __syncthreads();
    if (tid < Dd) {
        float s = 0.f;
        for (int r = 0; r < Dd; r++) s += P[r][tid];
        g_w[((long)b * Ee + e) * Dd + tid] = s * (1.f / (float)Dd);
    }
    // gram = sum_r p_r^T MV p_r
    float acc = 0.f;
    for (int r = w; r < Dd; r += 8) {
        float t0 = 0.f, t1 = 0.f;
        for (int bbk = 0; bbk < Dd; bbk++) {
            float p = P[r][bbk];
            t0 += MVs[lane * Dd + bbk] * p;
            if (lane + 32 < Dd) t1 += MVs[(lane + 32) * Dd + bbk] * p;
        }
        acc += P[r][lane] * t0;
        if (lane + 32 < Dd) acc += P[r][lane + 32] * t1;
    }
#pragma unroll
    for (int o = 16; o; o >>= 1) acc += __shfl_xor_sync(0xffffffffu, acc, o);
    if (lane == 0) gpart[w] = acc;
    __syncthreads();
    if (tid == 0) {
        float s = 0.f;
        for (int q = 0; q < 8; q++) s += gpart[q];
        g_gram[b * Ee + e] = s;
    }
}

// zbar = w^T Vp + epb ; stats s1, s2 via Gram identity
__global__ void zbar_stats_kernel(const float* __restrict__ ep_b) {
    int i = blockIdx.x, b = blockIdx.y;
    __shared__ float ws[Nn * Dd];
    __shared__ float sm[32];
    int tid = threadIdx.x; // 512
    for (int t = tid; t < Nn * Dd; t += 512) {
        int j = t / Dd, d2 = t % Dd;
        ws[t] = g_w[((long)b * Ee + i * Nn + j) * Dd + d2];
    }
    __syncthreads();
    float acc[Nn];
#pragma unroll
    for (int j = 0; j < Nn; j++) acc[j] = 0.f;
    const float* Vb = g_Vp + (long)((b * Nn + i) * Dd) * Cch;
    for (int d2 = 0; d2 < Dd; d2++) {
        float v = Vb[(long)d2 * Cch + tid];
#pragma unroll
        for (int j = 0; j < Nn; j++) acc[j] += ws[j * Dd + d2] * v;
    }
    float eb = ep_b[tid];
    float E = block_reduce_sum(eb * eb, sm);
    for (int j = 0; j < Nn; j++) {
        int e = i * Nn + j;
        float z = acc[j] + eb;
        g_zbar[((long)b * Ee + e) * Cch + tid] = z;
        float S = block_reduce_sum(z, sm);
        float T = block_reduce_sum(eb * z, sm);
        if (tid == 0) {
            g_ps1[b * Ee + e] = 49.f * S;
            g_ps2[b * Ee + e] = g_gram[b * Ee + e] + 98.f * T - 49.f * E;
        }
    }
}

// ---------------- cosine adjacency mask --------------------------------------
__global__ void mask_kernel() {
    int b = blockIdx.x;
    __shared__ float sinv[Nn];
    __shared__ float adj[Ee];
    __shared__ float dis[Nn];
    int tid = threadIdx.x; // 256
    if (tid < Nn) {
        const float* f = g_fv + (long)(b * Nn + tid) * Cch;
        float s = 0.f;
        for (int c = 0; c < Cch; c++) s += f[c] * f[c];
        sinv[tid] = 1.f / fmaxf(sqrtf(s), 1e-12f);
    }
    __syncthreads();
    if (tid < Ee) {
        int i = tid / Nn, jn = tid % Nn;
        const float* fi = g_fv + (long)(b * Nn + i) * Cch;
        const float* fj = g_fv + (long)(b * Nn + jn) * Cch;
        float s = 0.f;
        for (int c = 0; c < Cch; c++) s += fi[c] * fj[c];
        adj[tid] = s * sinv[i] * sinv[jn];
    }
    __syncthreads();
    if (tid < Nn) {
        float s = 0.f;
        for (int jn = 0; jn < Nn; jn++) s += adj[tid * Nn + jn];
        dis[tid] = rsqrtf(s);
    }
    __syncthreads();
    if (tid < Ee) {
        int i = tid / Nn, jn = tid % Nn;
        g_mask[b * Ee + tid] = adj[tid] * dis[i] * dis[jn];
    }
}

// ---------------- edge BN + mask ---------------------------------------------
__global__ void edge_bn_mask_kernel() {
    int e = blockIdx.x;
    __shared__ float mrs[2];
    int tid = threadIdx.x; // 256
    if (tid == 0) {
        float s1 = 0.f, s2 = 0.f;
        for (int b = 0; b < Bb; b++) { s1 += g_ps1[b * Ee + e]; s2 += g_ps2[b * Ee + e]; }
        float cnt = (float)(Bb * Dd * Cch);
        float m = s1 / cnt;
        float v = s2 / cnt - m * m;
        mrs[0] = m;
        mrs[1] = rsqrtf(fmaxf(v, 0.f) + EPS_);
    }
    __syncthreads();
    float m = mrs[0], r = mrs[1];
    for (int b = 0; b < Bb; b++) {
        float mk = g_mask[b * Ee + e];
        long base = (long)(b * Ee + e) * Cch;
        g_fe[base + tid]       = (g_zbar[base + tid] - m) * r * mk;
        g_fe[base + tid + 256] = (g_zbar[base + tid + 256] - m) * r * mk;
    }
}

// ---------------- GNN layer pieces -------------------------------------------
__global__ void agg_bn_kernel() {
    int e = blockIdx.x;
    int i = e / Nn, jn = e % Nn;
    __shared__ float sm[64];
    __shared__ float mrs[2];
    int tid = threadIdx.x; // 256
    float s1 = 0.f, s2 = 0.f;
    for (int b = 0; b < Bb; b++) {
        long na = (long)(b * Nn + i) * 2048;
        long nb = (long)(b * Nn + jn) * 2048;
        long ne = (long)(b * Ee + e) * Cch;
#pragma unroll
        for (int cc = 0; cc < 2; cc++) {
            int c = tid + cc * 256;
            float v = g_xnode[na + c] + g_xnode[nb + 512 + c] + g_xw[ne + c];
            g_agg[ne + c] = v;
            s1 += v; s2 += v * v;
        }
    }
    s1 = block_reduce_sum(s1, sm);
    s2 = block_reduce_sum(s2, sm);
    if (tid == 0) {
        float cnt = (float)(Bb * Cch);
        float m = s1 / cnt;
        float v = s2 / cnt - m * m;
        mrs[0] = m;
        mrs[1] = rsqrtf(fmaxf(v, 0.f) + EPS_);
    }
    __syncthreads();
    float m = mrs[0], r = mrs[1];
    for (int b = 0; b < Bb; b++) {
        long ne = (long)(b * Ee + e) * Cch;
#pragma unroll
        for (int cc = 0; cc < 2; cc++) {
            int c = tid + cc * 256;
            g_fe[ne + c] += fmaxf((g_agg[ne + c] - m) * r, 0.f);
        }
    }
}

__global__ void softmax_msg_kernel() {
    int bi = blockIdx.x;
    int b = bi / Nn, i = bi % Nn;
    int c = threadIdx.x; // 512
    float v[Nn];
    float mx = -1e30f;
#pragma unroll
    for (int jn = 0; jn < Nn; jn++) {
        float ed = g_fe[((long)(b * Ee + i * Nn + jn)) * Cch + c];
        float s = 1.f / (1.f + expf(-ed));
        v[jn] = s;
        mx = fmaxf(mx, s);
    }
    float sum = 0.f;
#pragma unroll
    for (int jn = 0; jn < Nn; jn++) { v[jn] = expf(v[jn] - mx); sum += v[jn]; }
    float acc = 0.f;
#pragma unroll
    for (int jn = 0; jn < Nn; jn++)
        acc += v[jn] * g_xnode[(long)(b * Nn + jn) * 2048 + 1536 + c];
    g_msg[(long)(b * Nn + i) * Cch + c] = acc / (sum * (float)Nn);
}

__global__ void node_bn_kernel() {
    int n = blockIdx.x;
    __shared__ float sm[64];
    __shared__ float mrs[2];
    int tid = threadIdx.x; // 256
    float s1 = 0.f, s2 = 0.f;
    for (int b = 0; b < Bb; b++) {
        long base = (long)(b * Nn + n) * Cch;
        long xub = (long)(b * Nn + n) * 2048 + 1024;
#pragma unroll
        for (int cc = 0; cc < 2; cc++) {
            int c = tid + cc * 256;
            float t = g_xnode[xub + c] + g_msg[base + c];
            g_t[base + c] = t;
            s1 += t; s2 += t * t;
        }
    }
    s1 = block_reduce_sum(s1, sm);
    s2 = block_reduce_sum(s2, sm);
    if (tid == 0) {
        float cnt = (float)(Bb * Cch);
        float m = s1 / cnt;
        float v = s2 / cnt - m * m;
        mrs[0] = m;
        mrs[1] = rsqrtf(fmaxf(v, 0.f) + EPS_);
    }
    __syncthreads();
    float m = mrs[0], r = mrs[1];
    for (int b = 0; b < Bb; b++) {
        long base = (long)(b * Nn + n) * Cch;
#pragma unroll
        for (int cc = 0; cc < 2; cc++) {
            int c = tid + cc * 256;
            g_fv[base + c] = fmaxf(g_fv[base + c] + (g_t[base + c] - m) * r, 0.f);
        }
    }
}

// ---------------- classifier heads -------------------------------------------
__global__ void cls_kernel(const float* __restrict__ sc_w, float* __restrict__ out) {
    int bn = blockIdx.x; // b*12+n
    int n = bn % Nn;
    __shared__ float sm[32];
    int tid = threadIdx.x; // 128
    float sf = 0.f, ff = 0.f, ss = 0.f;
    for (int c = tid; c < Cch; c += 128) {
        float f = g_fv[(long)bn * Cch + c];
        float s = fmaxf(sc_w[n * Cch + c], 0.f);
        sf += f * s; ff += f * f; ss += s * s;
    }
    sf = block_reduce_sum(sf, sm);
    ff = block_reduce_sum(ff, sm);
    ss = block_reduce_sum(ss, sm);
    if (tid == 0)
        out[bn] = sf / (fmaxf(sqrtf(ff), 1e-12f) * fmaxf(sqrtf(ss), 1e-12f));
}

__global__ void edgefc_kernel(const float* __restrict__ w, const float* __restrict__ bias,
                              float* __restrict__ out) {
    int row = blockIdx.x; // b*144+e
    int tid = threadIdx.x; // 128
    int k = tid >> 5, lane = tid & 31;
    const float* f = g_fe + (long)row * Cch;
    float dot = 0.f;
    for (int c = lane; c < Cch; c += 32) dot += f[c] * w[c * 4 + k];
#pragma unroll
    for (int o = 16; o; o >>= 1) dot += __shfl_xor_sync(0xffffffffu, dot, o);
    if (lane == 0) out[96 + row * 4 + k] = dot + bias[k];
}

// ---------------- host driver -------------------------------------------------
extern "C" void kernel_launch(void* const* d_in, const int* in_sizes, int n_in,
                              void* d_out, int out_size) {
    const float* x      = (const float*)d_in[0];
    const float* Wc     = (const float*)d_in[1];
    const float* fam_wq = (const float*)d_in[3];
    const float* fam_bq = (const float*)d_in[4];
    const float* fam_wk = (const float*)d_in[5];
    const float* fam_wv = (const float*)d_in[7];
    const float* fam_bv = (const float*)d_in[8];
    const float* arm_wq = (const float*)d_in[9];
    const float* arm_bq = (const float*)d_in[10];
    const float* arm_wk = (const float*)d_in[11];
    const float* arm_bk = (const float*)d_in[12];
    const float* arm_wv = (const float*)d_in[13];
    const float* arm_bv = (const float*)d_in[14];
    const float* ep_w   = (const float*)d_in[15];
    const float* ep_b   = (const float*)d_in[16];
    const float* gw[10];
    for (int t = 0; t < 10; t++) gw[t] = (const float*)d_in[17 + t];
    const float* sc_w   = (const float*)d_in[27];
    const float* efc_w  = (const float*)d_in[28];
    const float* efc_b  = (const float*)d_in[29];
    float* out = (float*)d_out;

    float *p_h, *p_q1, *p_k1, *p_v1, *p_S1, *p_P, *p_f1, *p_QK2, *p_Vp, *p_Wvp, *p_bvp;
    float *p_wqk, *p_bqk, *p_S, *p_MV, *p_fv, *p_fe, *p_wnode, *p_xnode, *p_xw;
    cudaGetSymbolAddress((void**)&p_h, g_h);
    cudaGetSymbolAddress((void**)&p_q1, g_q1);
    cudaGetSymbolAddress((void**)&p_k1, g_k1);
    cudaGetSymbolAddress((void**)&p_v1, g_v1);
    cudaGetSymbolAddress((void**)&p_S1, g_S1);
    cudaGetSymbolAddress((void**)&p_P, g_P);
    cudaGetSymbolAddress((void**)&p_f1, g_feat1);
    cudaGetSymbolAddress((void**)&p_QK2, g_QK2);
    cudaGetSymbolAddress((void**)&p_Vp, g_Vp);
    cudaGetSymbolAddress((void**)&p_Wvp, g_Wvp);
    cudaGetSymbolAddress((void**)&p_bvp, g_bvp);
    cudaGetSymbolAddress((void**)&p_wqk, g_wqk);
    cudaGetSymbolAddress((void**)&p_bqk, g_bqk);
    cudaGetSymbolAddress((void**)&p_S, g_S);
    cudaGetSymbolAddress((void**)&p_MV, g_MV);
    cudaGetSymbolAddress((void**)&p_fv, g_fv);
    cudaGetSymbolAddress((void**)&p_fe, g_fe);
    cudaGetSymbolAddress((void**)&p_wnode, g_wnode);
    cudaGetSymbolAddress((void**)&p_xnode, g_xnode);
    cudaGetSymbolAddress((void**)&p_xw, g_xw);

    pack_qk_kernel<<<1024, 256>>>(arm_wq, arm_wk, arm_bq, arm_bk);
    zero_v1pad_kernel<<<32, 256>>>();

    // h = x @ Wc[n]  (bc removed by BN), z = 12 classes
    // FIX: with zdiv=1, zr==0 always, so batch strides MUST be in the s?1 slots.
    gemm_tc<<<dim3(4, 4, 12), 256>>>(x, Wc, nullptr, p_h, ND, Cch, Cch,
                                     Cch, Cch, Cch,
                                     0, 0, (long)Cch * Cch, 0, (long)ND * Cch, 0, 1, 0);
    bn1_stats_kernel<<<dim3(12, 4), 128>>>();
    bn1_apply_kernel<<<dim3(12, 8), 256>>>();

    // first attention projections (K/V shared across classes; bk softmax-invariant)
    gemm_tc<<<dim3(2, 4, 1), 256>>>(x, fam_wk, nullptr, p_k1, ND, Hh, Cch,
                                    Cch, Hh, Hh, 0, 0, 0, 0, 0, 0, 1, 0);
    gemm_tc<<<dim3(4, 4, 1), 256>>>(x, fam_wv, fam_bv, p_v1, ND, Cch, Cch,
                                    Cch, Cch, Cch, 0, 0, 0, 0, 0, 0, 1, 0);
    gemm_tc<<<dim3(2, 37, 1), 256>>>(p_h, fam_wq, fam_bq, p_q1, RQ, Hh, Cch,
                                     Cch, Hh, Hh, 0, 0, 0, 0, 0, 0, 1, 0);

    // attn1 via TC: S1 = Q1 K1^T per (n,b); softmax; feat1 = P @ V1 (b-major out)
    gemm_tc<<<dim3(1, 1, 96), 256>>>(p_q1, p_k1, nullptr, p_S1, Dd, Dd, Hh,
                                     Hh, Hh, Dd,
                                     (long)8 * Dd * Hh, (long)Dd * Hh,
                                     0, (long)Dd * Hh,
                                     (long)8 * Dd * Dd, (long)Dd * Dd, 8, 1);
    softmaxP_kernel<<<96, 256>>>();
    gemm_tc<<<dim3(4, 1, 96), 256>>>(p_P, p_v1, nullptr, p_f1, Dd, Cch, 64,
                                     64, Cch, Cch,
                                     (long)8 * Dd * 64, (long)Dd * 64,
                                     0, (long)Dd * Cch,
                                     (long)Dd * Cch, (long)Nn * Dd * Cch, 8, 0);

    // fold ep projection: Wvp = arm_wv @ ep_w, bvp = arm_bv @ ep_w
    gemm_tc<<<dim3(4, 4, 1), 256>>>(arm_wv, ep_w, nullptr, p_Wvp, Cch, Cch, Cch,
                                    Cch, Cch, Cch, 0, 0, 0, 0, 0, 0, 1, 0);
    bvp_kernel<<<1, 512>>>(arm_bv, ep_w);

    // Q2|K2 in one GEMM; Vp with folded ep
    gemm_tc<<<dim3(4, 37, 1), 256>>>(p_f1, p_wqk, p_bqk, p_QK2, RQ, Cch, Cch,
                                     Cch, Cch, Cch, 0, 0, 0, 0, 0, 0, 1, 0);
    gemm_tc<<<dim3(4, 37, 1), 256>>>(p_f1, p_Wvp, p_bvp, p_Vp, RQ, Cch, Cch,
                                     Cch, Cch, Cch, 0, 0, 0, 0, 0, 0, 1, 0);

    // attn2 scores: S[b] = Q2_b @ K2_b^T  (588x588x256, z=8)
    gemm_tc<<<dim3(5, 5, 8), 256>>>(p_QK2, p_QK2 + 256, nullptr, p_S, SQ, SQ, Hh,
                                    Cch, Cch, SQ,
                                    (long)SQ * Cch, 0, (long)SQ * Cch, 0,
                                    (long)SQ * SQ, 0, 1, 1);
    // MV[b,i] = Vp_bi @ Vp_bi^T (49x49x512, z=96) — fp32 for variance safety
    gemm64_kernel<<<dim3(1, 1, 96), 256>>>(p_Vp, p_Vp, nullptr, p_MV,
                                           Dd, Dd, Cch, Cch, Cch, Dd,
                                           (long)Dd * Cch, (long)Dd * Cch, (long)Dd * Dd, 1);
    pg_kernel<<<dim3(Ee, Bb), 256>>>();
    zbar_stats_kernel<<<dim3(Nn, Bb), 512>>>(ep_b);
    mask_kernel<<<Bb, 256>>>();
    edge_bn_mask_kernel<<<Ee, 256>>>();

    // two GNN layers
    for (int L = 0; L < 2; L++) {
        pack_node_kernel<<<4096, 256>>>(gw[L * 5 + 0], gw[L * 5 + 1],
                                        gw[L * 5 + 3], gw[L * 5 + 4]);
        // xnode = fv @ [wa|wb|wu|wv]
        gemm_tc<<<dim3(16, 1, 1), 256>>>(p_fv, p_wnode, nullptr, p_xnode,
                                         Bb * Nn, 2048, Cch, Cch, 2048, 2048,
                                         0, 0, 0, 0, 0, 0, 1, 0);
        // xw = fe @ we
        gemm_tc<<<dim3(4, 9, 1), 256>>>(p_fe, gw[L * 5 + 2], nullptr, p_xw,
                                        Bb * Ee, Cch, Cch, Cch, Cch, Cch,
                                        0, 0, 0, 0, 0, 0, 1, 0);
        agg_bn_kernel<<<Ee, 256>>>();
        softmax_msg_kernel<<<Bb * Nn, 512>>>();
        node_bn_kernel<<<Nn, 256>>>();
    }

    cls_kernel<<<Bb * Nn, 128>>>(sc_w, out);
    edgefc_kernel<<<Bb * Ee, 128>>>(efc_w, efc_b, out);
}

// round 5
// speedup vs baseline: 4.7010x; 1.6307x over previous
#include <cuda_runtime.h>
#include <math.h>
#include <stdint.h>

// Problem constants
#define Bb   8
#define Dd   49
#define Cch  512
#define Nn   12
#define Hh   256          // C/2
#define Ee   144          // N*N
#define ND   392          // B*D
#define RQ   4704         // N*B*D
#define SQ   588          // N*D (rows per batch in attn2)
#define SCALE_ 0.0625f    // (C/2)^-0.5
#define EPS_  1e-5f

// ---------------- static device scratch (zero-initialized at load) ----------
__device__ float g_h[RQ * Cch];          // h then f_u in place, rows (n*8+b)*49+d
__device__ float g_q1[RQ * Hh];
__device__ float g_k1[ND * Hh];
__device__ float g_v1[(ND + 16) * Cch];  // padded rows stay 0 (zero-init)
__device__ float g_S1[96 * Dd * Dd];     // attn1 scores per (n,b)
__device__ float g_P[96 * Dd * 64];      // attn1 probs, K-padded to 64
__device__ float g_feat1[RQ * Cch];      // rows (b*12+n)*49+d  (b-major)
__device__ float g_QK2[RQ * Cch];        // cols 0-255 = Q2, 256-511 = K2
__device__ float g_Vp[RQ * Cch];
__device__ float g_Wvp[Cch * Cch];
__device__ float g_bvp[Cch];
__device__ float g_wqk[Cch * Cch];       // packed arm_wq | arm_wk
__device__ float g_bqk[Cch];
__device__ float g_S[Bb * SQ * SQ];      // attn2 raw scores
__device__ float g_MV[Bb * Nn * Dd * Dd];// Vp Gram per (b,i)
__device__ float g_w[Bb * Ee * Dd];      // aggregated attention weights
__device__ float g_gram[Bb * Ee];        // <P^T P, MV>
__device__ float g_fv[Bb * Nn * Cch];
__device__ float g_zbar[Bb * Ee * Cch];
__device__ float g_ps1[Bb * Ee];
__device__ float g_ps2[Bb * Ee];
__device__ float g_bn1m[Nn * Cch];
__device__ float g_bn1r[Nn * Cch];
__device__ float g_mask[Bb * Ee];
__device__ float g_fe[Bb * Ee * Cch];
__device__ float g_wnodeA[Cch * 2048];   // packed wa|wb|wu|wv layer 1
__device__ float g_wnodeB[Cch * 2048];   // layer 2
__device__ float g_xnode[Bb * Nn * 2048];
__device__ float g_xw[Bb * Ee * Cch];
__device__ float g_msg[Bb * Nn * Cch];

// ---------------- helpers ----------------------------------------------------
__device__ __forceinline__ float block_reduce_sum(float v, float* sm) {
    int lane = threadIdx.x & 31, w = threadIdx.x >> 5;
#pragma unroll
    for (int o = 16; o; o >>= 1) v += __shfl_xor_sync(0xffffffffu, v, o);
    if (lane == 0) sm[w] = v;
    __syncthreads();
    int nw = (blockDim.x + 31) >> 5;
    float r = 0.f;
    if (threadIdx.x < 32) {
        r = (threadIdx.x < nw) ? sm[threadIdx.x] : 0.f;
#pragma unroll
        for (int o = 16; o; o >>= 1) r += __shfl_xor_sync(0xffffffffu, r, o);
        if (threadIdx.x == 0) sm[0] = r;
    }
    __syncthreads();
    r = sm[0];
    __syncthreads();
    return r;
}

__device__ __forceinline__ uint32_t f2tf32(float x) {
    uint32_t r;
    asm("cvt.rna.tf32.f32 %0, %1;" : "=r"(r) : "f"(x));
    return r;
}

__device__ __forceinline__ void mma_tf32(float* c, const uint32_t* a, const uint32_t* b) {
    asm volatile(
        "mma.sync.aligned.m16n8k8.row.col.f32.tf32.tf32.f32 "
        "{%0,%1,%2,%3}, {%4,%5,%6,%7}, {%8,%9}, {%0,%1,%2,%3};"
        : "+f"(c[0]), "+f"(c[1]), "+f"(c[2]), "+f"(c[3])
        : "r"(a[0]), "r"(a[1]), "r"(a[2]), "r"(a[3]), "r"(b[0]), "r"(b[1]));
}

__device__ __forceinline__ float4 f4add(float4 a, float4 b) {
    return make_float4(a.x + b.x, a.y + b.y, a.z + b.z, a.w + b.w);
}

// ---------------- gemm_tc: TF32 tensor-core GEMM, 128x128x16 -----------------
__global__ __launch_bounds__(256) void gemm_tc(
    const float* __restrict__ A, const float* __restrict__ Bm,
    const float* __restrict__ bias, float* __restrict__ Cm,
    int M, int Np, int K, int lda, int ldb, int ldc,
    long sA1, long sA2, long sB1, long sB2, long sC1, long sC2,
    int zdiv, int transB)
{
    int z = blockIdx.z;
    int zq = z / zdiv, zr = z % zdiv;
    const float* Az = A + zq * sA1 + (long)zr * sA2;
    const float* Bz = Bm + zq * sB1 + (long)zr * sB2;
    float* Cz = Cm + zq * sC1 + (long)zr * sC2;

    __shared__ float As[2][16][132];
    __shared__ float Bs[2][16][132];
    int tid = threadIdx.x;
    int row0 = blockIdx.y * 128, col0 = blockIdx.x * 128;

    int arow = tid >> 1, ak0 = (tid & 1) * 8;
    int bkk = tid >> 4, bn0 = (tid & 15) * 8;

    int warp = tid >> 5, lane = tid & 31;
    int wm = (warp >> 2) * 64, wn = (warp & 3) * 32;
    int gid = lane >> 2, tig = lane & 3;

    float c[4][4][4];
#pragma unroll
    for (int mi = 0; mi < 4; mi++)
#pragma unroll
        for (int ni = 0; ni < 4; ni++)
#pragma unroll
            for (int q = 0; q < 4; q++) c[mi][ni][q] = 0.f;

    const float4 z4 = {0.f, 0.f, 0.f, 0.f};
    float4 a0g, a1g, b0g, b1g;

#define LOAD_TILE(k0)                                                          \
    {                                                                          \
        int gr = row0 + arow;                                                  \
        if (gr < M) {                                                          \
            const float* p = Az + (long)gr * lda + (k0) + ak0;                 \
            a0g = *(const float4*)p; a1g = *(const float4*)(p + 4);            \
        } else { a0g = z4; a1g = z4; }                                         \
        if (!transB) {                                                         \
            int gc = col0 + bn0;                                               \
            if (gc < Np) {                                                     \
                const float* p = Bz + (long)((k0) + bkk) * ldb + gc;           \
                b0g = *(const float4*)p; b1g = *(const float4*)(p + 4);        \
            } else { b0g = z4; b1g = z4; }                                     \
        } else {                                                               \
            int gn = col0 + arow;                                              \
            if (gn < Np) {                                                     \
                const float* p = Bz + (long)gn * ldb + (k0) + ak0;             \
                b0g = *(const float4*)p; b1g = *(const float4*)(p + 4);        \
            } else { b0g = z4; b1g = z4; }                                     \
        }                                                                      \
    }

#define STORE_TILE(buf)                                                        \
    {                                                                          \
        As[buf][ak0+0][arow]=a0g.x; As[buf][ak0+1][arow]=a0g.y;                \
        As[buf][ak0+2][arow]=a0g.z; As[buf][ak0+3][arow]=a0g.w;                \
        As[buf][ak0+4][arow]=a1g.x; As[buf][ak0+5][arow]=a1g.y;                \
        As[buf][ak0+6][arow]=a1g.z; As[buf][ak0+7][arow]=a1g.w;                \
        if (!transB) {                                                         \
            *(float4*)&Bs[buf][bkk][bn0] = b0g;                                \
            *(float4*)&Bs[buf][bkk][bn0+4] = b1g;                              \
        } else {                                                               \
            Bs[buf][ak0+0][arow]=b0g.x; Bs[buf][ak0+1][arow]=b0g.y;            \
            Bs[buf][ak0+2][arow]=b0g.z; Bs[buf][ak0+3][arow]=b0g.w;            \
            Bs[buf][ak0+4][arow]=b1g.x; Bs[buf][ak0+5][arow]=b1g.y;            \
            Bs[buf][ak0+6][arow]=b1g.z; Bs[buf][ak0+7][arow]=b1g.w;            \
        }                                                                      \
    }

    LOAD_TILE(0);
    STORE_TILE(0);
    __syncthreads();

    int nt = K >> 4;
    for (int t = 0; t < nt; t++) {
        int buf = t & 1;
        if (t + 1 < nt) LOAD_TILE((t + 1) << 4);
#pragma unroll
        for (int k8 = 0; k8 < 16; k8 += 8) {
            uint32_t af[4][4], bf[4][2];
#pragma unroll
            for (int mi = 0; mi < 4; mi++) {
                int mb = wm + mi * 16;
                af[mi][0] = f2tf32(As[buf][k8 + tig][mb + gid]);
                af[mi][1] = f2tf32(As[buf][k8 + tig][mb + gid + 8]);
                af[mi][2] = f2tf32(As[buf][k8 + tig + 4][mb + gid]);
                af[mi][3] = f2tf32(As[buf][k8 + tig + 4][mb + gid + 8]);
            }
#pragma unroll
            for (int ni = 0; ni < 4; ni++) {
                int nb = wn + ni * 8 + gid;
                bf[ni][0] = f2tf32(Bs[buf][k8 + tig][nb]);
                bf[ni][1] = f2tf32(Bs[buf][k8 + tig + 4][nb]);
            }
#pragma unroll
            for (int mi = 0; mi < 4; mi++)
#pragma unroll
                for (int ni = 0; ni < 4; ni++)
                    mma_tf32(c[mi][ni], af[mi], bf[ni]);
        }
        if (t + 1 < nt) {
            STORE_TILE(buf ^ 1);
            __syncthreads();
        }
    }

#pragma unroll
    for (int mi = 0; mi < 4; mi++) {
        int r0 = row0 + wm + mi * 16 + gid;
        int r1 = r0 + 8;
#pragma unroll
        for (int ni = 0; ni < 4; ni++) {
            int cb = col0 + wn + ni * 8 + 2 * tig;
            float bv0 = 0.f, bv1 = 0.f;
            if (bias) {
                if (cb < Np) bv0 = bias[cb];
                if (cb + 1 < Np) bv1 = bias[cb + 1];
            }
            if (r0 < M) {
                if (cb < Np)     Cz[(long)r0 * ldc + cb]     = c[mi][ni][0] + bv0;
                if (cb + 1 < Np) Cz[(long)r0 * ldc + cb + 1] = c[mi][ni][1] + bv1;
            }
            if (r1 < M) {
                if (cb < Np)     Cz[(long)r1 * ldc + cb]     = c[mi][ni][2] + bv0;
                if (cb + 1 < Np) Cz[(long)r1 * ldc + cb + 1] = c[mi][ni][3] + bv1;
            }
        }
    }
#undef LOAD_TILE
#undef STORE_TILE
}

// ---------------- gemm64 (fp32, kept only for the MV Gram) -------------------
__global__ __launch_bounds__(256) void gemm64_kernel(
    const float* __restrict__ A, const float* __restrict__ Bm,
    const float* __restrict__ bias, float* __restrict__ Cm,
    int M, int Np, int K, int lda, int ldb, int ldc,
    long sA, long sB, long sC, int transB)
{
    const float* Az = A + (long)blockIdx.z * sA;
    const float* Bz = Bm + (long)blockIdx.z * sB;
    float* Cz = Cm + (long)blockIdx.z * sC;
    __shared__ float As[16][64];
    __shared__ float Bs[16][64];
    int tid = threadIdx.x;
    int tx = tid & 15, ty = tid >> 4;
    int row0 = blockIdx.y * 64, col0 = blockIdx.x * 64;
    int lr = tid >> 2, lk = (tid & 3) * 4;
    int bkk = tid >> 4, bn = (tid & 15) * 4;
    const float4 z4 = {0.f, 0.f, 0.f, 0.f};
    float acc[4][4];
#pragma unroll
    for (int i = 0; i < 4; i++)
#pragma unroll
        for (int j = 0; j < 4; j++) acc[i][j] = 0.f;

    for (int k0 = 0; k0 < K; k0 += 16) {
        float4 av = z4, bv = z4;
        if (row0 + lr < M) av = *(const float4*)(Az + (long)(row0 + lr) * lda + k0 + lk);
        if (!transB) {
            if (col0 + bn < Np) bv = *(const float4*)(Bz + (long)(k0 + bkk) * ldb + col0 + bn);
        } else {
            if (col0 + lr < Np) bv = *(const float4*)(Bz + (long)(col0 + lr) * ldb + k0 + lk);
        }
        __syncthreads();
        As[lk+0][lr]=av.x; As[lk+1][lr]=av.y; As[lk+2][lr]=av.z; As[lk+3][lr]=av.w;
        if (!transB) {
            *(float4*)&Bs[bkk][bn] = bv;
        } else {
            Bs[lk+0][lr]=bv.x; Bs[lk+1][lr]=bv.y; Bs[lk+2][lr]=bv.z; Bs[lk+3][lr]=bv.w;
        }
        __syncthreads();
#pragma unroll
        for (int kk = 0; kk < 16; kk++) {
            float4 a4 = *(const float4*)&As[kk][ty * 4];
            float4 b4 = *(const float4*)&Bs[kk][tx * 4];
            float a[4] = {a4.x, a4.y, a4.z, a4.w};
            float b[4] = {b4.x, b4.y, b4.z, b4.w};
#pragma unroll
            for (int i = 0; i < 4; i++)
#pragma unroll
                for (int j = 0; j < 4; j++) acc[i][j] += a[i] * b[j];
        }
    }
#pragma unroll
    for (int i = 0; i < 4; i++) {
        int gr = row0 + ty * 4 + i;
        if (gr >= M) continue;
#pragma unroll
        for (int j = 0; j < 4; j++) {
            int gc = col0 + tx * 4 + j;
            if (gc < Np)
                Cz[(long)gr * ldc + gc] = acc[i][j] + (bias ? bias[gc] : 0.f);
        }
    }
}

// ---------------- weight packers ---------------------------------------------
__global__ void pack_qk_kernel(const float* __restrict__ wq, const float* __restrict__ wk,
                               const float* __restrict__ bq, const float* __restrict__ bk) {
    int idx = blockIdx.x * 256 + threadIdx.x;
    int k = idx >> 9, c = idx & 511;
    g_wqk[idx] = (c < 256) ? wq[k * 256 + c] : wk[k * 256 + c - 256];
    if (idx < 512) g_bqk[idx] = (idx < 256) ? bq[idx] : bk[idx - 256];
}

__global__ void pack_node_kernel(const float* __restrict__ wa, const float* __restrict__ wb,
                                 const float* __restrict__ wu, const float* __restrict__ wv,
                                 float* __restrict__ dst) {
    int idx = blockIdx.x * 256 + threadIdx.x;
    int k = idx >> 11, c = idx & 2047;
    const float* src = (c < 512) ? wa : (c < 1024) ? wb : (c < 1536) ? wu : wv;
    dst[idx] = src[k * 512 + (c & 511)];
}

// ---------------- BN1 ---------------------------------------------------------
// grid (12, 8), block 256: 64 channels x 4 row-groups
__global__ void bn1_stats_kernel() {
    int n = blockIdx.x;
    int cl = threadIdx.x & 63;
    int q = threadIdx.x >> 6;
    int c = blockIdx.y * 64 + cl;
    float s1 = 0.f, s2 = 0.f;
    const float* base = g_h + (long)n * ND * Cch + c;
    for (int r = q; r < ND; r += 4) {
        float v = base[(long)r * Cch];
        s1 += v; s2 += v * v;
    }
    __shared__ float sm1[4][64], sm2[4][64];
    sm1[q][cl] = s1; sm2[q][cl] = s2;
    __syncthreads();
    if (q == 0) {
        s1 = sm1[0][cl] + sm1[1][cl] + sm1[2][cl] + sm1[3][cl];
        s2 = sm2[0][cl] + sm2[1][cl] + sm2[2][cl] + sm2[3][cl];
        float m = s1 / (float)ND;
        float var = s2 / (float)ND - m * m;
        g_bn1m[n * Cch + c] = m;
        g_bn1r[n * Cch + c] = rsqrtf(fmaxf(var, 0.f) + EPS_);
    }
}

// grid (12, 8) = (n, b), block 128, float4
__global__ void bn1_apply_kernel() {
    int n = blockIdx.x, b = blockIdx.y;
    int c4 = threadIdx.x; // 0..127
    float4 m = ((const float4*)(g_bn1m + n * Cch))[c4];
    float4 r = ((const float4*)(g_bn1r + n * Cch))[c4];
    float4* hb = (float4*)(g_h + ((long)(n * Bb + b) * Dd) * Cch) + c4;
    float4 acc = {0.f, 0.f, 0.f, 0.f};
    for (int d = 0; d < Dd; d++) {
        float4 h = hb[(long)d * 128];
        float4 u;
        u.x = fmaxf((h.x - m.x) * r.x, 0.f);
        u.y = fmaxf((h.y - m.y) * r.y, 0.f);
        u.z = fmaxf((h.z - m.z) * r.z, 0.f);
        u.w = fmaxf((h.w - m.w) * r.w, 0.f);
        hb[(long)d * 128] = u;
        acc = f4add(acc, u);
    }
    float inv = 1.f / (float)Dd;
    acc.x *= inv; acc.y *= inv; acc.z *= inv; acc.w *= inv;
    ((float4*)(g_fv + (long)(b * Nn + n) * Cch))[c4] = acc;
}

// ---------------- attn1 softmax (S1 -> P, zero-padded K to 64) ----------------
__global__ void softmaxP_kernel() {
    int z = blockIdx.x;
    int tid = threadIdx.x, w = tid >> 5, lane = tid & 31;
    const float* Sb = g_S1 + (long)z * Dd * Dd;
    float* Pb = g_P + (long)z * Dd * 64;
    for (int r = w; r < Dd; r += 8) {
        float v0 = (lane < Dd) ? Sb[r * Dd + lane] * SCALE_ : -1e30f;
        float v1 = (lane + 32 < Dd) ? Sb[r * Dd + lane + 32] * SCALE_ : -1e30f;
        float mx = fmaxf(v0, v1);
#pragma unroll
        for (int o = 16; o; o >>= 1) mx = fmaxf(mx, __shfl_xor_sync(0xffffffffu, mx, o));
        float e0 = (lane < Dd) ? expf(v0 - mx) : 0.f;
        float e1 = (lane + 32 < Dd) ? expf(v1 - mx) : 0.f;
        float s = e0 + e1;
#pragma unroll
        for (int o = 16; o; o >>= 1) s += __shfl_xor_sync(0xffffffffu, s, o);
        float inv = 1.f / s;
        if (lane < Dd) Pb[r * 64 + lane] = e0 * inv;
        Pb[r * 64 + lane + 32] = (lane + 32 < Dd) ? e1 * inv : 0.f;
    }
}

// bvp = arm_bv @ ep_w
__global__ void bvp_kernel(const float* __restrict__ bv, const float* __restrict__ epw) {
    int c = threadIdx.x;
    float s = 0.f;
    for (int k = 0; k < Cch; k++) s += bv[k] * epw[k * Cch + c];
    g_bvp[c] = s;
}

// ---------------- attn2: per-(b,e) softmax + agg weights + Gram term ----------
__global__ void pg_kernel() {
    int e = blockIdx.x, b = blockIdx.y;
    int i = e / Nn, j = e % Nn;
    __shared__ float P[49][50];
    __shared__ float MVs[Dd * Dd];
    __shared__ float gpart[8];
    int tid = threadIdx.x, w = tid >> 5, lane = tid & 31;
    const float* MVg = g_MV + (long)(b * Nn + i) * (Dd * Dd);
    for (int t = tid; t < Dd * Dd; t += 256) MVs[t] = MVg[t];
    const float* Sb = g_S + (long)b * SQ * SQ + (long)(j * Dd) * SQ + i * Dd;
    for (int r = w; r < Dd; r += 8) {
        float v0 = (lane < Dd) ? Sb[r * SQ + lane] * SCALE_ : -1e30f;
        float v1 = (lane + 32 < Dd) ? Sb[r * SQ + lane + 32] * SCALE_ : -1e30f;
        float mx = fmaxf(v0, v1);
#pragma unroll
        for (int o = 16; o; o >>= 1) mx = fmaxf(mx, __shfl_xor_sync(0xffffffffu, mx, o));
        float e0 = (lane < Dd) ? expf(v0 - mx) : 0.f;
        float e1 = (lane + 32 < Dd) ? expf(v1 - mx) : 0.f;
        float s = e0 + e1;
#pragma unroll
        for (int o = 16; o; o >>= 1) s += __shfl_xor_sync(0xffffffffu, s, o);
        float inv = 1.f / s;
        if (lane < Dd) P[r][lane] = e0 * inv;
        if (lane + 32 < Dd) P[r][lane + 32] = e1 * inv;
    }
    __syncthreads();
    if (tid < Dd) {
        float s = 0.f;
        for (int r = 0; r < Dd; r++) s += P[r][tid];
        g_w[((long)b * Ee + e) * Dd + tid] = s * (1.f / (float)Dd);
    }
    float acc = 0.f;
    for (int r = w; r < Dd; r += 8) {
        float t0 = 0.f, t1 = 0.f;
        for (int bbk = 0; bbk < Dd; bbk++) {
            float p = P[r][bbk];
            t0 += MVs[lane * Dd + bbk] * p;
            if (lane + 32 < Dd) t1 += MVs[(lane + 32) * Dd + bbk] * p;
        }
        acc += P[r][lane] * t0;
        if (lane + 32 < Dd) acc += P[r][lane + 32] * t1;
    }
#pragma unroll
    for (int o = 16; o; o >>= 1) acc += __shfl_xor_sync(0xffffffffu, acc, o);
    if (lane == 0) gpart[w] = acc;
    __syncthreads();
    if (tid == 0) {
        float s = 0.f;
        for (int q = 0; q < 8; q++) s += gpart[q];
        g_gram[b * Ee + e] = s;
    }
}

// zbar = w^T Vp + epb ; stats via Gram identity. grid (12,8)=(i,b), block 512.
__global__ void zbar_stats_kernel(const float* __restrict__ ep_b) {
    int i = blockIdx.x, b = blockIdx.y;
    __shared__ float ws[Nn * Dd];
    __shared__ float red[16][26];
    int tid = threadIdx.x, lane = tid & 31, w = tid >> 5;
    for (int t = tid; t < Nn * Dd; t += 512) {
        int j = t / Dd, d2 = t % Dd;
        ws[t] = g_w[((long)b * Ee + i * Nn + j) * Dd + d2];
    }
    __syncthreads();
    float acc[Nn];
#pragma unroll
    for (int j = 0; j < Nn; j++) acc[j] = 0.f;
    const float* Vb = g_Vp + (long)((b * Nn + i) * Dd) * Cch;
    for (int d2 = 0; d2 < Dd; d2++) {
        float v = Vb[(long)d2 * Cch + tid];
#pragma unroll
        for (int j = 0; j < Nn; j++) acc[j] += ws[j * Dd + d2] * v;
    }
    float eb = ep_b[tid];
    float loc[25];
#pragma unroll
    for (int j = 0; j < Nn; j++) {
        float z = acc[j] + eb;
        g_zbar[((long)b * Ee + i * Nn + j) * Cch + tid] = z;
        loc[j] = z;
        loc[Nn + j] = eb * z;
    }
    loc[24] = eb * eb;
#pragma unroll
    for (int k = 0; k < 25; k++) {
        float v = loc[k];
#pragma unroll
        for (int o = 16; o; o >>= 1) v += __shfl_xor_sync(0xffffffffu, v, o);
        if (lane == 0) red[w][k] = v;
    }
    __syncthreads();
    if (tid < Nn) {
        float S = 0.f, T = 0.f, E = 0.f;
#pragma unroll
        for (int q = 0; q < 16; q++) {
            S += red[q][tid]; T += red[q][Nn + tid]; E += red[q][24];
        }
        int e = i * Nn + tid;
        g_ps1[b * Ee + e] = 49.f * S;
        g_ps2[b * Ee + e] = g_gram[b * Ee + e] + 98.f * T - 49.f * E;
    }
}

// ---------------- cosine adjacency mask (warp-cooperative) --------------------
__global__ void mask_kernel() {
    int b = blockIdx.x;
    __shared__ float sinv[Nn];
    __shared__ float adj[Ee];
    __shared__ float dis[Nn];
    int tid = threadIdx.x, w = tid >> 5, lane = tid & 31; // 8 warps
    for (int n = w; n < Nn; n += 8) {
        const float4* f = (const float4*)(g_fv + (long)(b * Nn + n) * Cch);
        float s = 0.f;
        for (int t = lane; t < 128; t += 32) {
            float4 x = f[t];
            s += x.x * x.x + x.y * x.y + x.z * x.z + x.w * x.w;
        }
#pragma unroll
        for (int o = 16; o; o >>= 1) s += __shfl_xor_sync(0xffffffffu, s, o);
        if (lane == 0) sinv[n] = 1.f / fmaxf(sqrtf(s), 1e-12f);
    }
    __syncthreads();
    for (int e = w; e < Ee; e += 8) {
        int i = e / Nn, jn = e % Nn;
        const float4* fi = (const float4*)(g_fv + (long)(b * Nn + i) * Cch);
        const float4* fj = (const float4*)(g_fv + (long)(b * Nn + jn) * Cch);
        float s = 0.f;
        for (int t = lane; t < 128; t += 32) {
            float4 a = fi[t], c = fj[t];
            s += a.x * c.x + a.y * c.y + a.z * c.z + a.w * c.w;
        }
#pragma unroll
        for (int o = 16; o; o >>= 1) s += __shfl_xor_sync(0xffffffffu, s, o);
        if (lane == 0) adj[e] = s * sinv[i] * sinv[jn];
    }
    __syncthreads();
    if (tid < Nn) {
        float s = 0.f;
        for (int jn = 0; jn < Nn; jn++) s += adj[tid * Nn + jn];
        dis[tid] = rsqrtf(s);
    }
    __syncthreads();
    if (tid < Ee) {
        int i = tid / Nn, jn = tid % Nn;
        g_mask[b * Ee + tid] = adj[tid] * dis[i] * dis[jn];
    }
}

// ---------------- edge BN + mask (float4) ------------------------------------
__global__ void edge_bn_mask_kernel() {
    int e = blockIdx.x;
    __shared__ float mrs[2];
    int tid = threadIdx.x; // 128
    if (tid == 0) {
        float s1 = 0.f, s2 = 0.f;
        for (int b = 0; b < Bb; b++) { s1 += g_ps1[b * Ee + e]; s2 += g_ps2[b * Ee + e]; }
        float cnt = (float)(Bb * Dd * Cch);
        float m = s1 / cnt;
        float v = s2 / cnt - m * m;
        mrs[0] = m;
        mrs[1] = rsqrtf(fmaxf(v, 0.f) + EPS_);
    }
    __syncthreads();
    float m = mrs[0], r = mrs[1];
    for (int b = 0; b < Bb; b++) {
        float mk = g_mask[b * Ee + e] * r;
        const float4* zb = (const float4*)(g_zbar + (long)(b * Ee + e) * Cch);
        float4* fe = (float4*)(g_fe + (long)(b * Ee + e) * Cch);
        float4 z = zb[tid];
        fe[tid] = make_float4((z.x - m) * mk, (z.y - m) * mk, (z.z - m) * mk, (z.w - m) * mk);
    }
}

// ---------------- GNN layer pieces -------------------------------------------
// grid 144, block 128; per-batch agg kept in registers
__global__ void agg_bn_kernel() {
    int e = blockIdx.x;
    int i = e / Nn, jn = e % Nn;
    __shared__ float sm[32];
    int tid = threadIdx.x;
    float4 agg[Bb];
    float s1 = 0.f, s2 = 0.f;
#pragma unroll
    for (int b = 0; b < Bb; b++) {
        float4 va = ((const float4*)(g_xnode + (long)(b * Nn + i) * 2048))[tid];
        float4 vb = ((const float4*)(g_xnode + (long)(b * Nn + jn) * 2048 + 512))[tid];
        float4 vw = ((const float4*)(g_xw + (long)(b * Ee + e) * Cch))[tid];
        float4 v = f4add(f4add(va, vb), vw);
        agg[b] = v;
        s1 += v.x + v.y + v.z + v.w;
        s2 += v.x * v.x + v.y * v.y + v.z * v.z + v.w * v.w;
    }
    s1 = block_reduce_sum(s1, sm);
    s2 = block_reduce_sum(s2, sm);
    float cnt = (float)(Bb * Cch);
    float m = s1 / cnt;
    float r = rsqrtf(fmaxf(s2 / cnt - m * m, 0.f) + EPS_);
#pragma unroll
    for (int b = 0; b < Bb; b++) {
        float4* fe = (float4*)(g_fe + (long)(b * Ee + e) * Cch);
        float4 f = fe[tid], v = agg[b];
        f.x += fmaxf((v.x - m) * r, 0.f);
        f.y += fmaxf((v.y - m) * r, 0.f);
        f.z += fmaxf((v.z - m) * r, 0.f);
        f.w += fmaxf((v.w - m) * r, 0.f);
        fe[tid] = f;
    }
}

// grid 96 = (b*12+i), block 128, float4
__global__ void softmax_msg_kernel() {
    int bi = blockIdx.x;
    int b = bi / Nn, i = bi % Nn;
    int tid = threadIdx.x;
    float4 v[Nn];
    float4 mx = {-1e30f, -1e30f, -1e30f, -1e30f};
#pragma unroll
    for (int jn = 0; jn < Nn; jn++) {
        float4 ed = ((const float4*)(g_fe + (long)(b * Ee + i * Nn + jn) * Cch))[tid];
        float4 s;
        s.x = 1.f / (1.f + expf(-ed.x));
        s.y = 1.f / (1.f + expf(-ed.y));
        s.z = 1.f / (1.f + expf(-ed.z));
        s.w = 1.f / (1.f + expf(-ed.w));
        v[jn] = s;
        mx.x = fmaxf(mx.x, s.x); mx.y = fmaxf(mx.y, s.y);
        mx.z = fmaxf(mx.z, s.z); mx.w = fmaxf(mx.w, s.w);
    }
    float4 sum = {0.f, 0.f, 0.f, 0.f};
#pragma unroll
    for (int jn = 0; jn < Nn; jn++) {
        v[jn].x = expf(v[jn].x - mx.x); v[jn].y = expf(v[jn].y - mx.y);
        v[jn].z = expf(v[jn].z - mx.z); v[jn].w = expf(v[jn].w - mx.w);
        sum = f4add(sum, v[jn]);
    }
    float4 acc = {0.f, 0.f, 0.f, 0.f};
#pragma unroll
    for (int jn = 0; jn < Nn; jn++) {
        float4 u = ((const float4*)(g_xnode + (long)(b * Nn + jn) * 2048 + 1536))[tid];
        acc.x += v[jn].x * u.x; acc.y += v[jn].y * u.y;
        acc.z += v[jn].z * u.z; acc.w += v[jn].w * u.w;
    }
    float4 o;
    o.x = acc.x / (sum.x * (float)Nn); o.y = acc.y / (sum.y * (float)Nn);
    o.z = acc.z / (sum.z * (float)Nn); o.w = acc.w / (sum.w * (float)Nn);
    ((float4*)(g_msg + (long)(b * Nn + i) * Cch))[tid] = o;
}

// grid 12, block 128
__global__ void node_bn_kernel() {
    int n = blockIdx.x;
    __shared__ float sm[32];
    int tid = threadIdx.x;
    float4 t[Bb];
    float s1 = 0.f, s2 = 0.f;
#pragma unroll
    for (int b = 0; b < Bb; b++) {
        float4 xu = ((const float4*)(g_xnode + (long)(b * Nn + n) * 2048 + 1024))[tid];
        float4 ms = ((const float4*)(g_msg + (long)(b * Nn + n) * Cch))[tid];
        float4 v = f4add(xu, ms);
        t[b] = v;
        s1 += v.x + v.y + v.z + v.w;
        s2 += v.x * v.x + v.y * v.y + v.z * v.z + v.w * v.w;
    }
    s1 = block_reduce_sum(s1, sm);
    s2 = block_reduce_sum(s2, sm);
    float cnt = (float)(Bb * Cch);
    float m = s1 / cnt;
    float r = rsqrtf(fmaxf(s2 / cnt - m * m, 0.f) + EPS_);
#pragma unroll
    for (int b = 0; b < Bb; b++) {
        float4* fv = (float4*)(g_fv + (long)(b * Nn + n) * Cch);
        float4 f = fv[tid], v = t[b];
        f.x = fmaxf(f.x + (v.x - m) * r, 0.f);
        f.y = fmaxf(f.y + (v.y - m) * r, 0.f);
        f.z = fmaxf(f.z + (v.z - m) * r, 0.f);
        f.w = fmaxf(f.w + (v.w - m) * r, 0.f);
        fv[tid] = f;
    }
}

// ---------------- classifier heads -------------------------------------------
__global__ void cls_kernel(const float* __restrict__ sc_w, float* __restrict__ out) {
    int bn = blockIdx.x;
    int n = bn % Nn;
    __shared__ float sm[32];
    int tid = threadIdx.x; // 128
    float sf = 0.f, ff = 0.f, ss = 0.f;
    for (int c = tid; c < Cch; c += 128) {
        float f = g_fv[(long)bn * Cch + c];
        float s = fmaxf(sc_w[n * Cch + c], 0.f);
        sf += f * s; ff += f * f; ss += s * s;
    }
    sf = block_reduce_sum(sf, sm);
    ff = block_reduce_sum(ff, sm);
    ss = block_reduce_sum(ss, sm);
    if (tid == 0)
        out[bn] = sf / (fmaxf(sqrtf(ff), 1e-12f) * fmaxf(sqrtf(ss), 1e-12f));
}

__global__ void edgefc_kernel(const float* __restrict__ w, const float* __restrict__ bias,
                              float* __restrict__ out) {
    int row = blockIdx.x;
    int tid = threadIdx.x;
    int k = tid >> 5, lane = tid & 31;
    const float* f = g_fe + (long)row * Cch;
    float dot = 0.f;
    for (int c = lane; c < Cch; c += 32) dot += f[c] * w[c * 4 + k];
#pragma unroll
    for (int o = 16; o; o >>= 1) dot += __shfl_xor_sync(0xffffffffu, dot, o);
    if (lane == 0) out[96 + row * 4 + k] = dot + bias[k];
}

// ---------------- host driver -------------------------------------------------
extern "C" void kernel_launch(void* const* d_in, const int* in_sizes, int n_in,
                              void* d_out, int out_size) {
    const float* x      = (const float*)d_in[0];
    const float* Wc     = (const float*)d_in[1];
    const float* fam_wq = (const float*)d_in[3];
    const float* fam_bq = (const float*)d_in[4];
    const float* fam_wk = (const float*)d_in[5];
    const float* fam_wv = (const float*)d_in[7];
    const float* fam_bv = (const float*)d_in[8];
    const float* arm_wq = (const float*)d_in[9];
    const float* arm_bq = (const float*)d_in[10];
    const float* arm_wk = (const float*)d_in[11];
    const float* arm_bk = (const float*)d_in[12];
    const float* arm_wv = (const float*)d_in[13];
    const float* arm_bv = (const float*)d_in[14];
    const float* ep_w   = (const float*)d_in[15];
    const float* ep_b   = (const float*)d_in[16];
    const float* gw[10];
    for (int t = 0; t < 10; t++) gw[t] = (const float*)d_in[17 + t];
    const float* sc_w   = (const float*)d_in[27];
    const float* efc_w  = (const float*)d_in[28];
    const float* efc_b  = (const float*)d_in[29];
    float* out = (float*)d_out;

    float *p_h, *p_q1, *p_k1, *p_v1, *p_S1, *p_P, *p_f1, *p_QK2, *p_Vp, *p_Wvp, *p_bvp;
    float *p_wqk, *p_bqk, *p_S, *p_MV, *p_fv, *p_fe, *p_wnA, *p_wnB, *p_xnode, *p_xw;
    cudaGetSymbolAddress((void**)&p_h, g_h);
    cudaGetSymbolAddress((void**)&p_q1, g_q1);
    cudaGetSymbolAddress((void**)&p_k1, g_k1);
    cudaGetSymbolAddress((void**)&p_v1, g_v1);
    cudaGetSymbolAddress((void**)&p_S1, g_S1);
    cudaGetSymbolAddress((void**)&p_P, g_P);
    cudaGetSymbolAddress((void**)&p_f1, g_feat1);
    cudaGetSymbolAddress((void**)&p_QK2, g_QK2);
    cudaGetSymbolAddress((void**)&p_Vp, g_Vp);
    cudaGetSymbolAddress((void**)&p_Wvp, g_Wvp);
    cudaGetSymbolAddress((void**)&p_bvp, g_bvp);
    cudaGetSymbolAddress((void**)&p_wqk, g_wqk);
    cudaGetSymbolAddress((void**)&p_bqk, g_bqk);
    cudaGetSymbolAddress((void**)&p_S, g_S);
    cudaGetSymbolAddress((void**)&p_MV, g_MV);
    cudaGetSymbolAddress((void**)&p_fv, g_fv);
    cudaGetSymbolAddress((void**)&p_fe, g_fe);
    cudaGetSymbolAddress((void**)&p_wnA, g_wnodeA);
    cudaGetSymbolAddress((void**)&p_wnB, g_wnodeB);
    cudaGetSymbolAddress((void**)&p_xnode, g_xnode);
    cudaGetSymbolAddress((void**)&p_xw, g_xw);

    // one-time stream/event setup (host resources only; no device allocations)
    static cudaStream_t s1 = nullptr, s2 = nullptr;
    static cudaEvent_t evRoot, evPackQK, evK1, evV1, evWvpB, evFv, evFeat1,
                       evMV, evMask, evXn1, evNB1, evXn2;
    if (!s1) {
        cudaStreamCreateWithFlags(&s1, cudaStreamNonBlocking);
        cudaStreamCreateWithFlags(&s2, cudaStreamNonBlocking);
        cudaEventCreateWithFlags(&evRoot, cudaEventDisableTiming);
        cudaEventCreateWithFlags(&evPackQK, cudaEventDisableTiming);
        cudaEventCreateWithFlags(&evK1, cudaEventDisableTiming);
        cudaEventCreateWithFlags(&evV1, cudaEventDisableTiming);
        cudaEventCreateWithFlags(&evWvpB, cudaEventDisableTiming);
        cudaEventCreateWithFlags(&evFv, cudaEventDisableTiming);
        cudaEventCreateWithFlags(&evFeat1, cudaEventDisableTiming);
        cudaEventCreateWithFlags(&evMV, cudaEventDisableTiming);
        cudaEventCreateWithFlags(&evMask, cudaEventDisableTiming);
        cudaEventCreateWithFlags(&evXn1, cudaEventDisableTiming);
        cudaEventCreateWithFlags(&evNB1, cudaEventDisableTiming);
        cudaEventCreateWithFlags(&evXn2, cudaEventDisableTiming);
    }
    cudaStream_t s0 = 0;

    cudaEventRecord(evRoot, s0);

    // ---- s1: packing + K/V projections of attn1 ----
    cudaStreamWaitEvent(s1, evRoot, 0);
    pack_qk_kernel<<<1024, 256, 0, s1>>>(arm_wq, arm_wk, arm_bq, arm_bk);
    cudaEventRecord(evPackQK, s1);
    gemm_tc<<<dim3(2, 4, 1), 256, 0, s1>>>(x, fam_wk, nullptr, p_k1, ND, Hh, Cch,
                                           Cch, Hh, Hh, 0, 0, 0, 0, 0, 0, 1, 0);
    cudaEventRecord(evK1, s1);
    gemm_tc<<<dim3(4, 4, 1), 256, 0, s1>>>(x, fam_wv, fam_bv, p_v1, ND, Cch, Cch,
                                           Cch, Cch, Cch, 0, 0, 0, 0, 0, 0, 1, 0);
    cudaEventRecord(evV1, s1);

    // ---- s2: Wvp/bvp + node-weight packs ----
    cudaStreamWaitEvent(s2, evRoot, 0);
    gemm_tc<<<dim3(4, 4, 1), 256, 0, s2>>>(arm_wv, ep_w, nullptr, p_Wvp, Cch, Cch, Cch,
                                           Cch, Cch, Cch, 0, 0, 0, 0, 0, 0, 1, 0);
    bvp_kernel<<<1, 512, 0, s2>>>(arm_bv, ep_w);
    cudaEventRecord(evWvpB, s2);
    pack_node_kernel<<<4096, 256, 0, s2>>>(gw[0], gw[1], gw[3], gw[4], p_wnA);
    pack_node_kernel<<<4096, 256, 0, s2>>>(gw[5], gw[6], gw[8], gw[9], p_wnB);

    // ---- s0 main chain: h -> BN1 ----
    gemm_tc<<<dim3(4, 4, 12), 256, 0, s0>>>(x, Wc, nullptr, p_h, ND, Cch, Cch,
                                            Cch, Cch, Cch,
                                            0, 0, (long)Cch * Cch, 0, (long)ND * Cch, 0, 1, 0);
    bn1_stats_kernel<<<dim3(12, 8), 256, 0, s0>>>();
    bn1_apply_kernel<<<dim3(12, 8), 128, 0, s0>>>();
    cudaEventRecord(evFv, s0);

    // ---- s2: mask + xnode L1 (need fv only) ----
    cudaStreamWaitEvent(s2, evFv, 0);
    mask_kernel<<<Bb, 256, 0, s2>>>();
    cudaEventRecord(evMask, s2);
    gemm_tc<<<dim3(16, 1, 1), 256, 0, s2>>>(p_fv, p_wnA, nullptr, p_xnode,
                                            Bb * Nn, 2048, Cch, Cch, 2048, 2048,
                                            0, 0, 0, 0, 0, 0, 1, 0);
    cudaEventRecord(evXn1, s2);

    // ---- s0: attn1 ----
    gemm_tc<<<dim3(2, 37, 1), 256, 0, s0>>>(p_h, fam_wq, fam_bq, p_q1, RQ, Hh, Cch,
                                            Cch, Hh, Hh, 0, 0, 0, 0, 0, 0, 1, 0);
    cudaStreamWaitEvent(s0, evK1, 0);
    gemm_tc<<<dim3(1, 1, 96), 256, 0, s0>>>(p_q1, p_k1, nullptr, p_S1, Dd, Dd, Hh,
                                            Hh, Hh, Dd,
                                            (long)8 * Dd * Hh, (long)Dd * Hh,
                                            0, (long)Dd * Hh,
                                            (long)8 * Dd * Dd, (long)Dd * Dd, 8, 1);
    softmaxP_kernel<<<96, 256, 0, s0>>>();
    cudaStreamWaitEvent(s0, evV1, 0);
    gemm_tc<<<dim3(4, 1, 96), 256, 0, s0>>>(p_P, p_v1, nullptr, p_f1, Dd, Cch, 64,
                                            64, Cch, Cch,
                                            (long)8 * Dd * 64, (long)Dd * 64,
                                            0, (long)Dd * Cch,
                                            (long)Dd * Cch, (long)Nn * Dd * Cch, 8, 0);
    cudaEventRecord(evFeat1, s0);

    // ---- s1: Vp + MV Gram (parallel with QK2/S on s0) ----
    cudaStreamWaitEvent(s1, evFeat1, 0);
    cudaStreamWaitEvent(s1, evWvpB, 0);
    gemm_tc<<<dim3(4, 37, 1), 256, 0, s1>>>(p_f1, p_Wvp, p_bvp, p_Vp, RQ, Cch, Cch,
                                            Cch, Cch, Cch, 0, 0, 0, 0, 0, 0, 1, 0);
    gemm64_kernel<<<dim3(1, 1, 96), 256, 0, s1>>>(p_Vp, p_Vp, nullptr, p_MV,
                                                  Dd, Dd, Cch, Cch, Cch, Dd,
                                                  (long)Dd * Cch, (long)Dd * Cch, (long)Dd * Dd, 1);
    cudaEventRecord(evMV, s1);

    // ---- s0: QK2 -> S -> pg -> zbar -> edge ----
    cudaStreamWaitEvent(s0, evPackQK, 0);
    gemm_tc<<<dim3(4, 37, 1), 256, 0, s0>>>(p_f1, p_wqk, p_bqk, p_QK2, RQ, Cch, Cch,
                                            Cch, Cch, Cch, 0, 0, 0, 0, 0, 0, 1, 0);
    gemm_tc<<<dim3(5, 5, 8), 256, 0, s0>>>(p_QK2, p_QK2 + 256, nullptr, p_S, SQ, SQ, Hh,
                                           Cch, Cch, SQ,
                                           (long)SQ * Cch, 0, (long)SQ * Cch, 0,
                                           (long)SQ * SQ, 0, 1, 1);
    cudaStreamWaitEvent(s0, evMV, 0);
    pg_kernel<<<dim3(Ee, Bb), 256, 0, s0>>>();
    zbar_stats_kernel<<<dim3(Nn, Bb), 512, 0, s0>>>(ep_b);
    cudaStreamWaitEvent(s0, evMask, 0);
    edge_bn_mask_kernel<<<Ee, 128, 0, s0>>>();

    // ---- GNN layer 1 ----
    gemm_tc<<<dim3(4, 9, 1), 256, 0, s0>>>(p_fe, gw[2], nullptr, p_xw,
                                           Bb * Ee, Cch, Cch, Cch, Cch, Cch,
                                           0, 0, 0, 0, 0, 0, 1, 0);
    cudaStreamWaitEvent(s0, evXn1, 0);
    agg_bn_kernel<<<Ee, 128, 0, s0>>>();
    softmax_msg_kernel<<<Bb * Nn, 128, 0, s0>>>();
    node_bn_kernel<<<Nn, 128, 0, s0>>>();
    cudaEventRecord(evNB1, s0);

    // ---- GNN layer 2 (xnode on s1 overlapped with xw on s0) ----
    cudaStreamWaitEvent(s1, evNB1, 0);
    gemm_tc<<<dim3(16, 1, 1), 256, 0, s1>>>(p_fv, p_wnB, nullptr, p_xnode,
                                            Bb * Nn, 2048, Cch, Cch, 2048, 2048,
                                            0, 0, 0, 0, 0, 0, 1, 0);
    cudaEventRecord(evXn2, s1);
    gemm_tc<<<dim3(4, 9, 1), 256, 0, s0>>>(p_fe, gw[7], nullptr, p_xw,
                                           Bb * Ee, Cch, Cch, Cch, Cch, Cch,
                                           0, 0, 0, 0, 0, 0, 1, 0);
    cudaStreamWaitEvent(s0, evXn2, 0);
    agg_bn_kernel<<<Ee, 128, 0, s0>>>();
    softmax_msg_kernel<<<Bb * Nn, 128, 0, s0>>>();
    node_bn_kernel<<<Nn, 128, 0, s0>>>();

    cls_kernel<<<Bb * Nn, 128, 0, s0>>>(sc_w, out);
    edgefc_kernel<<<Bb * Ee, 128, 0, s0>>>(efc_w, efc_b, out);
}

// round 6
// speedup vs baseline: 4.7390x; 1.0081x over previous
#include <cuda_runtime.h>
#include <math.h>
#include <stdint.h>

// Problem constants
#define Bb   8
#define Dd   49
#define Cch  512
#define Nn   12
#define Hh   256          // C/2
#define Ee   144          // N*N
#define ND   392          // B*D
#define RQ   4704         // N*B*D
#define SQ   588          // N*D (rows per batch in attn2)
#define SCALE_ 0.0625f    // (C/2)^-0.5
#define EPS_  1e-5f

// ---------------- static device scratch (zero-initialized at load) ----------
__device__ float g_h[RQ * Cch];
__device__ float g_q1[RQ * Hh];
__device__ float g_k1[ND * Hh];
__device__ float g_v1[(ND + 16) * Cch];  // padded rows stay 0 (zero-init)
__device__ float g_S1[96 * Dd * Dd];
__device__ float g_P[96 * Dd * 64];
__device__ float g_feat1[RQ * Cch];      // rows (b*12+n)*49+d  (b-major)
__device__ float g_QK2[RQ * Cch];        // cols 0-255 = Q2, 256-511 = K2
__device__ float g_Vp[RQ * Cch];
__device__ float g_Wvp[Cch * Cch];
__device__ float g_bvp[Cch];
__device__ float g_wqk[Cch * Cch];
__device__ float g_bqk[Cch];
__device__ float g_S[Bb * SQ * SQ];
__device__ float g_MV[Bb * Nn * Dd * Dd];
__device__ float g_w[Bb * Ee * Dd];
__device__ float g_gram[Bb * Ee];
__device__ float g_fv[Bb * Nn * Cch];
__device__ float g_zbar[Bb * Ee * Cch];
__device__ float g_ps1[Bb * Ee];
__device__ float g_ps2[Bb * Ee];
__device__ float g_bn1m[Nn * Cch];
__device__ float g_bn1r[Nn * Cch];
__device__ float g_mask[Bb * Ee];
__device__ float g_fe[Bb * Ee * Cch];
__device__ float g_wnodeA[Cch * 2048];
__device__ float g_wnodeB[Cch * 2048];
__device__ float g_xnode[Bb * Nn * 2048];
__device__ float g_xw[Bb * Ee * Cch];
__device__ float g_msg[Bb * Nn * Cch];

// ---------------- helpers ----------------------------------------------------
__device__ __forceinline__ float block_reduce_sum(float v, float* sm) {
    int lane = threadIdx.x & 31, w = threadIdx.x >> 5;
#pragma unroll
    for (int o = 16; o; o >>= 1) v += __shfl_xor_sync(0xffffffffu, v, o);
    if (lane == 0) sm[w] = v;
    __syncthreads();
    int nw = (blockDim.x + 31) >> 5;
    float r = 0.f;
    if (threadIdx.x < 32) {
        r = (threadIdx.x < nw) ? sm[threadIdx.x] : 0.f;
#pragma unroll
        for (int o = 16; o; o >>= 1) r += __shfl_xor_sync(0xffffffffu, r, o);
        if (threadIdx.x == 0) sm[0] = r;
    }
    __syncthreads();
    r = sm[0];
    __syncthreads();
    return r;
}

__device__ __forceinline__ uint32_t f2tf32(float x) {
    uint32_t r;
    asm("cvt.rna.tf32.f32 %0, %1;" : "=r"(r) : "f"(x));
    return r;
}

__device__ __forceinline__ void mma_tf32(float* c, const uint32_t* a, const uint32_t* b) {
    asm volatile(
        "mma.sync.aligned.m16n8k8.row.col.f32.tf32.tf32.f32 "
        "{%0,%1,%2,%3}, {%4,%5,%6,%7}, {%8,%9}, {%0,%1,%2,%3};"
        : "+f"(c[0]), "+f"(c[1]), "+f"(c[2]), "+f"(c[3])
        : "r"(a[0]), "r"(a[1]), "r"(a[2]), "r"(a[3]), "r"(b[0]), "r"(b[1]));
}

__device__ __forceinline__ float4 f4add(float4 a, float4 b) {
    return make_float4(a.x + b.x, a.y + b.y, a.z + b.z, a.w + b.w);
}

// ---------------- gemm_tc: TF32 tensor-core GEMM, 128x128x16 -----------------
// Smem holds PRE-CONVERTED tf32 bits; inner loop is pure LDS + MMA.
__global__ __launch_bounds__(256, 2) void gemm_tc(
    const float* __restrict__ A, const float* __restrict__ Bm,
    const float* __restrict__ bias, float* __restrict__ Cm,
    int M, int Np, int K, int lda, int ldb, int ldc,
    long sA1, long sA2, long sB1, long sB2, long sC1, long sC2,
    int zdiv, int transB)
{
    int z = blockIdx.z;
    int zq = z / zdiv, zr = z % zdiv;
    const float* Az = A + zq * sA1 + (long)zr * sA2;
    const float* Bz = Bm + zq * sB1 + (long)zr * sB2;
    float* Cz = Cm + zq * sC1 + (long)zr * sC2;

    __shared__ uint32_t As[2][16][132];
    __shared__ uint32_t Bs[2][16][132];
    int tid = threadIdx.x;
    int row0 = blockIdx.y * 128, col0 = blockIdx.x * 128;

    int arow = tid >> 1, ak0 = (tid & 1) * 8;
    int bkk = tid >> 4, bn0 = (tid & 15) * 8;

    int warp = tid >> 5, lane = tid & 31;
    int wm = (warp >> 2) * 64, wn = (warp & 3) * 32;
    int gid = lane >> 2, tig = lane & 3;

    float c[4][4][4];
#pragma unroll
    for (int mi = 0; mi < 4; mi++)
#pragma unroll
        for (int ni = 0; ni < 4; ni++)
#pragma unroll
            for (int q = 0; q < 4; q++) c[mi][ni][q] = 0.f;

    const float4 z4 = {0.f, 0.f, 0.f, 0.f};
    float4 a0g, a1g, b0g, b1g;

#define LOAD_TILE(k0)                                                          \
    {                                                                          \
        int gr = row0 + arow;                                                  \
        if (gr < M) {                                                          \
            const float* p = Az + (long)gr * lda + (k0) + ak0;                 \
            a0g = *(const float4*)p; a1g = *(const float4*)(p + 4);            \
        } else { a0g = z4; a1g = z4; }                                         \
        if (!transB) {                                                         \
            int gc = col0 + bn0;                                               \
            if (gc < Np) {                                                     \
                const float* p = Bz + (long)((k0) + bkk) * ldb + gc;           \
                b0g = *(const float4*)p; b1g = *(const float4*)(p + 4);        \
            } else { b0g = z4; b1g = z4; }                                     \
        } else {                                                               \
            int gn = col0 + arow;                                              \
            if (gn < Np) {                                                     \
                const float* p = Bz + (long)gn * ldb + (k0) + ak0;             \
                b0g = *(const float4*)p; b1g = *(const float4*)(p + 4);        \
            } else { b0g = z4; b1g = z4; }                                     \
        }                                                                      \
    }

// convert once here; inner loop never converts
#define STORE_TILE(buf)                                                        \
    {                                                                          \
        As[buf][ak0+0][arow]=f2tf32(a0g.x); As[buf][ak0+1][arow]=f2tf32(a0g.y);\
        As[buf][ak0+2][arow]=f2tf32(a0g.z); As[buf][ak0+3][arow]=f2tf32(a0g.w);\
        As[buf][ak0+4][arow]=f2tf32(a1g.x); As[buf][ak0+5][arow]=f2tf32(a1g.y);\
        As[buf][ak0+6][arow]=f2tf32(a1g.z); As[buf][ak0+7][arow]=f2tf32(a1g.w);\
        if (!transB) {                                                         \
            uint4 u0, u1;                                                      \
            u0.x=f2tf32(b0g.x); u0.y=f2tf32(b0g.y);                            \
            u0.z=f2tf32(b0g.z); u0.w=f2tf32(b0g.w);                            \
            u1.x=f2tf32(b1g.x); u1.y=f2tf32(b1g.y);                            \
            u1.z=f2tf32(b1g.z); u1.w=f2tf32(b1g.w);                            \
            *(uint4*)&Bs[buf][bkk][bn0] = u0;                                  \
            *(uint4*)&Bs[buf][bkk][bn0+4] = u1;                                \
        } else {                                                               \
            Bs[buf][ak0+0][arow]=f2tf32(b0g.x); Bs[buf][ak0+1][arow]=f2tf32(b0g.y);\
            Bs[buf][ak0+2][arow]=f2tf32(b0g.z); Bs[buf][ak0+3][arow]=f2tf32(b0g.w);\
            Bs[buf][ak0+4][arow]=f2tf32(b1g.x); Bs[buf][ak0+5][arow]=f2tf32(b1g.y);\
            Bs[buf][ak0+6][arow]=f2tf32(b1g.z); Bs[buf][ak0+7][arow]=f2tf32(b1g.w);\
        }                                                                      \
    }

    LOAD_TILE(0);
    STORE_TILE(0);
    __syncthreads();

    int nt = K >> 4;
    for (int t = 0; t < nt; t++) {
        int buf = t & 1;
        if (t + 1 < nt) LOAD_TILE((t + 1) << 4);
#pragma unroll
        for (int k8 = 0; k8 < 16; k8 += 8) {
            uint32_t af[4][4], bf[4][2];
#pragma unroll
            for (int mi = 0; mi < 4; mi++) {
                int mb = wm + mi * 16;
                af[mi][0] = As[buf][k8 + tig][mb + gid];
                af[mi][1] = As[buf][k8 + tig][mb + gid + 8];
                af[mi][2] = As[buf][k8 + tig + 4][mb + gid];
                af[mi][3] = As[buf][k8 + tig + 4][mb + gid + 8];
            }
#pragma unroll
            for (int ni = 0; ni < 4; ni++) {
                int nb = wn + ni * 8 + gid;
                bf[ni][0] = Bs[buf][k8 + tig][nb];
                bf[ni][1] = Bs[buf][k8 + tig + 4][nb];
            }
#pragma unroll
            for (int mi = 0; mi < 4; mi++)
#pragma unroll
                for (int ni = 0; ni < 4; ni++)
                    mma_tf32(c[mi][ni], af[mi], bf[ni]);
        }
        if (t + 1 < nt) {
            STORE_TILE(buf ^ 1);
            __syncthreads();
        }
    }

#pragma unroll
    for (int mi = 0; mi < 4; mi++) {
        int r0 = row0 + wm + mi * 16 + gid;
        int r1 = r0 + 8;
#pragma unroll
        for (int ni = 0; ni < 4; ni++) {
            int cb = col0 + wn + ni * 8 + 2 * tig;
            float bv0 = 0.f, bv1 = 0.f;
            if (bias) {
                if (cb < Np) bv0 = bias[cb];
                if (cb + 1 < Np) bv1 = bias[cb + 1];
            }
            if (r0 < M) {
                if (cb < Np)     Cz[(long)r0 * ldc + cb]     = c[mi][ni][0] + bv0;
                if (cb + 1 < Np) Cz[(long)r0 * ldc + cb + 1] = c[mi][ni][1] + bv1;
            }
            if (r1 < M) {
                if (cb < Np)     Cz[(long)r1 * ldc + cb]     = c[mi][ni][2] + bv0;
                if (cb + 1 < Np) Cz[(long)r1 * ldc + cb + 1] = c[mi][ni][3] + bv1;
            }
        }
    }
#undef LOAD_TILE
#undef STORE_TILE
}

// ---------------- gemm64 (fp32, kept only for the MV Gram) -------------------
__global__ __launch_bounds__(256) void gemm64_kernel(
    const float* __restrict__ A, const float* __restrict__ Bm,
    const float* __restrict__ bias, float* __restrict__ Cm,
    int M, int Np, int K, int lda, int ldb, int ldc,
    long sA, long sB, long sC, int transB)
{
    const float* Az = A + (long)blockIdx.z * sA;
    const float* Bz = Bm + (long)blockIdx.z * sB;
    float* Cz = Cm + (long)blockIdx.z * sC;
    __shared__ float As[16][64];
    __shared__ float Bs[16][64];
    int tid = threadIdx.x;
    int tx = tid & 15, ty = tid >> 4;
    int row0 = blockIdx.y * 64, col0 = blockIdx.x * 64;
    int lr = tid >> 2, lk = (tid & 3) * 4;
    int bkk = tid >> 4, bn = (tid & 15) * 4;
    const float4 z4 = {0.f, 0.f, 0.f, 0.f};
    float acc[4][4];
#pragma unroll
    for (int i = 0; i < 4; i++)
#pragma unroll
        for (int j = 0; j < 4; j++) acc[i][j] = 0.f;

    for (int k0 = 0; k0 < K; k0 += 16) {
        float4 av = z4, bv = z4;
        if (row0 + lr < M) av = *(const float4*)(Az + (long)(row0 + lr) * lda + k0 + lk);
        if (!transB) {
            if (col0 + bn < Np) bv = *(const float4*)(Bz + (long)(k0 + bkk) * ldb + col0 + bn);
        } else {
            if (col0 + lr < Np) bv = *(const float4*)(Bz + (long)(col0 + lr) * ldb + k0 + lk);
        }
        __syncthreads();
        As[lk+0][lr]=av.x; As[lk+1][lr]=av.y; As[lk+2][lr]=av.z; As[lk+3][lr]=av.w;
        if (!transB) {
            *(float4*)&Bs[bkk][bn] = bv;
        } else {
            Bs[lk+0][lr]=bv.x; Bs[lk+1][lr]=bv.y; Bs[lk+2][lr]=bv.z; Bs[lk+3][lr]=bv.w;
        }
        __syncthreads();
#pragma unroll
        for (int kk = 0; kk < 16; kk++) {
            float4 a4 = *(const float4*)&As[kk][ty * 4];
            float4 b4 = *(const float4*)&Bs[kk][tx * 4];
            float a[4] = {a4.x, a4.y, a4.z, a4.w};
            float b[4] = {b4.x, b4.y, b4.z, b4.w};
#pragma unroll
            for (int i = 0; i < 4; i++)
#pragma unroll
                for (int j = 0; j < 4; j++) acc[i][j] += a[i] * b[j];
        }
    }
#pragma unroll
    for (int i = 0; i < 4; i++) {
        int gr = row0 + ty * 4 + i;
        if (gr >= M) continue;
#pragma unroll
        for (int j = 0; j < 4; j++) {
            int gc = col0 + tx * 4 + j;
            if (gc < Np)
                Cz[(long)gr * ldc + gc] = acc[i][j] + (bias ? bias[gc] : 0.f);
        }
    }
}

// ---------------- weight packers ---------------------------------------------
__global__ void pack_qk_kernel(const float* __restrict__ wq, const float* __restrict__ wk,
                               const float* __restrict__ bq, const float* __restrict__ bk) {
    int idx = blockIdx.x * 256 + threadIdx.x;
    int k = idx >> 9, c = idx & 511;
    g_wqk[idx] = (c < 256) ? wq[k * 256 + c] : wk[k * 256 + c - 256];
    if (idx < 512) g_bqk[idx] = (idx < 256) ? bq[idx] : bk[idx - 256];
}

__global__ void pack_node_kernel(const float* __restrict__ wa, const float* __restrict__ wb,
                                 const float* __restrict__ wu, const float* __restrict__ wv,
                                 float* __restrict__ dst) {
    int idx = blockIdx.x * 256 + threadIdx.x;
    int k = idx >> 11, c = idx & 2047;
    const float* src = (c < 512) ? wa : (c < 1024) ? wb : (c < 1536) ? wu : wv;
    dst[idx] = src[k * 512 + (c & 511)];
}

// ---------------- BN1 ---------------------------------------------------------
__global__ void bn1_stats_kernel() {
    int n = blockIdx.x;
    int cl = threadIdx.x & 63;
    int q = threadIdx.x >> 6;
    int c = blockIdx.y * 64 + cl;
    float s1 = 0.f, s2 = 0.f;
    const float* base = g_h + (long)n * ND * Cch + c;
    for (int r = q; r < ND; r += 4) {
        float v = base[(long)r * Cch];
        s1 += v; s2 += v * v;
    }
    __shared__ float sm1[4][64], sm2[4][64];
    sm1[q][cl] = s1; sm2[q][cl] = s2;
    __syncthreads();
    if (q == 0) {
        s1 = sm1[0][cl] + sm1[1][cl] + sm1[2][cl] + sm1[3][cl];
        s2 = sm2[0][cl] + sm2[1][cl] + sm2[2][cl] + sm2[3][cl];
        float m = s1 / (float)ND;
        float var = s2 / (float)ND - m * m;
        g_bn1m[n * Cch + c] = m;
        g_bn1r[n * Cch + c] = rsqrtf(fmaxf(var, 0.f) + EPS_);
    }
}

__global__ void bn1_apply_kernel() {
    int n = blockIdx.x, b = blockIdx.y;
    int c4 = threadIdx.x;
    float4 m = ((const float4*)(g_bn1m + n * Cch))[c4];
    float4 r = ((const float4*)(g_bn1r + n * Cch))[c4];
    float4* hb = (float4*)(g_h + ((long)(n * Bb + b) * Dd) * Cch) + c4;
    float4 acc = {0.f, 0.f, 0.f, 0.f};
    for (int d = 0; d < Dd; d++) {
        float4 h = hb[(long)d * 128];
        float4 u;
        u.x = fmaxf((h.x - m.x) * r.x, 0.f);
        u.y = fmaxf((h.y - m.y) * r.y, 0.f);
        u.z = fmaxf((h.z - m.z) * r.z, 0.f);
        u.w = fmaxf((h.w - m.w) * r.w, 0.f);
        hb[(long)d * 128] = u;
        acc = f4add(acc, u);
    }
    float inv = 1.f / (float)Dd;
    acc.x *= inv; acc.y *= inv; acc.z *= inv; acc.w *= inv;
    ((float4*)(g_fv + (long)(b * Nn + n) * Cch))[c4] = acc;
}

// ---------------- attn1 softmax ----------------------------------------------
__global__ void softmaxP_kernel() {
    int z = blockIdx.x;
    int tid = threadIdx.x, w = tid >> 5, lane = tid & 31;
    const float* Sb = g_S1 + (long)z * Dd * Dd;
    float* Pb = g_P + (long)z * Dd * 64;
    for (int r = w; r < Dd; r += 8) {
        float v0 = (lane < Dd) ? Sb[r * Dd + lane] * SCALE_ : -1e30f;
        float v1 = (lane + 32 < Dd) ? Sb[r * Dd + lane + 32] * SCALE_ : -1e30f;
        float mx = fmaxf(v0, v1);
#pragma unroll
        for (int o = 16; o; o >>= 1) mx = fmaxf(mx, __shfl_xor_sync(0xffffffffu, mx, o));
        float e0 = (lane < Dd) ? expf(v0 - mx) : 0.f;
        float e1 = (lane + 32 < Dd) ? expf(v1 - mx) : 0.f;
        float s = e0 + e1;
#pragma unroll
        for (int o = 16; o; o >>= 1) s += __shfl_xor_sync(0xffffffffu, s, o);
        float inv = 1.f / s;
        if (lane < Dd) Pb[r * 64 + lane] = e0 * inv;
        Pb[r * 64 + lane + 32] = (lane + 32 < Dd) ? e1 * inv : 0.f;
    }
}

__global__ void bvp_kernel(const float* __restrict__ bv, const float* __restrict__ epw) {
    int c = threadIdx.x;
    float s = 0.f;
    for (int k = 0; k < Cch; k++) s += bv[k] * epw[k * Cch + c];
    g_bvp[c] = s;
}

// ---------------- attn2: per-(b,e) softmax + agg weights + Gram term ----------
__global__ void pg_kernel() {
    int e = blockIdx.x, b = blockIdx.y;
    int i = e / Nn, j = e % Nn;
    __shared__ float P[49][50];
    __shared__ float MVs[Dd * Dd];
    __shared__ float gpart[8];
    int tid = threadIdx.x, w = tid >> 5, lane = tid & 31;
    const float* MVg = g_MV + (long)(b * Nn + i) * (Dd * Dd);
    for (int t = tid; t < Dd * Dd; t += 256) MVs[t] = MVg[t];
    const float* Sb = g_S + (long)b * SQ * SQ + (long)(j * Dd) * SQ + i * Dd;
    for (int r = w; r < Dd; r += 8) {
        float v0 = (lane < Dd) ? Sb[r * SQ + lane] * SCALE_ : -1e30f;
        float v1 = (lane + 32 < Dd) ? Sb[r * SQ + lane + 32] * SCALE_ : -1e30f;
        float mx = fmaxf(v0, v1);
#pragma unroll
        for (int o = 16; o; o >>= 1) mx = fmaxf(mx, __shfl_xor_sync(0xffffffffu, mx, o));
        float e0 = (lane < Dd) ? expf(v0 - mx) : 0.f;
        float e1 = (lane + 32 < Dd) ? expf(v1 - mx) : 0.f;
        float s = e0 + e1;
#pragma unroll
        for (int o = 16; o; o >>= 1) s += __shfl_xor_sync(0xffffffffu, s, o);
        float inv = 1.f / s;
        if (lane < Dd) P[r][lane] = e0 * inv;
        if (lane + 32 < Dd) P[r][lane + 32] = e1 * inv;
    }
    __syncthreads();
    if (tid < Dd) {
        float s = 0.f;
        for (int r = 0; r < Dd; r++) s += P[r][tid];
        g_w[((long)b * Ee + e) * Dd + tid] = s * (1.f / (float)Dd);
    }
    float acc = 0.f;
    for (int r = w; r < Dd; r += 8) {
        float t0 = 0.f, t1 = 0.f;
        for (int bbk = 0; bbk < Dd; bbk++) {
            float p = P[r][bbk];
            t0 += MVs[lane * Dd + bbk] * p;
            if (lane + 32 < Dd) t1 += MVs[(lane + 32) * Dd + bbk] * p;
        }
        acc += P[r][lane] * t0;
        if (lane + 32 < Dd) acc += P[r][lane + 32] * t1;
    }
#pragma unroll
    for (int o = 16; o; o >>= 1) acc += __shfl_xor_sync(0xffffffffu, acc, o);
    if (lane == 0) gpart[w] = acc;
    __syncthreads();
    if (tid == 0) {
        float s = 0.f;
        for (int q = 0; q < 8; q++) s += gpart[q];
        g_gram[b * Ee + e] = s;
    }
}

// zbar = w^T Vp + epb ; stats via Gram identity. grid (12,8)=(i,b), block 512.
__global__ void zbar_stats_kernel(const float* __restrict__ ep_b) {
    int i = blockIdx.x, b = blockIdx.y;
    __shared__ float ws[Nn * Dd];
    __shared__ float red[16][26];
    int tid = threadIdx.x, lane = tid & 31, w = tid >> 5;
    for (int t = tid; t < Nn * Dd; t += 512) {
        int j = t / Dd, d2 = t % Dd;
        ws[t] = g_w[((long)b * Ee + i * Nn + j) * Dd + d2];
    }
    __syncthreads();
    float acc[Nn];
#pragma unroll
    for (int j = 0; j < Nn; j++) acc[j] = 0.f;
    const float* Vb = g_Vp + (long)((b * Nn + i) * Dd) * Cch;
    for (int d2 = 0; d2 < Dd; d2++) {
        float v = Vb[(long)d2 * Cch + tid];
#pragma unroll
        for (int j = 0; j < Nn; j++) acc[j] += ws[j * Dd + d2] * v;
    }
    float eb = ep_b[tid];
    float loc[25];
#pragma unroll
    for (int j = 0; j < Nn; j++) {
        float z = acc[j] + eb;
        g_zbar[((long)b * Ee + i * Nn + j) * Cch + tid] = z;
        loc[j] = z;
        loc[Nn + j] = eb * z;
    }
    loc[24] = eb * eb;
#pragma unroll
    for (int k = 0; k < 25; k++) {
        float v = loc[k];
#pragma unroll
        for (int o = 16; o; o >>= 1) v += __shfl_xor_sync(0xffffffffu, v, o);
        if (lane == 0) red[w][k] = v;
    }
    __syncthreads();
    if (tid < Nn) {
        float S = 0.f, T = 0.f, E = 0.f;
#pragma unroll
        for (int q = 0; q < 16; q++) {
            S += red[q][tid]; T += red[q][Nn + tid]; E += red[q][24];
        }
        int e = i * Nn + tid;
        g_ps1[b * Ee + e] = 49.f * S;
        g_ps2[b * Ee + e] = g_gram[b * Ee + e] + 98.f * T - 49.f * E;
    }
}

// ---------------- cosine adjacency mask --------------------------------------
__global__ void mask_kernel() {
    int b = blockIdx.x;
    __shared__ float sinv[Nn];
    __shared__ float adj[Ee];
    __shared__ float dis[Nn];
    int tid = threadIdx.x, w = tid >> 5, lane = tid & 31;
    for (int n = w; n < Nn; n += 8) {
        const float4* f = (const float4*)(g_fv + (long)(b * Nn + n) * Cch);
        float s = 0.f;
        for (int t = lane; t < 128; t += 32) {
            float4 x = f[t];
            s += x.x * x.x + x.y * x.y + x.z * x.z + x.w * x.w;
        }
#pragma unroll
        for (int o = 16; o; o >>= 1) s += __shfl_xor_sync(0xffffffffu, s, o);
        if (lane == 0) sinv[n] = 1.f / fmaxf(sqrtf(s), 1e-12f);
    }
    __syncthreads();
    for (int e = w; e < Ee; e += 8) {
        int i = e / Nn, jn = e % Nn;
        const float4* fi = (const float4*)(g_fv + (long)(b * Nn + i) * Cch);
        const float4* fj = (const float4*)(g_fv + (long)(b * Nn + jn) * Cch);
        float s = 0.f;
        for (int t = lane; t < 128; t += 32) {
            float4 a = fi[t], c = fj[t];
            s += a.x * c.x + a.y * c.y + a.z * c.z + a.w * c.w;
        }
#pragma unroll
        for (int o = 16; o; o >>= 1) s += __shfl_xor_sync(0xffffffffu, s, o);
        if (lane == 0) adj[e] = s * sinv[i] * sinv[jn];
    }
    __syncthreads();
    if (tid < Nn) {
        float s = 0.f;
        for (int jn = 0; jn < Nn; jn++) s += adj[tid * Nn + jn];
        dis[tid] = rsqrtf(s);
    }
    __syncthreads();
    if (tid < Ee) {
        int i = tid / Nn, jn = tid % Nn;
        g_mask[b * Ee + tid] = adj[tid] * dis[i] * dis[jn];
    }
}

// ---------------- edge BN + mask ---------------------------------------------
__global__ void edge_bn_mask_kernel() {
    int e = blockIdx.x;
    __shared__ float mrs[2];
    int tid = threadIdx.x;
    if (tid == 0) {
        float s1 = 0.f, s2 = 0.f;
        for (int b = 0; b < Bb; b++) { s1 += g_ps1[b * Ee + e]; s2 += g_ps2[b * Ee + e]; }
        float cnt = (float)(Bb * Dd * Cch);
        float m = s1 / cnt;
        float v = s2 / cnt - m * m;
        mrs[0] = m;
        mrs[1] = rsqrtf(fmaxf(v, 0.f) + EPS_);
    }
    __syncthreads();
    float m = mrs[0], r = mrs[1];
    for (int b = 0; b < Bb; b++) {
        float mk = g_mask[b * Ee + e] * r;
        const float4* zb = (const float4*)(g_zbar + (long)(b * Ee + e) * Cch);
        float4* fe = (float4*)(g_fe + (long)(b * Ee + e) * Cch);
        float4 z = zb[tid];
        fe[tid] = make_float4((z.x - m) * mk, (z.y - m) * mk, (z.z - m) * mk, (z.w - m) * mk);
    }
}

// ---------------- GNN layer pieces -------------------------------------------
__global__ void agg_bn_kernel() {
    int e = blockIdx.x;
    int i = e / Nn, jn = e % Nn;
    __shared__ float sm[32];
    int tid = threadIdx.x;
    float4 agg[Bb];
    float s1 = 0.f, s2 = 0.f;
#pragma unroll
    for (int b = 0; b < Bb; b++) {
        float4 va = ((const float4*)(g_xnode + (long)(b * Nn + i) * 2048))[tid];
        float4 vb = ((const float4*)(g_xnode + (long)(b * Nn + jn) * 2048 + 512))[tid];
        float4 vw = ((const float4*)(g_xw + (long)(b * Ee + e) * Cch))[tid];
        float4 v = f4add(f4add(va, vb), vw);
        agg[b] = v;
        s1 += v.x + v.y + v.z + v.w;
        s2 += v.x * v.x + v.y * v.y + v.z * v.z + v.w * v.w;
    }
    s1 = block_reduce_sum(s1, sm);
    s2 = block_reduce_sum(s2, sm);
    float cnt = (float)(Bb * Cch);
    float m = s1 / cnt;
    float r = rsqrtf(fmaxf(s2 / cnt - m * m, 0.f) + EPS_);
#pragma unroll
    for (int b = 0; b < Bb; b++) {
        float4* fe = (float4*)(g_fe + (long)(b * Ee + e) * Cch);
        float4 f = fe[tid], v = agg[b];
        f.x += fmaxf((v.x - m) * r, 0.f);
        f.y += fmaxf((v.y - m) * r, 0.f);
        f.z += fmaxf((v.z - m) * r, 0.f);
        f.w += fmaxf((v.w - m) * r, 0.f);
        fe[tid] = f;
    }
}

__global__ void softmax_msg_kernel() {
    int bi = blockIdx.x;
    int b = bi / Nn, i = bi % Nn;
    int tid = threadIdx.x;
    float4 v[Nn];
    float4 mx = {-1e30f, -1e30f, -1e30f, -1e30f};
#pragma unroll
    for (int jn = 0; jn < Nn; jn++) {
        float4 ed = ((const float4*)(g_fe + (long)(b * Ee + i * Nn + jn) * Cch))[tid];
        float4 s;
        s.x = 1.f / (1.f + expf(-ed.x));
        s.y = 1.f / (1.f + expf(-ed.y));
        s.z = 1.f / (1.f + expf(-ed.z));
        s.w = 1.f / (1.f + expf(-ed.w));
        v[jn] = s;
        mx.x = fmaxf(mx.x, s.x); mx.y = fmaxf(mx.y, s.y);
        mx.z = fmaxf(mx.z, s.z); mx.w = fmaxf(mx.w, s.w);
    }
    float4 sum = {0.f, 0.f, 0.f, 0.f};
#pragma unroll
    for (int jn = 0; jn < Nn; jn++) {
        v[jn].x = expf(v[jn].x - mx.x); v[jn].y = expf(v[jn].y - mx.y);
        v[jn].z = expf(v[jn].z - mx.z); v[jn].w = expf(v[jn].w - mx.w);
        sum = f4add(sum, v[jn]);
    }
    float4 acc = {0.f, 0.f, 0.f, 0.f};
#pragma unroll
    for (int jn = 0; jn < Nn; jn++) {
        float4 u = ((const float4*)(g_xnode + (long)(b * Nn + jn) * 2048 + 1536))[tid];
        acc.x += v[jn].x * u.x; acc.y += v[jn].y * u.y;
        acc.z += v[jn].z * u.z; acc.w += v[jn].w * u.w;
    }
    float4 o;
    o.x = acc.x / (sum.x * (float)Nn); o.y = acc.y / (sum.y * (float)Nn);
    o.z = acc.z / (sum.z * (float)Nn); o.w = acc.w / (sum.w * (float)Nn);
    ((float4*)(g_msg + (long)(b * Nn + i) * Cch))[tid] = o;
}

__global__ void node_bn_kernel() {
    int n = blockIdx.x;
    __shared__ float sm[32];
    int tid = threadIdx.x;
    float4 t[Bb];
    float s1 = 0.f, s2 = 0.f;
#pragma unroll
    for (int b = 0; b < Bb; b++) {
        float4 xu = ((const float4*)(g_xnode + (long)(b * Nn + n) * 2048 + 1024))[tid];
        float4 ms = ((const float4*)(g_msg + (long)(b * Nn + n) * Cch))[tid];
        float4 v = f4add(xu, ms);
        t[b] = v;
        s1 += v.x + v.y + v.z + v.w;
        s2 += v.x * v.x + v.y * v.y + v.z * v.z + v.w * v.w;
    }
    s1 = block_reduce_sum(s1, sm);
    s2 = block_reduce_sum(s2, sm);
    float cnt = (float)(Bb * Cch);
    float m = s1 / cnt;
    float r = rsqrtf(fmaxf(s2 / cnt - m * m, 0.f) + EPS_);
#pragma unroll
    for (int b = 0; b < Bb; b++) {
        float4* fv = (float4*)(g_fv + (long)(b * Nn + n) * Cch);
        float4 f = fv[tid], v = t[b];
        f.x = fmaxf(f.x + (v.x - m) * r, 0.f);
        f.y = fmaxf(f.y + (v.y - m) * r, 0.f);
        f.z = fmaxf(f.z + (v.z - m) * r, 0.f);
        f.w = fmaxf(f.w + (v.w - m) * r, 0.f);
        fv[tid] = f;
    }
}

// ---------------- classifier heads -------------------------------------------
__global__ void cls_kernel(const float* __restrict__ sc_w, float* __restrict__ out) {
    int bn = blockIdx.x;
    int n = bn % Nn;
    __shared__ float sm[32];
    int tid = threadIdx.x;
    float sf = 0.f, ff = 0.f, ss = 0.f;
    for (int c = tid; c < Cch; c += 128) {
        float f = g_fv[(long)bn * Cch + c];
        float s = fmaxf(sc_w[n * Cch + c], 0.f);
        sf += f * s; ff += f * f; ss += s * s;
    }
    sf = block_reduce_sum(sf, sm);
    ff = block_reduce_sum(ff, sm);
    ss = block_reduce_sum(ss, sm);
    if (tid == 0)
        out[bn] = sf / (fmaxf(sqrtf(ff), 1e-12f) * fmaxf(sqrtf(ss), 1e-12f));
}

__global__ void edgefc_kernel(const float* __restrict__ w, const float* __restrict__ bias,
                              float* __restrict__ out) {
    int row = blockIdx.x;
    int tid = threadIdx.x;
    int k = tid >> 5, lane = tid & 31;
    const float* f = g_fe + (long)row * Cch;
    float dot = 0.f;
    for (int c = lane; c < Cch; c += 32) dot += f[c] * w[c * 4 + k];
#pragma unroll
    for (int o = 16; o; o >>= 1) dot += __shfl_xor_sync(0xffffffffu, dot, o);
    if (lane == 0) out[96 + row * 4 + k] = dot + bias[k];
}

// ---------------- host driver -------------------------------------------------
extern "C" void kernel_launch(void* const* d_in, const int* in_sizes, int n_in,
                              void* d_out, int out_size) {
    const float* x      = (const float*)d_in[0];
    const float* Wc     = (const float*)d_in[1];
    const float* fam_wq = (const float*)d_in[3];
    const float* fam_bq = (const float*)d_in[4];
    const float* fam_wk = (const float*)d_in[5];
    const float* fam_wv = (const float*)d_in[7];
    const float* fam_bv = (const float*)d_in[8];
    const float* arm_wq = (const float*)d_in[9];
    const float* arm_bq = (const float*)d_in[10];
    const float* arm_wk = (const float*)d_in[11];
    const float* arm_bk = (const float*)d_in[12];
    const float* arm_wv = (const float*)d_in[13];
    const float* arm_bv = (const float*)d_in[14];
    const float* ep_w   = (const float*)d_in[15];
    const float* ep_b   = (const float*)d_in[16];
    const float* gw[10];
    for (int t = 0; t < 10; t++) gw[t] = (const float*)d_in[17 + t];
    const float* sc_w   = (const float*)d_in[27];
    const float* efc_w  = (const float*)d_in[28];
    const float* efc_b  = (const float*)d_in[29];
    float* out = (float*)d_out;

    float *p_h, *p_q1, *p_k1, *p_v1, *p_S1, *p_P, *p_f1, *p_QK2, *p_Vp, *p_Wvp, *p_bvp;
    float *p_wqk, *p_bqk, *p_S, *p_MV, *p_fv, *p_fe, *p_wnA, *p_wnB, *p_xnode, *p_xw;
    cudaGetSymbolAddress((void**)&p_h, g_h);
    cudaGetSymbolAddress((void**)&p_q1, g_q1);
    cudaGetSymbolAddress((void**)&p_k1, g_k1);
    cudaGetSymbolAddress((void**)&p_v1, g_v1);
    cudaGetSymbolAddress((void**)&p_S1, g_S1);
    cudaGetSymbolAddress((void**)&p_P, g_P);
    cudaGetSymbolAddress((void**)&p_f1, g_feat1);
    cudaGetSymbolAddress((void**)&p_QK2, g_QK2);
    cudaGetSymbolAddress((void**)&p_Vp, g_Vp);
    cudaGetSymbolAddress((void**)&p_Wvp, g_Wvp);
    cudaGetSymbolAddress((void**)&p_bvp, g_bvp);
    cudaGetSymbolAddress((void**)&p_wqk, g_wqk);
    cudaGetSymbolAddress((void**)&p_bqk, g_bqk);
    cudaGetSymbolAddress((void**)&p_S, g_S);
    cudaGetSymbolAddress((void**)&p_MV, g_MV);
    cudaGetSymbolAddress((void**)&p_fv, g_fv);
    cudaGetSymbolAddress((void**)&p_fe, g_fe);
    cudaGetSymbolAddress((void**)&p_wnA, g_wnodeA);
    cudaGetSymbolAddress((void**)&p_wnB, g_wnodeB);
    cudaGetSymbolAddress((void**)&p_xnode, g_xnode);
    cudaGetSymbolAddress((void**)&p_xw, g_xw);

    static cudaStream_t s1 = nullptr, s2 = nullptr;
    static cudaEvent_t evRoot, evPackQK, evK1, evV1, evWvpB, evFv, evFeat1,
                       evMV, evMask, evXn1, evNB1, evXn2;
    if (!s1) {
        cudaStreamCreateWithFlags(&s1, cudaStreamNonBlocking);
        cudaStreamCreateWithFlags(&s2, cudaStreamNonBlocking);
        cudaEventCreateWithFlags(&evRoot, cudaEventDisableTiming);
        cudaEventCreateWithFlags(&evPackQK, cudaEventDisableTiming);
        cudaEventCreateWithFlags(&evK1, cudaEventDisableTiming);
        cudaEventCreateWithFlags(&evV1, cudaEventDisableTiming);
        cudaEventCreateWithFlags(&evWvpB, cudaEventDisableTiming);
        cudaEventCreateWithFlags(&evFv, cudaEventDisableTiming);
        cudaEventCreateWithFlags(&evFeat1, cudaEventDisableTiming);
        cudaEventCreateWithFlags(&evMV, cudaEventDisableTiming);
        cudaEventCreateWithFlags(&evMask, cudaEventDisableTiming);
        cudaEventCreateWithFlags(&evXn1, cudaEventDisableTiming);
        cudaEventCreateWithFlags(&evNB1, cudaEventDisableTiming);
        cudaEventCreateWithFlags(&evXn2, cudaEventDisableTiming);
    }
    cudaStream_t s0 = 0;

    cudaEventRecord(evRoot, s0);

    // ---- s1: packing + K/V projections of attn1 ----
    cudaStreamWaitEvent(s1, evRoot, 0);
    pack_qk_kernel<<<1024, 256, 0, s1>>>(arm_wq, arm_wk, arm_bq, arm_bk);
    cudaEventRecord(evPackQK, s1);
    gemm_tc<<<dim3(2, 4, 1), 256, 0, s1>>>(x, fam_wk, nullptr, p_k1, ND, Hh, Cch,
                                           Cch, Hh, Hh, 0, 0, 0, 0, 0, 0, 1, 0);
    cudaEventRecord(evK1, s1);
    gemm_tc<<<dim3(4, 4, 1), 256, 0, s1>>>(x, fam_wv, fam_bv, p_v1, ND, Cch, Cch,
                                           Cch, Cch, Cch, 0, 0, 0, 0, 0, 0, 1, 0);
    cudaEventRecord(evV1, s1);

    // ---- s2: Wvp/bvp + node-weight packs ----
    cudaStreamWaitEvent(s2, evRoot, 0);
    gemm_tc<<<dim3(4, 4, 1), 256, 0, s2>>>(arm_wv, ep_w, nullptr, p_Wvp, Cch, Cch, Cch,
                                           Cch, Cch, Cch, 0, 0, 0, 0, 0, 0, 1, 0);
    bvp_kernel<<<1, 512, 0, s2>>>(arm_bv, ep_w);
    cudaEventRecord(evWvpB, s2);
    pack_node_kernel<<<4096, 256, 0, s2>>>(gw[0], gw[1], gw[3], gw[4], p_wnA);
    pack_node_kernel<<<4096, 256, 0, s2>>>(gw[5], gw[6], gw[8], gw[9], p_wnB);

    // ---- s0 main chain: h -> BN1 ----
    gemm_tc<<<dim3(4, 4, 12), 256, 0, s0>>>(x, Wc, nullptr, p_h, ND, Cch, Cch,
                                            Cch, Cch, Cch,
                                            0, 0, (long)Cch * Cch, 0, (long)ND * Cch, 0, 1, 0);
    bn1_stats_kernel<<<dim3(12, 8), 256, 0, s0>>>();
    bn1_apply_kernel<<<dim3(12, 8), 128, 0, s0>>>();
    cudaEventRecord(evFv, s0);

    // ---- s2: mask + xnode L1 ----
    cudaStreamWaitEvent(s2, evFv, 0);
    mask_kernel<<<Bb, 256, 0, s2>>>();
    cudaEventRecord(evMask, s2);
    gemm_tc<<<dim3(16, 1, 1), 256, 0, s2>>>(p_fv, p_wnA, nullptr, p_xnode,
                                            Bb * Nn, 2048, Cch, Cch, 2048, 2048,
                                            0, 0, 0, 0, 0, 0, 1, 0);
    cudaEventRecord(evXn1, s2);

    // ---- s0: attn1 ----
    gemm_tc<<<dim3(2, 37, 1), 256, 0, s0>>>(p_h, fam_wq, fam_bq, p_q1, RQ, Hh, Cch,
                                            Cch, Hh, Hh, 0, 0, 0, 0, 0, 0, 1, 0);
    cudaStreamWaitEvent(s0, evK1, 0);
    gemm_tc<<<dim3(1, 1, 96), 256, 0, s0>>>(p_q1, p_k1, nullptr, p_S1, Dd, Dd, Hh,
                                            Hh, Hh, Dd,
                                            (long)8 * Dd * Hh, (long)Dd * Hh,
                                            0, (long)Dd * Hh,
                                            (long)8 * Dd * Dd, (long)Dd * Dd, 8, 1);
    softmaxP_kernel<<<96, 256, 0, s0>>>();
    cudaStreamWaitEvent(s0, evV1, 0);
    gemm_tc<<<dim3(4, 1, 96), 256, 0, s0>>>(p_P, p_v1, nullptr, p_f1, Dd, Cch, 64,
                                            64, Cch, Cch,
                                            (long)8 * Dd * 64, (long)Dd * 64,
                                            0, (long)Dd * Cch,
                                            (long)Dd * Cch, (long)Nn * Dd * Cch, 8, 0);
    cudaEventRecord(evFeat1, s0);

    // ---- s1: Vp + MV Gram ----
    cudaStreamWaitEvent(s1, evFeat1, 0);
    cudaStreamWaitEvent(s1, evWvpB, 0);
    gemm_tc<<<dim3(4, 37, 1), 256, 0, s1>>>(p_f1, p_Wvp, p_bvp, p_Vp, RQ, Cch, Cch,
                                            Cch, Cch, Cch, 0, 0, 0, 0, 0, 0, 1, 0);
    gemm64_kernel<<<dim3(1, 1, 96), 256, 0, s1>>>(p_Vp, p_Vp, nullptr, p_MV,
                                                  Dd, Dd, Cch, Cch, Cch, Dd,
                                                  (long)Dd * Cch, (long)Dd * Cch, (long)Dd * Dd, 1);
    cudaEventRecord(evMV, s1);

    // ---- s0: QK2 -> S -> pg -> zbar -> edge ----
    cudaStreamWaitEvent(s0, evPackQK, 0);
    gemm_tc<<<dim3(4, 37, 1), 256, 0, s0>>>(p_f1, p_wqk, p_bqk, p_QK2, RQ, Cch, Cch,
                                            Cch, Cch, Cch, 0, 0, 0, 0, 0, 0, 1, 0);
    gemm_tc<<<dim3(5, 5, 8), 256, 0, s0>>>(p_QK2, p_QK2 + 256, nullptr, p_S, SQ, SQ, Hh,
                                           Cch, Cch, SQ,
                                           (long)SQ * Cch, 0, (long)SQ * Cch, 0,
                                           (long)SQ * SQ, 0, 1, 1);
    cudaStreamWaitEvent(s0, evMV, 0);
    pg_kernel<<<dim3(Ee, Bb), 256, 0, s0>>>();
    zbar_stats_kernel<<<dim3(Nn, Bb), 512, 0, s0>>>(ep_b);
    cudaStreamWaitEvent(s0, evMask, 0);
    edge_bn_mask_kernel<<<Ee, 128, 0, s0>>>();

    // ---- GNN layer 1 ----
    gemm_tc<<<dim3(4, 9, 1), 256, 0, s0>>>(p_fe, gw[2], nullptr, p_xw,
                                           Bb * Ee, Cch, Cch, Cch, Cch, Cch,
                                           0, 0, 0, 0, 0, 0, 1, 0);
    cudaStreamWaitEvent(s0, evXn1, 0);
    agg_bn_kernel<<<Ee, 128, 0, s0>>>();
    softmax_msg_kernel<<<Bb * Nn, 128, 0, s0>>>();
    node_bn_kernel<<<Nn, 128, 0, s0>>>();
    cudaEventRecord(evNB1, s0);

    // ---- GNN layer 2 ----
    cudaStreamWaitEvent(s1, evNB1, 0);
    gemm_tc<<<dim3(16, 1, 1), 256, 0, s1>>>(p_fv, p_wnB, nullptr, p_xnode,
                                            Bb * Nn, 2048, Cch, Cch, 2048, 2048,
                                            0, 0, 0, 0, 0, 0, 1, 0);
    cudaEventRecord(evXn2, s1);
    gemm_tc<<<dim3(4, 9, 1), 256, 0, s0>>>(p_fe, gw[7], nullptr, p_xw,
                                           Bb * Ee, Cch, Cch, Cch, Cch, Cch,
                                           0, 0, 0, 0, 0, 0, 1, 0);
    cudaStreamWaitEvent(s0, evXn2, 0);
    agg_bn_kernel<<<Ee, 128, 0, s0>>>();
    softmax_msg_kernel<<<Bb * Nn, 128, 0, s0>>>();
    node_bn_kernel<<<Nn, 128, 0, s0>>>();

    cls_kernel<<<Bb * Nn, 128, 0, s0>>>(sc_w, out);
    edgefc_kernel<<<Bb * Ee, 128, 0, s0>>>(efc_w, efc_b, out);
}

// round 7
// speedup vs baseline: 4.8093x; 1.0148x over previous
#include <cuda_runtime.h>
#include <math.h>
#include <stdint.h>

// Problem constants
#define Bb   8
#define Dd   49
#define Cch  512
#define Nn   12
#define Hh   256          // C/2
#define Ee   144          // N*N
#define ND   392          // B*D
#define RQ   4704         // N*B*D
#define SQ   588          // N*D (rows per batch in attn2)
#define SCALE_ 0.0625f    // (C/2)^-0.5
#define EPS_  1e-5f

// ---------------- static device scratch (zero-initialized at load) ----------
__device__ float g_h[RQ * Cch];
__device__ float g_q1[RQ * Hh];
__device__ float g_k1[ND * Hh];
__device__ float g_v1[(ND + 16) * Cch];  // padded rows stay 0 (zero-init)
__device__ float g_S1[96 * Dd * Dd];
__device__ float g_P[96 * Dd * 64];
__device__ float g_feat1[RQ * Cch];      // rows (b*12+n)*49+d  (b-major)
__device__ float g_QK2[RQ * Cch];        // cols 0-255 = Q2, 256-511 = K2
__device__ float g_Vp[RQ * Cch];
__device__ float g_Wvp[Cch * Cch];
__device__ float g_bvp[Cch];
__device__ float g_wqk[Cch * Cch];
__device__ float g_bqk[Cch];
__device__ float g_S[Bb * SQ * SQ];
__device__ float g_MV[Bb * Nn * Dd * Dd];
__device__ float g_w[Bb * Ee * Dd];
__device__ float g_gram[Bb * Ee];
__device__ float g_fv[Bb * Nn * Cch];
__device__ float g_zbar[Bb * Ee * Cch];
__device__ float g_ps1[Bb * Ee];
__device__ float g_ps2[Bb * Ee];
__device__ float g_bn1m[Nn * Cch];
__device__ float g_bn1r[Nn * Cch];
__device__ float g_mask[Bb * Ee];
__device__ float g_fe[Bb * Ee * Cch];
__device__ float g_wnodeA[Cch * 2048];
__device__ float g_wnodeB[Cch * 2048];
__device__ float g_xnode[Bb * Nn * 2048];
__device__ float g_xw[Bb * Ee * Cch];
__device__ float g_msg[Bb * Nn * Cch];

// ---------------- helpers ----------------------------------------------------
__device__ __forceinline__ float block_reduce_sum(float v, float* sm) {
    int lane = threadIdx.x & 31, w = threadIdx.x >> 5;
#pragma unroll
    for (int o = 16; o; o >>= 1) v += __shfl_xor_sync(0xffffffffu, v, o);
    if (lane == 0) sm[w] = v;
    __syncthreads();
    int nw = (blockDim.x + 31) >> 5;
    float r = 0.f;
    if (threadIdx.x < 32) {
        r = (threadIdx.x < nw) ? sm[threadIdx.x] : 0.f;
#pragma unroll
        for (int o = 16; o; o >>= 1) r += __shfl_xor_sync(0xffffffffu, r, o);
        if (threadIdx.x == 0) sm[0] = r;
    }
    __syncthreads();
    r = sm[0];
    __syncthreads();
    return r;
}

__device__ __forceinline__ uint32_t f2tf32(float x) {
    uint32_t r;
    asm("cvt.rna.tf32.f32 %0, %1;" : "=r"(r) : "f"(x));
    return r;
}

__device__ __forceinline__ void mma_tf32(float* c, const uint32_t* a, const uint32_t* b) {
    asm volatile(
        "mma.sync.aligned.m16n8k8.row.col.f32.tf32.tf32.f32 "
        "{%0,%1,%2,%3}, {%4,%5,%6,%7}, {%8,%9}, {%0,%1,%2,%3};"
        : "+f"(c[0]), "+f"(c[1]), "+f"(c[2]), "+f"(c[3])
        : "r"(a[0]), "r"(a[1]), "r"(a[2]), "r"(a[3]), "r"(b[0]), "r"(b[1]));
}

__device__ __forceinline__ float4 f4add(float4 a, float4 b) {
    return make_float4(a.x + b.x, a.y + b.y, a.z + b.z, a.w + b.w);
}

// ---------------- gemm_tc: TF32 tensor-core GEMM, 128x128x16 -----------------
// Smem holds tf32 bits in PAIRED-K layout: element [kp][m] packs (k, k+4) of an
// 8-k block as uint2 -> every fragment load is one LDS.64.
//   kp(k) = (k>>3)*4 + (k&3), half(k) = (k>>2)&1
__global__ __launch_bounds__(256, 2) void gemm_tc(
    const float* __restrict__ A, const float* __restrict__ Bm,
    const float* __restrict__ bias, float* __restrict__ Cm,
    int M, int Np, int K, int lda, int ldb, int ldc,
    long sA1, long sA2, long sB1, long sB2, long sC1, long sC2,
    int zdiv, int transB)
{
    int z = blockIdx.z;
    int zq = z / zdiv, zr = z % zdiv;
    const float* Az = A + zq * sA1 + (long)zr * sA2;
    const float* Bz = Bm + zq * sB1 + (long)zr * sB2;
    float* Cz = Cm + zq * sC1 + (long)zr * sC2;

    __shared__ uint2 As[2][8][132];
    __shared__ uint2 Bs[2][8][132];
    int tid = threadIdx.x;
    int row0 = blockIdx.y * 128, col0 = blockIdx.x * 128;

    int arow = tid >> 1, ak0 = (tid & 1) * 8;   // A / B-NT loader
    int akb  = ak0 >> 1;                        // 0 or 4 (kp base)
    int bkk = tid >> 4, bn0 = (tid & 15) * 8;   // B-NN loader
    int bkp  = (bkk >> 3) * 4 + (bkk & 3);
    int bhalf = (bkk >> 2) & 1;

    int warp = tid >> 5, lane = tid & 31;
    int wm = (warp >> 2) * 64, wn = (warp & 3) * 32;
    int gid = lane >> 2, tig = lane & 3;

    float c[4][4][4];
#pragma unroll
    for (int mi = 0; mi < 4; mi++)
#pragma unroll
        for (int ni = 0; ni < 4; ni++)
#pragma unroll
            for (int q = 0; q < 4; q++) c[mi][ni][q] = 0.f;

    const float4 z4 = {0.f, 0.f, 0.f, 0.f};
    float4 a0g, a1g, b0g, b1g;

#define LOAD_TILE(k0)                                                          \
    {                                                                          \
        int gr = row0 + arow;                                                  \
        if (gr < M) {                                                          \
            const float* p = Az + (long)gr * lda + (k0) + ak0;                 \
            a0g = *(const float4*)p; a1g = *(const float4*)(p + 4);            \
        } else { a0g = z4; a1g = z4; }                                         \
        if (!transB) {                                                         \
            int gc = col0 + bn0;                                               \
            if (gc < Np) {                                                     \
                const float* p = Bz + (long)((k0) + bkk) * ldb + gc;           \
                b0g = *(const float4*)p; b1g = *(const float4*)(p + 4);        \
            } else { b0g = z4; b1g = z4; }                                     \
        } else {                                                               \
            int gn = col0 + arow;                                              \
            if (gn < Np) {                                                     \
                const float* p = Bz + (long)gn * ldb + (k0) + ak0;             \
                b0g = *(const float4*)p; b1g = *(const float4*)(p + 4);        \
            } else { b0g = z4; b1g = z4; }                                     \
        }                                                                      \
    }

// convert + pack pairs (k, k+4) once at store time
#define STORE_TILE(buf)                                                        \
    {                                                                          \
        float av_[8] = {a0g.x,a0g.y,a0g.z,a0g.w,a1g.x,a1g.y,a1g.z,a1g.w};      \
        As[buf][akb+0][arow] = make_uint2(f2tf32(av_[0]), f2tf32(av_[4]));     \
        As[buf][akb+1][arow] = make_uint2(f2tf32(av_[1]), f2tf32(av_[5]));     \
        As[buf][akb+2][arow] = make_uint2(f2tf32(av_[2]), f2tf32(av_[6]));     \
        As[buf][akb+3][arow] = make_uint2(f2tf32(av_[3]), f2tf32(av_[7]));     \
        if (!transB) {                                                         \
            float bv_[8] = {b0g.x,b0g.y,b0g.z,b0g.w,b1g.x,b1g.y,b1g.z,b1g.w};  \
            if (bhalf == 0) {                                                  \
                for (int i_ = 0; i_ < 8; i_++)                                 \
                    Bs[buf][bkp][bn0+i_].x = f2tf32(bv_[i_]);                  \
            } else {                                                           \
                for (int i_ = 0; i_ < 8; i_++)                                 \
                    Bs[buf][bkp][bn0+i_].y = f2tf32(bv_[i_]);                  \
            }                                                                  \
        } else {                                                               \
            float bv_[8] = {b0g.x,b0g.y,b0g.z,b0g.w,b1g.x,b1g.y,b1g.z,b1g.w};  \
            Bs[buf][akb+0][arow] = make_uint2(f2tf32(bv_[0]), f2tf32(bv_[4])); \
            Bs[buf][akb+1][arow] = make_uint2(f2tf32(bv_[1]), f2tf32(bv_[5])); \
            Bs[buf][akb+2][arow] = make_uint2(f2tf32(bv_[2]), f2tf32(bv_[6])); \
            Bs[buf][akb+3][arow] = make_uint2(f2tf32(bv_[3]), f2tf32(bv_[7])); \
        }                                                                      \
    }

    LOAD_TILE(0);
    STORE_TILE(0);
    __syncthreads();

    int nt = K >> 4;
    for (int t = 0; t < nt; t++) {
        int buf = t & 1;
        if (t + 1 < nt) LOAD_TILE((t + 1) << 4);
#pragma unroll
        for (int k8i = 0; k8i < 2; k8i++) {
            int kp = k8i * 4 + tig;
            uint32_t af[4][4], bf[4][2];
#pragma unroll
            for (int mi = 0; mi < 4; mi++) {
                int mb = wm + mi * 16 + gid;
                uint2 ua = As[buf][kp][mb];
                uint2 ub = As[buf][kp][mb + 8];
                af[mi][0] = ua.x; af[mi][2] = ua.y;
                af[mi][1] = ub.x; af[mi][3] = ub.y;
            }
#pragma unroll
            for (int ni = 0; ni < 4; ni++) {
                uint2 v = Bs[buf][kp][wn + ni * 8 + gid];
                bf[ni][0] = v.x; bf[ni][1] = v.y;
            }
#pragma unroll
            for (int mi = 0; mi < 4; mi++)
#pragma unroll
                for (int ni = 0; ni < 4; ni++)
                    mma_tf32(c[mi][ni], af[mi], bf[ni]);
        }
        if (t + 1 < nt) {
            STORE_TILE(buf ^ 1);
            __syncthreads();
        }
    }

#pragma unroll
    for (int mi = 0; mi < 4; mi++) {
        int r0 = row0 + wm + mi * 16 + gid;
        int r1 = r0 + 8;
#pragma unroll
        for (int ni = 0; ni < 4; ni++) {
            int cb = col0 + wn + ni * 8 + 2 * tig;
            float bv0 = 0.f, bv1 = 0.f;
            if (bias) {
                if (cb < Np) bv0 = bias[cb];
                if (cb + 1 < Np) bv1 = bias[cb + 1];
            }
            if (r0 < M) {
                if (cb < Np)     Cz[(long)r0 * ldc + cb]     = c[mi][ni][0] + bv0;
                if (cb + 1 < Np) Cz[(long)r0 * ldc + cb + 1] = c[mi][ni][1] + bv1;
            }
            if (r1 < M) {
                if (cb < Np)     Cz[(long)r1 * ldc + cb]     = c[mi][ni][2] + bv0;
                if (cb + 1 < Np) Cz[(long)r1 * ldc + cb + 1] = c[mi][ni][3] + bv1;
            }
        }
    }
#undef LOAD_TILE
#undef STORE_TILE
}

// ---------------- gemm64 (fp32, kept only for the MV Gram) -------------------
__global__ __launch_bounds__(256) void gemm64_kernel(
    const float* __restrict__ A, const float* __restrict__ Bm,
    const float* __restrict__ bias, float* __restrict__ Cm,
    int M, int Np, int K, int lda, int ldb, int ldc,
    long sA, long sB, long sC, int transB)
{
    const float* Az = A + (long)blockIdx.z * sA;
    const float* Bz = Bm + (long)blockIdx.z * sB;
    float* Cz = Cm + (long)blockIdx.z * sC;
    __shared__ float As[16][64];
    __shared__ float Bs[16][64];
    int tid = threadIdx.x;
    int tx = tid & 15, ty = tid >> 4;
    int row0 = blockIdx.y * 64, col0 = blockIdx.x * 64;
    int lr = tid >> 2, lk = (tid & 3) * 4;
    int bkk = tid >> 4, bn = (tid & 15) * 4;
    const float4 z4 = {0.f, 0.f, 0.f, 0.f};
    float acc[4][4];
#pragma unroll
    for (int i = 0; i < 4; i++)
#pragma unroll
        for (int j = 0; j < 4; j++) acc[i][j] = 0.f;

    for (int k0 = 0; k0 < K; k0 += 16) {
        float4 av = z4, bv = z4;
        if (row0 + lr < M) av = *(const float4*)(Az + (long)(row0 + lr) * lda + k0 + lk);
        if (!transB) {
            if (col0 + bn < Np) bv = *(const float4*)(Bz + (long)(k0 + bkk) * ldb + col0 + bn);
        } else {
            if (col0 + lr < Np) bv = *(const float4*)(Bz + (long)(col0 + lr) * ldb + k0 + lk);
        }
        __syncthreads();
        As[lk+0][lr]=av.x; As[lk+1][lr]=av.y; As[lk+2][lr]=av.z; As[lk+3][lr]=av.w;
        if (!transB) {
            *(float4*)&Bs[bkk][bn] = bv;
        } else {
            Bs[lk+0][lr]=bv.x; Bs[lk+1][lr]=bv.y; Bs[lk+2][lr]=bv.z; Bs[lk+3][lr]=bv.w;
        }
        __syncthreads();
#pragma unroll
        for (int kk = 0; kk < 16; kk++) {
            float4 a4 = *(const float4*)&As[kk][ty * 4];
            float4 b4 = *(const float4*)&Bs[kk][tx * 4];
            float a[4] = {a4.x, a4.y, a4.z, a4.w};
            float b[4] = {b4.x, b4.y, b4.z, b4.w};
#pragma unroll
            for (int i = 0; i < 4; i++)
#pragma unroll
                for (int j = 0; j < 4; j++) acc[i][j] += a[i] * b[j];
        }
    }
#pragma unroll
    for (int i = 0; i < 4; i++) {
        int gr = row0 + ty * 4 + i;
        if (gr >= M) continue;
#pragma unroll
        for (int j = 0; j < 4; j++) {
            int gc = col0 + tx * 4 + j;
            if (gc < Np)
                Cz[(long)gr * ldc + gc] = acc[i][j] + (bias ? bias[gc] : 0.f);
        }
    }
}

// ---------------- weight packers ---------------------------------------------
__global__ void pack_qk_kernel(const float* __restrict__ wq, const float* __restrict__ wk,
                               const float* __restrict__ bq, const float* __restrict__ bk) {
    int idx = blockIdx.x * 256 + threadIdx.x;
    int k = idx >> 9, c = idx & 511;
    g_wqk[idx] = (c < 256) ? wq[k * 256 + c] : wk[k * 256 + c - 256];
    if (idx < 512) g_bqk[idx] = (idx < 256) ? bq[idx] : bk[idx - 256];
}

__global__ void pack_node_kernel(const float* __restrict__ wa, const float* __restrict__ wb,
                                 const float* __restrict__ wu, const float* __restrict__ wv,
                                 float* __restrict__ dst) {
    int idx = blockIdx.x * 256 + threadIdx.x;
    int k = idx >> 11, c = idx & 2047;
    const float* src = (c < 512) ? wa : (c < 1024) ? wb : (c < 1536) ? wu : wv;
    dst[idx] = src[k * 512 + (c & 511)];
}

// ---------------- BN1 ---------------------------------------------------------
__global__ void bn1_stats_kernel() {
    int n = blockIdx.x;
    int cl = threadIdx.x & 63;
    int q = threadIdx.x >> 6;
    int c = blockIdx.y * 64 + cl;
    float s1 = 0.f, s2 = 0.f;
    const float* base = g_h + (long)n * ND * Cch + c;
    for (int r = q; r < ND; r += 4) {
        float v = base[(long)r * Cch];
        s1 += v; s2 += v * v;
    }
    __shared__ float sm1[4][64], sm2[4][64];
    sm1[q][cl] = s1; sm2[q][cl] = s2;
    __syncthreads();
    if (q == 0) {
        s1 = sm1[0][cl] + sm1[1][cl] + sm1[2][cl] + sm1[3][cl];
        s2 = sm2[0][cl] + sm2[1][cl] + sm2[2][cl] + sm2[3][cl];
        float m = s1 / (float)ND;
        float var = s2 / (float)ND - m * m;
        g_bn1m[n * Cch + c] = m;
        g_bn1r[n * Cch + c] = rsqrtf(fmaxf(var, 0.f) + EPS_);
    }
}

__global__ void bn1_apply_kernel() {
    int n = blockIdx.x, b = blockIdx.y;
    int c4 = threadIdx.x;
    float4 m = ((const float4*)(g_bn1m + n * Cch))[c4];
    float4 r = ((const float4*)(g_bn1r + n * Cch))[c4];
    float4* hb = (float4*)(g_h + ((long)(n * Bb + b) * Dd) * Cch) + c4;
    float4 acc = {0.f, 0.f, 0.f, 0.f};
    for (int d = 0; d < Dd; d++) {
        float4 h = hb[(long)d * 128];
        float4 u;
        u.x = fmaxf((h.x - m.x) * r.x, 0.f);
        u.y = fmaxf((h.y - m.y) * r.y, 0.f);
        u.z = fmaxf((h.z - m.z) * r.z, 0.f);
        u.w = fmaxf((h.w - m.w) * r.w, 0.f);
        hb[(long)d * 128] = u;
        acc = f4add(acc, u);
    }
    float inv = 1.f / (float)Dd;
    acc.x *= inv; acc.y *= inv; acc.z *= inv; acc.w *= inv;
    ((float4*)(g_fv + (long)(b * Nn + n) * Cch))[c4] = acc;
}

// ---------------- attn1 softmax ----------------------------------------------
__global__ void softmaxP_kernel() {
    int z = blockIdx.x;
    int tid = threadIdx.x, w = tid >> 5, lane = tid & 31;
    const float* Sb = g_S1 + (long)z * Dd * Dd;
    float* Pb = g_P + (long)z * Dd * 64;
    for (int r = w; r < Dd; r += 8) {
        float v0 = (lane < Dd) ? Sb[r * Dd + lane] * SCALE_ : -1e30f;
        float v1 = (lane + 32 < Dd) ? Sb[r * Dd + lane + 32] * SCALE_ : -1e30f;
        float mx = fmaxf(v0, v1);
#pragma unroll
        for (int o = 16; o; o >>= 1) mx = fmaxf(mx, __shfl_xor_sync(0xffffffffu, mx, o));
        float e0 = (lane < Dd) ? expf(v0 - mx) : 0.f;
        float e1 = (lane + 32 < Dd) ? expf(v1 - mx) : 0.f;
        float s = e0 + e1;
#pragma unroll
        for (int o = 16; o; o >>= 1) s += __shfl_xor_sync(0xffffffffu, s, o);
        float inv = 1.f / s;
        if (lane < Dd) Pb[r * 64 + lane] = e0 * inv;
        Pb[r * 64 + lane + 32] = (lane + 32 < Dd) ? e1 * inv : 0.f;
    }
}

__global__ void bvp_kernel(const float* __restrict__ bv, const float* __restrict__ epw) {
    int c = threadIdx.x;
    float s = 0.f;
    for (int k = 0; k < Cch; k++) s += bv[k] * epw[k * Cch + c];
    g_bvp[c] = s;
}

// ---------------- attn2: per-(b,e) softmax + agg weights + Gram term ----------
__global__ void pg_kernel() {
    int e = blockIdx.x, b = blockIdx.y;
    int i = e / Nn, j = e % Nn;
    __shared__ float P[49][50];
    __shared__ float MVs[Dd * Dd];
    __shared__ float gpart[8];
    int tid = threadIdx.x, w = tid >> 5, lane = tid & 31;
    const float* MVg = g_MV + (long)(b * Nn + i) * (Dd * Dd);
    for (int t = tid; t < Dd * Dd; t += 256) MVs[t] = MVg[t];
    const float* Sb = g_S + (long)b * SQ * SQ + (long)(j * Dd) * SQ + i * Dd;
    for (int r = w; r < Dd; r += 8) {
        float v0 = (lane < Dd) ? Sb[r * SQ + lane] * SCALE_ : -1e30f;
        float v1 = (lane + 32 < Dd) ? Sb[r * SQ + lane + 32] * SCALE_ : -1e30f;
        float mx = fmaxf(v0, v1);
#pragma unroll
        for (int o = 16; o; o >>= 1) mx = fmaxf(mx, __shfl_xor_sync(0xffffffffu, mx, o));
        float e0 = (lane < Dd) ? expf(v0 - mx) : 0.f;
        float e1 = (lane + 32 < Dd) ? expf(v1 - mx) : 0.f;
        float s = e0 + e1;
#pragma unroll
        for (int o = 16; o; o >>= 1) s += __shfl_xor_sync(0xffffffffu, s, o);
        float inv = 1.f / s;
        if (lane < Dd) P[r][lane] = e0 * inv;
        if (lane + 32 < Dd) P[r][lane + 32] = e1 * inv;
    }
    __syncthreads();
    if (tid < Dd) {
        float s = 0.f;
        for (int r = 0; r < Dd; r++) s += P[r][tid];
        g_w[((long)b * Ee + e) * Dd + tid] = s * (1.f / (float)Dd);
    }
    float acc = 0.f;
    for (int r = w; r < Dd; r += 8) {
        float t0 = 0.f, t1 = 0.f;
        for (int bbk = 0; bbk < Dd; bbk++) {
            float p = P[r][bbk];
            t0 += MVs[lane * Dd + bbk] * p;
            if (lane + 32 < Dd) t1 += MVs[(lane + 32) * Dd + bbk] * p;
        }
        acc += P[r][lane] * t0;
        if (lane + 32 < Dd) acc += P[r][lane + 32] * t1;
    }
#pragma unroll
    for (int o = 16; o; o >>= 1) acc += __shfl_xor_sync(0xffffffffu, acc, o);
    if (lane == 0) gpart[w] = acc;
    __syncthreads();
    if (tid == 0) {
        float s = 0.f;
        for (int q = 0; q < 8; q++) s += gpart[q];
        g_gram[b * Ee + e] = s;
    }
}

// zbar = w^T Vp + epb ; stats via Gram identity. grid (12,8)=(i,b), block 512.
__global__ void zbar_stats_kernel(const float* __restrict__ ep_b) {
    int i = blockIdx.x, b = blockIdx.y;
    __shared__ float ws[Nn * Dd];
    __shared__ float red[16][26];
    int tid = threadIdx.x, lane = tid & 31, w = tid >> 5;
    for (int t = tid; t < Nn * Dd; t += 512) {
        int j = t / Dd, d2 = t % Dd;
        ws[t] = g_w[((long)b * Ee + i * Nn + j) * Dd + d2];
    }
    __syncthreads();
    float acc[Nn];
#pragma unroll
    for (int j = 0; j < Nn; j++) acc[j] = 0.f;
    const float* Vb = g_Vp + (long)((b * Nn + i) * Dd) * Cch;
    for (int d2 = 0; d2 < Dd; d2++) {
        float v = Vb[(long)d2 * Cch + tid];
#pragma unroll
        for (int j = 0; j < Nn; j++) acc[j] += ws[j * Dd + d2] * v;
    }
    float eb = ep_b[tid];
    float loc[25];
#pragma unroll
    for (int j = 0; j < Nn; j++) {
        float z = acc[j] + eb;
        g_zbar[((long)b * Ee + i * Nn + j) * Cch + tid] = z;
        loc[j] = z;
        loc[Nn + j] = eb * z;
    }
    loc[24] = eb * eb;
#pragma unroll
    for (int k = 0; k < 25; k++) {
        float v = loc[k];
#pragma unroll
        for (int o = 16; o; o >>= 1) v += __shfl_xor_sync(0xffffffffu, v, o);
        if (lane == 0) red[w][k] = v;
    }
    __syncthreads();
    if (tid < Nn) {
        float S = 0.f, T = 0.f, E = 0.f;
#pragma unroll
        for (int q = 0; q < 16; q++) {
            S += red[q][tid]; T += red[q][Nn + tid]; E += red[q][24];
        }
        int e = i * Nn + tid;
        g_ps1[b * Ee + e] = 49.f * S;
        g_ps2[b * Ee + e] = g_gram[b * Ee + e] + 98.f * T - 49.f * E;
    }
}

// ---------------- cosine adjacency mask --------------------------------------
__global__ void mask_kernel() {
    int b = blockIdx.x;
    __shared__ float sinv[Nn];
    __shared__ float adj[Ee];
    __shared__ float dis[Nn];
    int tid = threadIdx.x, w = tid >> 5, lane = tid & 31;
    for (int n = w; n < Nn; n += 8) {
        const float4* f = (const float4*)(g_fv + (long)(b * Nn + n) * Cch);
        float s = 0.f;
        for (int t = lane; t < 128; t += 32) {
            float4 x = f[t];
            s += x.x * x.x + x.y * x.y + x.z * x.z + x.w * x.w;
        }
#pragma unroll
        for (int o = 16; o; o >>= 1) s += __shfl_xor_sync(0xffffffffu, s, o);
        if (lane == 0) sinv[n] = 1.f / fmaxf(sqrtf(s), 1e-12f);
    }
    __syncthreads();
    for (int e = w; e < Ee; e += 8) {
        int i = e / Nn, jn = e % Nn;
        const float4* fi = (const float4*)(g_fv + (long)(b * Nn + i) * Cch);
        const float4* fj = (const float4*)(g_fv + (long)(b * Nn + jn) * Cch);
        float s = 0.f;
        for (int t = lane; t < 128; t += 32) {
            float4 a = fi[t], c = fj[t];
            s += a.x * c.x + a.y * c.y + a.z * c.z + a.w * c.w;
        }
#pragma unroll
        for (int o = 16; o; o >>= 1) s += __shfl_xor_sync(0xffffffffu, s, o);
        if (lane == 0) adj[e] = s * sinv[i] * sinv[jn];
    }
    __syncthreads();
    if (tid < Nn) {
        float s = 0.f;
        for (int jn = 0; jn < Nn; jn++) s += adj[tid * Nn + jn];
        dis[tid] = rsqrtf(s);
    }
    __syncthreads();
    if (tid < Ee) {
        int i = tid / Nn, jn = tid % Nn;
        g_mask[b * Ee + tid] = adj[tid] * dis[i] * dis[jn];
    }
}

// ---------------- edge BN + mask ---------------------------------------------
__global__ void edge_bn_mask_kernel() {
    int e = blockIdx.x;
    __shared__ float mrs[2];
    int tid = threadIdx.x;
    if (tid == 0) {
        float s1 = 0.f, s2 = 0.f;
        for (int b = 0; b < Bb; b++) { s1 += g_ps1[b * Ee + e]; s2 += g_ps2[b * Ee + e]; }
        float cnt = (float)(Bb * Dd * Cch);
        float m = s1 / cnt;
        float v = s2 / cnt - m * m;
        mrs[0] = m;
        mrs[1] = rsqrtf(fmaxf(v, 0.f) + EPS_);
    }
    __syncthreads();
    float m = mrs[0], r = mrs[1];
    for (int b = 0; b < Bb; b++) {
        float mk = g_mask[b * Ee + e] * r;
        const float4* zb = (const float4*)(g_zbar + (long)(b * Ee + e) * Cch);
        float4* fe = (float4*)(g_fe + (long)(b * Ee + e) * Cch);
        float4 z = zb[tid];
        fe[tid] = make_float4((z.x - m) * mk, (z.y - m) * mk, (z.z - m) * mk, (z.w - m) * mk);
    }
}

// ---------------- GNN layer pieces -------------------------------------------
__global__ void agg_bn_kernel() {
    int e = blockIdx.x;
    int i = e / Nn, jn = e % Nn;
    __shared__ float sm[32];
    int tid = threadIdx.x;
    float4 agg[Bb];
    float s1 = 0.f, s2 = 0.f;
#pragma unroll
    for (int b = 0; b < Bb; b++) {
        float4 va = ((const float4*)(g_xnode + (long)(b * Nn + i) * 2048))[tid];
        float4 vb = ((const float4*)(g_xnode + (long)(b * Nn + jn) * 2048 + 512))[tid];
        float4 vw = ((const float4*)(g_xw + (long)(b * Ee + e) * Cch))[tid];
        float4 v = f4add(f4add(va, vb), vw);
        agg[b] = v;
        s1 += v.x + v.y + v.z + v.w;
        s2 += v.x * v.x + v.y * v.y + v.z * v.z + v.w * v.w;
    }
    s1 = block_reduce_sum(s1, sm);
    s2 = block_reduce_sum(s2, sm);
    float cnt = (float)(Bb * Cch);
    float m = s1 / cnt;
    float r = rsqrtf(fmaxf(s2 / cnt - m * m, 0.f) + EPS_);
#pragma unroll
    for (int b = 0; b < Bb; b++) {
        float4* fe = (float4*)(g_fe + (long)(b * Ee + e) * Cch);
        float4 f = fe[tid], v = agg[b];
        f.x += fmaxf((v.x - m) * r, 0.f);
        f.y += fmaxf((v.y - m) * r, 0.f);
        f.z += fmaxf((v.z - m) * r, 0.f);
        f.w += fmaxf((v.w - m) * r, 0.f);
        fe[tid] = f;
    }
}

__global__ void softmax_msg_kernel() {
    int bi = blockIdx.x;
    int b = bi / Nn, i = bi % Nn;
    int tid = threadIdx.x;
    float4 v[Nn];
    float4 mx = {-1e30f, -1e30f, -1e30f, -1e30f};
#pragma unroll
    for (int jn = 0; jn < Nn; jn++) {
        float4 ed = ((const float4*)(g_fe + (long)(b * Ee + i * Nn + jn) * Cch))[tid];
        float4 s;
        s.x = 1.f / (1.f + expf(-ed.x));
        s.y = 1.f / (1.f + expf(-ed.y));
        s.z = 1.f / (1.f + expf(-ed.z));
        s.w = 1.f / (1.f + expf(-ed.w));
        v[jn] = s;
        mx.x = fmaxf(mx.x, s.x); mx.y = fmaxf(mx.y, s.y);
        mx.z = fmaxf(mx.z, s.z); mx.w = fmaxf(mx.w, s.w);
    }
    float4 sum = {0.f, 0.f, 0.f, 0.f};
#pragma unroll
    for (int jn = 0; jn < Nn; jn++) {
        v[jn].x = expf(v[jn].x - mx.x); v[jn].y = expf(v[jn].y - mx.y);
        v[jn].z = expf(v[jn].z - mx.z); v[jn].w = expf(v[jn].w - mx.w);
        sum = f4add(sum, v[jn]);
    }
    float4 acc = {0.f, 0.f, 0.f, 0.f};
#pragma unroll
    for (int jn = 0; jn < Nn; jn++) {
        float4 u = ((const float4*)(g_xnode + (long)(b * Nn + jn) * 2048 + 1536))[tid];
        acc.x += v[jn].x * u.x; acc.y += v[jn].y * u.y;
        acc.z += v[jn].z * u.z; acc.w += v[jn].w * u.w;
    }
    float4 o;
    o.x = acc.x / (sum.x * (float)Nn); o.y = acc.y / (sum.y * (float)Nn);
    o.z = acc.z / (sum.z * (float)Nn); o.w = acc.w / (sum.w * (float)Nn);
    ((float4*)(g_msg + (long)(b * Nn + i) * Cch))[tid] = o;
}

__global__ void node_bn_kernel() {
    int n = blockIdx.x;
    __shared__ float sm[32];
    int tid = threadIdx.x;
    float4 t[Bb];
    float s1 = 0.f, s2 = 0.f;
#pragma unroll
    for (int b = 0; b < Bb; b++) {
        float4 xu = ((const float4*)(g_xnode + (long)(b * Nn + n) * 2048 + 1024))[tid];
        float4 ms = ((const float4*)(g_msg + (long)(b * Nn + n) * Cch))[tid];
        float4 v = f4add(xu, ms);
        t[b] = v;
        s1 += v.x + v.y + v.z + v.w;
        s2 += v.x * v.x + v.y * v.y + v.z * v.z + v.w * v.w;
    }
    s1 = block_reduce_sum(s1, sm);
    s2 = block_reduce_sum(s2, sm);
    float cnt = (float)(Bb * Cch);
    float m = s1 / cnt;
    float r = rsqrtf(fmaxf(s2 / cnt - m * m, 0.f) + EPS_);
#pragma unroll
    for (int b = 0; b < Bb; b++) {
        float4* fv = (float4*)(g_fv + (long)(b * Nn + n) * Cch);
        float4 f = fv[tid], v = t[b];
        f.x = fmaxf(f.x + (v.x - m) * r, 0.f);
        f.y = fmaxf(f.y + (v.y - m) * r, 0.f);
        f.z = fmaxf(f.z + (v.z - m) * r, 0.f);
        f.w = fmaxf(f.w + (v.w - m) * r, 0.f);
        fv[tid] = f;
    }
}

// ---------------- classifier heads -------------------------------------------
__global__ void cls_kernel(const float* __restrict__ sc_w, float* __restrict__ out) {
    int bn = blockIdx.x;
    int n = bn % Nn;
    __shared__ float sm[32];
    int tid = threadIdx.x;
    float sf = 0.f, ff = 0.f, ss = 0.f;
    for (int c = tid; c < Cch; c += 128) {
        float f = g_fv[(long)bn * Cch + c];
        float s = fmaxf(sc_w[n * Cch + c], 0.f);
        sf += f * s; ff += f * f; ss += s * s;
    }
    sf = block_reduce_sum(sf, sm);
    ff = block_reduce_sum(ff, sm);
    ss = block_reduce_sum(ss, sm);
    if (tid == 0)
        out[bn] = sf / (fmaxf(sqrtf(ff), 1e-12f) * fmaxf(sqrtf(ss), 1e-12f));
}

__global__ void edgefc_kernel(const float* __restrict__ w, const float* __restrict__ bias,
                              float* __restrict__ out) {
    int row = blockIdx.x;
    int tid = threadIdx.x;
    int k = tid >> 5, lane = tid & 31;
    const float* f = g_fe + (long)row * Cch;
    float dot = 0.f;
    for (int c = lane; c < Cch; c += 32) dot += f[c] * w[c * 4 + k];
#pragma unroll
    for (int o = 16; o; o >>= 1) dot += __shfl_xor_sync(0xffffffffu, dot, o);
    if (lane == 0) out[96 + row * 4 + k] = dot + bias[k];
}

// ---------------- host driver -------------------------------------------------
extern "C" void kernel_launch(void* const* d_in, const int* in_sizes, int n_in,
                              void* d_out, int out_size) {
    const float* x      = (const float*)d_in[0];
    const float* Wc     = (const float*)d_in[1];
    const float* fam_wq = (const float*)d_in[3];
    const float* fam_bq = (const float*)d_in[4];
    const float* fam_wk = (const float*)d_in[5];
    const float* fam_wv = (const float*)d_in[7];
    const float* fam_bv = (const float*)d_in[8];
    const float* arm_wq = (const float*)d_in[9];
    const float* arm_bq = (const float*)d_in[10];
    const float* arm_wk = (const float*)d_in[11];
    const float* arm_bk = (const float*)d_in[12];
    const float* arm_wv = (const float*)d_in[13];
    const float* arm_bv = (const float*)d_in[14];
    const float* ep_w   = (const float*)d_in[15];
    const float* ep_b   = (const float*)d_in[16];
    const float* gw[10];
    for (int t = 0; t < 10; t++) gw[t] = (const float*)d_in[17 + t];
    const float* sc_w   = (const float*)d_in[27];
    const float* efc_w  = (const float*)d_in[28];
    const float* efc_b  = (const float*)d_in[29];
    float* out = (float*)d_out;

    float *p_h, *p_q1, *p_k1, *p_v1, *p_S1, *p_P, *p_f1, *p_QK2, *p_Vp, *p_Wvp, *p_bvp;
    float *p_wqk, *p_bqk, *p_S, *p_MV, *p_fv, *p_fe, *p_wnA, *p_wnB, *p_xnode, *p_xw;
    cudaGetSymbolAddress((void**)&p_h, g_h);
    cudaGetSymbolAddress((void**)&p_q1, g_q1);
    cudaGetSymbolAddress((void**)&p_k1, g_k1);
    cudaGetSymbolAddress((void**)&p_v1, g_v1);
    cudaGetSymbolAddress((void**)&p_S1, g_S1);
    cudaGetSymbolAddress((void**)&p_P, g_P);
    cudaGetSymbolAddress((void**)&p_f1, g_feat1);
    cudaGetSymbolAddress((void**)&p_QK2, g_QK2);
    cudaGetSymbolAddress((void**)&p_Vp, g_Vp);
    cudaGetSymbolAddress((void**)&p_Wvp, g_Wvp);
    cudaGetSymbolAddress((void**)&p_bvp, g_bvp);
    cudaGetSymbolAddress((void**)&p_wqk, g_wqk);
    cudaGetSymbolAddress((void**)&p_bqk, g_bqk);
    cudaGetSymbolAddress((void**)&p_S, g_S);
    cudaGetSymbolAddress((void**)&p_MV, g_MV);
    cudaGetSymbolAddress((void**)&p_fv, g_fv);
    cudaGetSymbolAddress((void**)&p_fe, g_fe);
    cudaGetSymbolAddress((void**)&p_wnA, g_wnodeA);
    cudaGetSymbolAddress((void**)&p_wnB, g_wnodeB);
    cudaGetSymbolAddress((void**)&p_xnode, g_xnode);
    cudaGetSymbolAddress((void**)&p_xw, g_xw);

    static cudaStream_t s1 = nullptr, s2 = nullptr;
    static cudaEvent_t evRoot, evPackQK, evK1, evV1, evWvpB, evFv, evFeat1,
                       evMV, evMask, evXn1, evNB1, evXn2;
    if (!s1) {
        cudaStreamCreateWithFlags(&s1, cudaStreamNonBlocking);
        cudaStreamCreateWithFlags(&s2, cudaStreamNonBlocking);
        cudaEventCreateWithFlags(&evRoot, cudaEventDisableTiming);
        cudaEventCreateWithFlags(&evPackQK, cudaEventDisableTiming);
        cudaEventCreateWithFlags(&evK1, cudaEventDisableTiming);
        cudaEventCreateWithFlags(&evV1, cudaEventDisableTiming);
        cudaEventCreateWithFlags(&evWvpB, cudaEventDisableTiming);
        cudaEventCreateWithFlags(&evFv, cudaEventDisableTiming);
        cudaEventCreateWithFlags(&evFeat1, cudaEventDisableTiming);
        cudaEventCreateWithFlags(&evMV, cudaEventDisableTiming);
        cudaEventCreateWithFlags(&evMask, cudaEventDisableTiming);
        cudaEventCreateWithFlags(&evXn1, cudaEventDisableTiming);
        cudaEventCreateWithFlags(&evNB1, cudaEventDisableTiming);
        cudaEventCreateWithFlags(&evXn2, cudaEventDisableTiming);
    }
    cudaStream_t s0 = 0;

    cudaEventRecord(evRoot, s0);

    // ---- s1: packing + K/V projections of attn1 ----
    cudaStreamWaitEvent(s1, evRoot, 0);
    pack_qk_kernel<<<1024, 256, 0, s1>>>(arm_wq, arm_wk, arm_bq, arm_bk);
    cudaEventRecord(evPackQK, s1);
    gemm_tc<<<dim3(2, 4, 1), 256, 0, s1>>>(x, fam_wk, nullptr, p_k1, ND, Hh, Cch,
                                           Cch, Hh, Hh, 0, 0, 0, 0, 0, 0, 1, 0);
    cudaEventRecord(evK1, s1);
    gemm_tc<<<dim3(4, 4, 1), 256, 0, s1>>>(x, fam_wv, fam_bv, p_v1, ND, Cch, Cch,
                                           Cch, Cch, Cch, 0, 0, 0, 0, 0, 0, 1, 0);
    cudaEventRecord(evV1, s1);

    // ---- s2: Wvp/bvp + node-weight packs ----
    cudaStreamWaitEvent(s2, evRoot, 0);
    gemm_tc<<<dim3(4, 4, 1), 256, 0, s2>>>(arm_wv, ep_w, nullptr, p_Wvp, Cch, Cch, Cch,
                                           Cch, Cch, Cch, 0, 0, 0, 0, 0, 0, 1, 0);
    bvp_kernel<<<1, 512, 0, s2>>>(arm_bv, ep_w);
    cudaEventRecord(evWvpB, s2);
    pack_node_kernel<<<4096, 256, 0, s2>>>(gw[0], gw[1], gw[3], gw[4], p_wnA);
    pack_node_kernel<<<4096, 256, 0, s2>>>(gw[5], gw[6], gw[8], gw[9], p_wnB);

    // ---- s0 main chain: h -> BN1 ----
    gemm_tc<<<dim3(4, 4, 12), 256, 0, s0>>>(x, Wc, nullptr, p_h, ND, Cch, Cch,
                                            Cch, Cch, Cch,
                                            0, 0, (long)Cch * Cch, 0, (long)ND * Cch, 0, 1, 0);
    bn1_stats_kernel<<<dim3(12, 8), 256, 0, s0>>>();
    bn1_apply_kernel<<<dim3(12, 8), 128, 0, s0>>>();
    cudaEventRecord(evFv, s0);

    // ---- s2: mask + xnode L1 ----
    cudaStreamWaitEvent(s2, evFv, 0);
    mask_kernel<<<Bb, 256, 0, s2>>>();
    cudaEventRecord(evMask, s2);
    gemm_tc<<<dim3(16, 1, 1), 256, 0, s2>>>(p_fv, p_wnA, nullptr, p_xnode,
                                            Bb * Nn, 2048, Cch, Cch, 2048, 2048,
                                            0, 0, 0, 0, 0, 0, 1, 0);
    cudaEventRecord(evXn1, s2);

    // ---- s0: attn1 ----
    gemm_tc<<<dim3(2, 37, 1), 256, 0, s0>>>(p_h, fam_wq, fam_bq, p_q1, RQ, Hh, Cch,
                                            Cch, Hh, Hh, 0, 0, 0, 0, 0, 0, 1, 0);
    cudaStreamWaitEvent(s0, evK1, 0);
    gemm_tc<<<dim3(1, 1, 96), 256, 0, s0>>>(p_q1, p_k1, nullptr, p_S1, Dd, Dd, Hh,
                                            Hh, Hh, Dd,
                                            (long)8 * Dd * Hh, (long)Dd * Hh,
                                            0, (long)Dd * Hh,
                                            (long)8 * Dd * Dd, (long)Dd * Dd, 8, 1);
    softmaxP_kernel<<<96, 256, 0, s0>>>();
    cudaStreamWaitEvent(s0, evV1, 0);
    gemm_tc<<<dim3(4, 1, 96), 256, 0, s0>>>(p_P, p_v1, nullptr, p_f1, Dd, Cch, 64,
                                            64, Cch, Cch,
                                            (long)8 * Dd * 64, (long)Dd * 64,
                                            0, (long)Dd * Cch,
                                            (long)Dd * Cch, (long)Nn * Dd * Cch, 8, 0);
    cudaEventRecord(evFeat1, s0);

    // ---- s1: Vp + MV Gram ----
    cudaStreamWaitEvent(s1, evFeat1, 0);
    cudaStreamWaitEvent(s1, evWvpB, 0);
    gemm_tc<<<dim3(4, 37, 1), 256, 0, s1>>>(p_f1, p_Wvp, p_bvp, p_Vp, RQ, Cch, Cch,
                                            Cch, Cch, Cch, 0, 0, 0, 0, 0, 0, 1, 0);
    gemm64_kernel<<<dim3(1, 1, 96), 256, 0, s1>>>(p_Vp, p_Vp, nullptr, p_MV,
                                                  Dd, Dd, Cch, Cch, Cch, Dd,
                                                  (long)Dd * Cch, (long)Dd * Cch, (long)Dd * Dd, 1);
    cudaEventRecord(evMV, s1);

    // ---- s0: QK2 -> S -> pg -> zbar -> edge ----
    cudaStreamWaitEvent(s0, evPackQK, 0);
    gemm_tc<<<dim3(4, 37, 1), 256, 0, s0>>>(p_f1, p_wqk, p_bqk, p_QK2, RQ, Cch, Cch,
                                            Cch, Cch, Cch, 0, 0, 0, 0, 0, 0, 1, 0);
    gemm_tc<<<dim3(5, 5, 8), 256, 0, s0>>>(p_QK2, p_QK2 + 256, nullptr, p_S, SQ, SQ, Hh,
                                           Cch, Cch, SQ,
                                           (long)SQ * Cch, 0, (long)SQ * Cch, 0,
                                           (long)SQ * SQ, 0, 1, 1);
    cudaStreamWaitEvent(s0, evMV, 0);
    pg_kernel<<<dim3(Ee, Bb), 256, 0, s0>>>();
    zbar_stats_kernel<<<dim3(Nn, Bb), 512, 0, s0>>>(ep_b);
    cudaStreamWaitEvent(s0, evMask, 0);
    edge_bn_mask_kernel<<<Ee, 128, 0, s0>>>();

    // ---- GNN layer 1 ----
    gemm_tc<<<dim3(4, 9, 1), 256, 0, s0>>>(p_fe, gw[2], nullptr, p_xw,
                                           Bb * Ee, Cch, Cch, Cch, Cch, Cch,
                                           0, 0, 0, 0, 0, 0, 1, 0);
    cudaStreamWaitEvent(s0, evXn1, 0);
    agg_bn_kernel<<<Ee, 128, 0, s0>>>();
    softmax_msg_kernel<<<Bb * Nn, 128, 0, s0>>>();
    node_bn_kernel<<<Nn, 128, 0, s0>>>();
    cudaEventRecord(evNB1, s0);

    // ---- GNN layer 2 ----
    cudaStreamWaitEvent(s1, evNB1, 0);
    gemm_tc<<<dim3(16, 1, 1), 256, 0, s1>>>(p_fv, p_wnB, nullptr, p_xnode,
                                            Bb * Nn, 2048, Cch, Cch, 2048, 2048,
                                            0, 0, 0, 0, 0, 0, 1, 0);
    cudaEventRecord(evXn2, s1);
    gemm_tc<<<dim3(4, 9, 1), 256, 0, s0>>>(p_fe, gw[7], nullptr, p_xw,
                                           Bb * Ee, Cch, Cch, Cch, Cch, Cch,
                                           0, 0, 0, 0, 0, 0, 1, 0);
    cudaStreamWaitEvent(s0, evXn2, 0);
    agg_bn_kernel<<<Ee, 128, 0, s0>>>();
    softmax_msg_kernel<<<Bb * Nn, 128, 0, s0>>>();
    node_bn_kernel<<<Nn, 128, 0, s0>>>();

    cls_kernel<<<Bb * Nn, 128, 0, s0>>>(sc_w, out);
    edgefc_kernel<<<Bb * Ee, 128, 0, s0>>>(efc_w, efc_b, out);
}

// round 11
// speedup vs baseline: 5.1402x; 1.0688x over previous
#include <cuda_runtime.h>
#include <math.h>
#include <stdint.h>

// Problem constants
#define Bb   8
#define Dd   49
#define Cch  512
#define Nn   12
#define Hh   256          // C/2
#define Ee   144          // N*N
#define ND   392          // B*D
#define RQ   4704         // N*B*D
#define SQ   588          // N*D (rows per batch in attn2)
#define SCALE_ 0.0625f    // (C/2)^-0.5
#define EPS_  1e-5f

#define GEMM_SMEM 61440   // 3 stages * (A 10240B + B 10240B)

// ---------------- static device scratch (zero-initialized at load) ----------
__device__ float g_h[RQ * Cch];
__device__ float g_q1[RQ * Hh];
__device__ float g_k1[ND * Hh];
__device__ float g_v1[(ND + 16) * Cch];  // padded rows stay 0 (zero-init)
__device__ float g_S1[96 * Dd * Dd];
__device__ float g_P[96 * Dd * 64];
__device__ float g_feat1[RQ * Cch];      // rows (b*12+n)*49+d  (b-major)
__device__ float g_QK2[RQ * Cch];        // cols 0-255 = Q2, 256-511 = K2
__device__ float g_Vp[RQ * Cch];
__device__ float g_Wvp[Cch * Cch];
__device__ float g_bvp[Cch];
__device__ float g_wqk[Cch * Cch];
__device__ float g_bqk[Cch];
__device__ float g_S[Bb * SQ * SQ];
__device__ float g_MV[Bb * Nn * Dd * Dd];
__device__ float g_w[Bb * Ee * Dd];
__device__ float g_gram[Bb * Ee];
__device__ float g_fv[Bb * Nn * Cch];
__device__ float g_zbar[Bb * Ee * Cch];
__device__ float g_ps1[Bb * Ee];
__device__ float g_ps2[Bb * Ee];
__device__ float g_bn1m[Nn * Cch];
__device__ float g_bn1r[Nn * Cch];
__device__ float g_mask[Bb * Ee];
__device__ float g_fe[Bb * Ee * Cch];
__device__ float g_wnodeA[Cch * 2048];
__device__ float g_wnodeB[Cch * 2048];
__device__ float g_xnode[Bb * Nn * 2048];
__device__ float g_xw[Bb * Ee * Cch];
__device__ float g_msg[Bb * Nn * Cch];

// ---------------- helpers ----------------------------------------------------
__device__ __forceinline__ float block_reduce_sum(float v, float* sm) {
    int lane = threadIdx.x & 31, w = threadIdx.x >> 5;
#pragma unroll
    for (int o = 16; o; o >>= 1) v += __shfl_xor_sync(0xffffffffu, v, o);
    if (lane == 0) sm[w] = v;
    __syncthreads();
    int nw = (blockDim.x + 31) >> 5;
    float r = 0.f;
    if (threadIdx.x < 32) {
        r = (threadIdx.x < nw) ? sm[threadIdx.x] : 0.f;
#pragma unroll
        for (int o = 16; o; o >>= 1) r += __shfl_xor_sync(0xffffffffu, r, o);
        if (threadIdx.x == 0) sm[0] = r;
    }
    __syncthreads();
    r = sm[0];
    __syncthreads();
    return r;
}

__device__ __forceinline__ uint32_t f2tf32(float x) {
    uint32_t r;
    asm("cvt.rna.tf32.f32 %0, %1;" : "=r"(r) : "f"(x));
    return r;
}

__device__ __forceinline__ void mma_tf32(float* c, const uint32_t* a, const uint32_t* b) {
    asm volatile(
        "mma.sync.aligned.m16n8k8.row.col.f32.tf32.tf32.f32 "
        "{%0,%1,%2,%3}, {%4,%5,%6,%7}, {%8,%9}, {%0,%1,%2,%3};"
        : "+f"(c[0]), "+f"(c[1]), "+f"(c[2]), "+f"(c[3])
        : "r"(a[0]), "r"(a[1]), "r"(a[2]), "r"(a[3]), "r"(b[0]), "r"(b[1]));
}

__device__ __forceinline__ void cp16(uint32_t s, const void* g, int sz) {
    asm volatile("cp.async.ca.shared.global [%0], [%1], 16, %2;"
                 :: "r"(s), "l"(g), "r"(sz));
}

__device__ __forceinline__ float4 f4add(float4 a, float4 b) {
    return make_float4(a.x + b.x, a.y + b.y, a.z + b.z, a.w + b.w);
}

// ---------------- gemm_tc: TF32 TC GEMM, 128x128x16, 3-stage cp.async --------
// Smem fp32: A[m][k] stride 20 (conflict-free frag loads), B NN [k][n] stride 136,
// B NT [n][k] stride 20. One commit_group per k-tile; wait_group 1; 1 sync/tile.
// Out-of-bounds rows/cols: predicate src-size=0 (zero-fill) with pointer clamped
// to a valid row so no OOB address is ever formed.
__global__ __launch_bounds__(256, 2) void gemm_tc(
    const float* __restrict__ A, const float* __restrict__ Bm,
    const float* __restrict__ bias, float* __restrict__ Cm,
    int M, int Np, int K, int lda, int ldb, int ldc,
    long sA1, long sA2, long sB1, long sB2, long sC1, long sC2,
    int zdiv, int transB)
{
    const int S = 3;
    extern __shared__ float smem[];
    float* Asm = smem;              // [S][2560]  A: m*20+k
    float* Bsm = smem + S * 2560;   // [S][2560]  B: NN k*136+n / NT n*20+k

    int z = blockIdx.z;
    int zq = z / zdiv, zr = z % zdiv;
    const float* Az = A + zq * sA1 + (long)zr * sA2;
    const float* Bz = Bm + zq * sB1 + (long)zr * sB2;
    float* Cz = Cm + zq * sC1 + (long)zr * sC2;

    int tid = threadIdx.x;
    int row0 = blockIdx.y * 128, col0 = blockIdx.x * 128;
    int warp = tid >> 5, lane = tid & 31;
    int wm = (warp >> 2) * 64, wn = (warp & 3) * 32;
    int gid = lane >> 2, tig = lane & 3;

    float c[4][4][4];
#pragma unroll
    for (int mi = 0; mi < 4; mi++)
#pragma unroll
        for (int ni = 0; ni < 4; ni++)
#pragma unroll
            for (int q = 0; q < 4; q++) c[mi][ni][q] = 0.f;

    int nt = K >> 4;

#define ISSUE(t)                                                               \
    {                                                                          \
        int k0_ = (t) << 4;                                                    \
        float* Ab_ = Asm + ((t) % S) * 2560;                                   \
        float* Bb_ = Bsm + ((t) % S) * 2560;                                   \
        _Pragma("unroll")                                                      \
        for (int cc_ = 0; cc_ < 2; cc_++) {                                    \
            int idx_ = tid * 2 + cc_;                                          \
            int row_ = idx_ >> 2, kq_ = (idx_ & 3) * 4;                        \
            int gr_ = row0 + row_;                                             \
            int ok_ = (gr_ < M);                                               \
            const float* gp_ = Az + (long)(ok_ ? gr_ : 0) * lda + k0_ + kq_;   \
            uint32_t sa_ = (uint32_t)__cvta_generic_to_shared(                 \
                Ab_ + row_ * 20 + kq_);                                        \
            cp16(sa_, gp_, ok_ ? 16 : 0);                                      \
        }                                                                      \
        if (!transB) {                                                         \
            _Pragma("unroll")                                                  \
            for (int cc_ = 0; cc_ < 2; cc_++) {                                \
                int idx_ = tid * 2 + cc_;                                      \
                int kk_ = idx_ >> 5, n4_ = (idx_ & 31) * 4;                    \
                int gc_ = col0 + n4_;                                          \
                int ok_ = (gc_ < Np);                                          \
                const float* gp_ = Bz + (long)(k0_ + kk_) * ldb +              \
                                   (ok_ ? gc_ : 0);                            \
                uint32_t sa_ = (uint32_t)__cvta_generic_to_shared(             \
                    Bb_ + kk_ * 136 + n4_);                                    \
                cp16(sa_, gp_, ok_ ? 16 : 0);                                  \
            }                                                                  \
        } else {                                                               \
            _Pragma("unroll")                                                  \
            for (int cc_ = 0; cc_ < 2; cc_++) {                                \
                int idx_ = tid * 2 + cc_;                                      \
                int row_ = idx_ >> 2, kq_ = (idx_ & 3) * 4;                    \
                int gn_ = col0 + row_;                                         \
                int ok_ = (gn_ < Np);                                          \
                const float* gp_ = Bz + (long)(ok_ ? gn_ : 0) * ldb +          \
                                   k0_ + kq_;                                  \
                uint32_t sa_ = (uint32_t)__cvta_generic_to_shared(             \
                    Bb_ + row_ * 20 + kq_);                                    \
                cp16(sa_, gp_, ok_ ? 16 : 0);                                  \
            }                                                                  \
        }                                                                      \
        asm volatile("cp.async.commit_group;");                                \
    }

    // preload S-1 stages (empty commits keep group counts consistent)
#pragma unroll
    for (int pt = 0; pt < S - 1; pt++) {
        if (pt < nt) ISSUE(pt)
        else asm volatile("cp.async.commit_group;");
    }

    for (int t = 0; t < nt; t++) {
        asm volatile("cp.async.wait_group 1;");  // stage t complete
        __syncthreads();                          // visible to all; prior compute done
        if (t + S - 1 < nt) ISSUE(t + S - 1)
        else asm volatile("cp.async.commit_group;");

        const float* Apt = Asm + (t % S) * 2560;
        const float* Bpt = Bsm + (t % S) * 2560;
#pragma unroll
        for (int k8i = 0; k8i < 2; k8i++) {
            int kk = k8i * 8 + tig;
            uint32_t af[4][4], bf[4][2];
#pragma unroll
            for (int mi = 0; mi < 4; mi++) {
                int mb = wm + mi * 16 + gid;
                af[mi][0] = f2tf32(Apt[mb * 20 + kk]);
                af[mi][2] = f2tf32(Apt[mb * 20 + kk + 4]);
                af[mi][1] = f2tf32(Apt[(mb + 8) * 20 + kk]);
                af[mi][3] = f2tf32(Apt[(mb + 8) * 20 + kk + 4]);
            }
            if (!transB) {
#pragma unroll
                for (int ni = 0; ni < 4; ni++) {
                    int nb = wn + ni * 8 + gid;
                    bf[ni][0] = f2tf32(Bpt[kk * 136 + nb]);
                    bf[ni][1] = f2tf32(Bpt[(kk + 4) * 136 + nb]);
                }
            } else {
#pragma unroll
                for (int ni = 0; ni < 4; ni++) {
                    int nb = wn + ni * 8 + gid;
                    bf[ni][0] = f2tf32(Bpt[nb * 20 + kk]);
                    bf[ni][1] = f2tf32(Bpt[nb * 20 + kk + 4]);
                }
            }
#pragma unroll
            for (int mi = 0; mi < 4; mi++)
#pragma unroll
                for (int ni = 0; ni < 4; ni++)
                    mma_tf32(c[mi][ni], af[mi], bf[ni]);
        }
    }
#undef ISSUE

#pragma unroll
    for (int mi = 0; mi < 4; mi++) {
        int r0 = row0 + wm + mi * 16 + gid;
        int r1 = r0 + 8;
#pragma unroll
        for (int ni = 0; ni < 4; ni++) {
            int cb = col0 + wn + ni * 8 + 2 * tig;
            float bv0 = 0.f, bv1 = 0.f;
            if (bias) {
                if (cb < Np) bv0 = bias[cb];
                if (cb + 1 < Np) bv1 = bias[cb + 1];
            }
            if (r0 < M) {
                if (cb < Np)     Cz[(long)r0 * ldc + cb]     = c[mi][ni][0] + bv0;
                if (cb + 1 < Np) Cz[(long)r0 * ldc + cb + 1] = c[mi][ni][1] + bv1;
            }
            if (r1 < M) {
                if (cb < Np)     Cz[(long)r1 * ldc + cb]     = c[mi][ni][2] + bv0;
                if (cb + 1 < Np) Cz[(long)r1 * ldc + cb + 1] = c[mi][ni][3] + bv1;
            }
        }
    }
}

// ---------------- gemm64 (fp32, kept only for the MV Gram) -------------------
__global__ __launch_bounds__(256) void gemm64_kernel(
    const float* __restrict__ A, const float* __restrict__ Bm,
    const float* __restrict__ bias, float* __restrict__ Cm,
    int M, int Np, int K, int lda, int ldb, int ldc,
    long sA, long sB, long sC, int transB)
{
    const float* Az = A + (long)blockIdx.z * sA;
    const float* Bz = Bm + (long)blockIdx.z * sB;
    float* Cz = Cm + (long)blockIdx.z * sC;
    __shared__ float As[16][64];
    __shared__ float Bs[16][64];
    int tid = threadIdx.x;
    int tx = tid & 15, ty = tid >> 4;
    int row0 = blockIdx.y * 64, col0 = blockIdx.x * 64;
    int lr = tid >> 2, lk = (tid & 3) * 4;
    int bkk = tid >> 4, bn = (tid & 15) * 4;
    const float4 z4 = {0.f, 0.f, 0.f, 0.f};
    float acc[4][4];
#pragma unroll
    for (int i = 0; i < 4; i++)
#pragma unroll
        for (int j = 0; j < 4; j++) acc[i][j] = 0.f;

    for (int k0 = 0; k0 < K; k0 += 16) {
        float4 av = z4, bv = z4;
        if (row0 + lr < M) av = *(const float4*)(Az + (long)(row0 + lr) * lda + k0 + lk);
        if (!transB) {
            if (col0 + bn < Np) bv = *(const float4*)(Bz + (long)(k0 + bkk) * ldb + col0 + bn);
        } else {
            if (col0 + lr < Np) bv = *(const float4*)(Bz + (long)(col0 + lr) * ldb + k0 + lk);
        }
        __syncthreads();
        As[lk+0][lr]=av.x; As[lk+1][lr]=av.y; As[lk+2][lr]=av.z; As[lk+3][lr]=av.w;
        if (!transB) {
            *(float4*)&Bs[bkk][bn] = bv;
        } else {
            Bs[lk+0][lr]=bv.x; Bs[lk+1][lr]=bv.y; Bs[lk+2][lr]=bv.z; Bs[lk+3][lr]=bv.w;
        }
        __syncthreads();
#pragma unroll
        for (int kk = 0; kk < 16; kk++) {
            float4 a4 = *(const float4*)&As[kk][ty * 4];
            float4 b4 = *(const float4*)&Bs[kk][tx * 4];
            float a[4] = {a4.x, a4.y, a4.z, a4.w};
            float b[4] = {b4.x, b4.y, b4.z, b4.w};
#pragma unroll
            for (int i = 0; i < 4; i++)
#pragma unroll
                for (int j = 0; j < 4; j++) acc[i][j] += a[i] * b[j];
        }
    }
#pragma unroll
    for (int i = 0; i < 4; i++) {
        int gr = row0 + ty * 4 + i;
        if (gr >= M) continue;
#pragma unroll
        for (int j = 0; j < 4; j++) {
            int gc = col0 + tx * 4 + j;
            if (gc < Np)
                Cz[(long)gr * ldc + gc] = acc[i][j] + (bias ? bias[gc] : 0.f);
        }
    }
}

// ---------------- weight packers ---------------------------------------------
__global__ void pack_qk_kernel(const float* __restrict__ wq, const float* __restrict__ wk,
                               const float* __restrict__ bq, const float* __restrict__ bk) {
    int idx = blockIdx.x * 256 + threadIdx.x;
    int k = idx >> 9, c = idx & 511;
    g_wqk[idx] = (c < 256) ? wq[k * 256 + c] : wk[k * 256 + c - 256];
    if (idx < 512) g_bqk[idx] = (idx < 256) ? bq[idx] : bk[idx - 256];
}

__global__ void pack_node_kernel(const float* __restrict__ wa, const float* __restrict__ wb,
                                 const float* __restrict__ wu, const float* __restrict__ wv,
                                 float* __restrict__ dst) {
    int idx = blockIdx.x * 256 + threadIdx.x;
    int k = idx >> 11, c = idx & 2047;
    const float* src = (c < 512) ? wa : (c < 1024) ? wb : (c < 1536) ? wu : wv;
    dst[idx] = src[k * 512 + (c & 511)];
}

// ---------------- BN1 ---------------------------------------------------------
__global__ void bn1_stats_kernel() {
    int n = blockIdx.x;
    int cl = threadIdx.x & 63;
    int q = threadIdx.x >> 6;
    int c = blockIdx.y * 64 + cl;
    float s1 = 0.f, s2 = 0.f;
    const float* base = g_h + (long)n * ND * Cch + c;
    for (int r = q; r < ND; r += 4) {
        float v = base[(long)r * Cch];
        s1 += v; s2 += v * v;
    }
    __shared__ float sm1[4][64], sm2[4][64];
    sm1[q][cl] = s1; sm2[q][cl] = s2;
    __syncthreads();
    if (q == 0) {
        s1 = sm1[0][cl] + sm1[1][cl] + sm1[2][cl] + sm1[3][cl];
        s2 = sm2[0][cl] + sm2[1][cl] + sm2[2][cl] + sm2[3][cl];
        float m = s1 / (float)ND;
        float var = s2 / (float)ND - m * m;
        g_bn1m[n * Cch + c] = m;
        g_bn1r[n * Cch + c] = rsqrtf(fmaxf(var, 0.f) + EPS_);
    }
}

__global__ void bn1_apply_kernel() {
    int n = blockIdx.x, b = blockIdx.y;
    int c4 = threadIdx.x;
    float4 m = ((const float4*)(g_bn1m + n * Cch))[c4];
    float4 r = ((const float4*)(g_bn1r + n * Cch))[c4];
    float4* hb = (float4*)(g_h + ((long)(n * Bb + b) * Dd) * Cch) + c4;
    float4 acc = {0.f, 0.f, 0.f, 0.f};
    for (int d = 0; d < Dd; d++) {
        float4 h = hb[(long)d * 128];
        float4 u;
        u.x = fmaxf((h.x - m.x) * r.x, 0.f);
        u.y = fmaxf((h.y - m.y) * r.y, 0.f);
        u.z = fmaxf((h.z - m.z) * r.z, 0.f);
        u.w = fmaxf((h.w - m.w) * r.w, 0.f);
        hb[(long)d * 128] = u;
        acc = f4add(acc, u);
    }
    float inv = 1.f / (float)Dd;
    acc.x *= inv; acc.y *= inv; acc.z *= inv; acc.w *= inv;
    ((float4*)(g_fv + (long)(b * Nn + n) * Cch))[c4] = acc;
}

// ---------------- attn1 softmax ----------------------------------------------
__global__ void softmaxP_kernel() {
    int z = blockIdx.x;
    int tid = threadIdx.x, w = tid >> 5, lane = tid & 31;
    const float* Sb = g_S1 + (long)z * Dd * Dd;
    float* Pb = g_P + (long)z * Dd * 64;
    for (int r = w; r < Dd; r += 8) {
        float v0 = (lane < Dd) ? Sb[r * Dd + lane] * SCALE_ : -1e30f;
        float v1 = (lane + 32 < Dd) ? Sb[r * Dd + lane + 32] * SCALE_ : -1e30f;
        float mx = fmaxf(v0, v1);
#pragma unroll
        for (int o = 16; o; o >>= 1) mx = fmaxf(mx, __shfl_xor_sync(0xffffffffu, mx, o));
        float e0 = (lane < Dd) ? expf(v0 - mx) : 0.f;
        float e1 = (lane + 32 < Dd) ? expf(v1 - mx) : 0.f;
        float s = e0 + e1;
#pragma unroll
        for (int o = 16; o; o >>= 1) s += __shfl_xor_sync(0xffffffffu, s, o);
        float inv = 1.f / s;
        if (lane < Dd) Pb[r * 64 + lane] = e0 * inv;
        Pb[r * 64 + lane + 32] = (lane + 32 < Dd) ? e1 * inv : 0.f;
    }
}

__global__ void bvp_kernel(const float* __restrict__ bv, const float* __restrict__ epw) {
    int c = threadIdx.x;
    float s = 0.f;
    for (int k = 0; k < Cch; k++) s += bv[k] * epw[k * Cch + c];
    g_bvp[c] = s;
}

// ---------------- attn2: per-(b,e) softmax + agg weights + Gram term ----------
__global__ void pg_kernel() {
    int e = blockIdx.x, b = blockIdx.y;
    int i = e / Nn, j = e % Nn;
    __shared__ float P[49][50];
    __shared__ float MVs[Dd * Dd];
    __shared__ float gpart[8];
    int tid = threadIdx.x, w = tid >> 5, lane = tid & 31;
    const float* MVg = g_MV + (long)(b * Nn + i) * (Dd * Dd);
    for (int t = tid; t < Dd * Dd; t += 256) MVs[t] = MVg[t];
    const float* Sb = g_S + (long)b * SQ * SQ + (long)(j * Dd) * SQ + i * Dd;
    for (int r = w; r < Dd; r += 8) {
        float v0 = (lane < Dd) ? Sb[r * SQ + lane] * SCALE_ : -1e30f;
        float v1 = (lane + 32 < Dd) ? Sb[r * SQ + lane + 32] * SCALE_ : -1e30f;
        float mx = fmaxf(v0, v1);
#pragma unroll
        for (int o = 16; o; o >>= 1) mx = fmaxf(mx, __shfl_xor_sync(0xffffffffu, mx, o));
        float e0 = (lane < Dd) ? expf(v0 - mx) : 0.f;
        float e1 = (lane + 32 < Dd) ? expf(v1 - mx) : 0.f;
        float s = e0 + e1;
#pragma unroll
        for (int o = 16; o; o >>= 1) s += __shfl_xor_sync(0xffffffffu, s, o);
        float inv = 1.f / s;
        if (lane < Dd) P[r][lane] = e0 * inv;
        if (lane + 32 < Dd) P[r][lane + 32] = e1 * inv;
    }
    __syncthreads();
    if (tid < Dd) {
        float s = 0.f;
        for (int r = 0; r < Dd; r++) s += P[r][tid];
        g_w[((long)b * Ee + e) * Dd + tid] = s * (1.f / (float)Dd);
    }
    float acc = 0.f;
    for (int r = w; r < Dd; r += 8) {
        float t0 = 0.f, t1 = 0.f;
        for (int bbk = 0; bbk < Dd; bbk++) {
            float p = P[r][bbk];
            t0 += MVs[lane * Dd + bbk] * p;
            if (lane + 32 < Dd) t1 += MVs[(lane + 32) * Dd + bbk] * p;
        }
        acc += P[r][lane] * t0;
        if (lane + 32 < Dd) acc += P[r][lane + 32] * t1;
    }
#pragma unroll
    for (int o = 16; o; o >>= 1) acc += __shfl_xor_sync(0xffffffffu, acc, o);
    if (lane == 0) gpart[w] = acc;
    __syncthreads();
    if (tid == 0) {
        float s = 0.f;
        for (int q = 0; q < 8; q++) s += gpart[q];
        g_gram[b * Ee + e] = s;
    }
}

// zbar = w^T Vp + epb ; stats via Gram identity. grid (12,8)=(i,b), block 512.
__global__ void zbar_stats_kernel(const float* __restrict__ ep_b) {
    int i = blockIdx.x, b = blockIdx.y;
    __shared__ float ws[Nn * Dd];
    __shared__ float red[16][26];
    int tid = threadIdx.x, lane = tid & 31, w = tid >> 5;
    for (int t = tid; t < Nn * Dd; t += 512) {
        int j = t / Dd, d2 = t % Dd;
        ws[t] = g_w[((long)b * Ee + i * Nn + j) * Dd + d2];
    }
    __syncthreads();
    float acc[Nn];
#pragma unroll
    for (int j = 0; j < Nn; j++) acc[j] = 0.f;
    const float* Vb = g_Vp + (long)((b * Nn + i) * Dd) * Cch;
    for (int d2 = 0; d2 < Dd; d2++) {
        float v = Vb[(long)d2 * Cch + tid];
#pragma unroll
        for (int j = 0; j < Nn; j++) acc[j] += ws[j * Dd + d2] * v;
    }
    float eb = ep_b[tid];
    float loc[25];
#pragma unroll
    for (int j = 0; j < Nn; j++) {
        float z = acc[j] + eb;
        g_zbar[((long)b * Ee + i * Nn + j) * Cch + tid] = z;
        loc[j] = z;
        loc[Nn + j] = eb * z;
    }
    loc[24] = eb * eb;
#pragma unroll
    for (int k = 0; k < 25; k++) {
        float v = loc[k];
#pragma unroll
        for (int o = 16; o; o >>= 1) v += __shfl_xor_sync(0xffffffffu, v, o);
        if (lane == 0) red[w][k] = v;
    }
    __syncthreads();
    if (tid < Nn) {
        float S = 0.f, T = 0.f, E = 0.f;
#pragma unroll
        for (int q = 0; q < 16; q++) {
            S += red[q][tid]; T += red[q][Nn + tid]; E += red[q][24];
        }
        int e = i * Nn + tid;
        g_ps1[b * Ee + e] = 49.f * S;
        g_ps2[b * Ee + e] = g_gram[b * Ee + e] + 98.f * T - 49.f * E;
    }
}

// ---------------- cosine adjacency mask --------------------------------------
__global__ void mask_kernel() {
    int b = blockIdx.x;
    __shared__ float sinv[Nn];
    __shared__ float adj[Ee];
    __shared__ float dis[Nn];
    int tid = threadIdx.x, w = tid >> 5, lane = tid & 31;
    for (int n = w; n < Nn; n += 8) {
        const float4* f = (const float4*)(g_fv + (long)(b * Nn + n) * Cch);
        float s = 0.f;
        for (int t = lane; t < 128; t += 32) {
            float4 x = f[t];
            s += x.x * x.x + x.y * x.y + x.z * x.z + x.w * x.w;
        }
#pragma unroll
        for (int o = 16; o; o >>= 1) s += __shfl_xor_sync(0xffffffffu, s, o);
        if (lane == 0) sinv[n] = 1.f / fmaxf(sqrtf(s), 1e-12f);
    }
    __syncthreads();
    for (int e = w; e < Ee; e += 8) {
        int i = e / Nn, jn = e % Nn;
        const float4* fi = (const float4*)(g_fv + (long)(b * Nn + i) * Cch);
        const float4* fj = (const float4*)(g_fv + (long)(b * Nn + jn) * Cch);
        float s = 0.f;
        for (int t = lane; t < 128; t += 32) {
            float4 a = fi[t], c = fj[t];
            s += a.x * c.x + a.y * c.y + a.z * c.z + a.w * c.w;
        }
#pragma unroll
        for (int o = 16; o; o >>= 1) s += __shfl_xor_sync(0xffffffffu, s, o);
        if (lane == 0) adj[e] = s * sinv[i] * sinv[jn];
    }
    __syncthreads();
    if (tid < Nn) {
        float s = 0.f;
        for (int jn = 0; jn < Nn; jn++) s += adj[tid * Nn + jn];
        dis[tid] = rsqrtf(s);
    }
    __syncthreads();
    if (tid < Ee) {
        int i = tid / Nn, jn = tid % Nn;
        g_mask[b * Ee + tid] = adj[tid] * dis[i] * dis[jn];
    }
}

// ---------------- edge BN + mask ---------------------------------------------
__global__ void edge_bn_mask_kernel() {
    int e = blockIdx.x;
    __shared__ float mrs[2];
    int tid = threadIdx.x;
    if (tid == 0) {
        float s1 = 0.f, s2 = 0.f;
        for (int b = 0; b < Bb; b++) { s1 += g_ps1[b * Ee + e]; s2 += g_ps2[b * Ee + e]; }
        float cnt = (float)(Bb * Dd * Cch);
        float m = s1 / cnt;
        float v = s2 / cnt - m * m;
        mrs[0] = m;
        mrs[1] = rsqrtf(fmaxf(v, 0.f) + EPS_);
    }
    __syncthreads();
    float m = mrs[0], r = mrs[1];
    for (int b = 0; b < Bb; b++) {
        float mk = g_mask[b * Ee + e] * r;
        const float4* zb = (const float4*)(g_zbar + (long)(b * Ee + e) * Cch);
        float4* fe = (float4*)(g_fe + (long)(b * Ee + e) * Cch);
        float4 z = zb[tid];
        fe[tid] = make_float4((z.x - m) * mk, (z.y - m) * mk, (z.z - m) * mk, (z.w - m) * mk);
    }
}

// ---------------- GNN layer pieces -------------------------------------------
__global__ void agg_bn_kernel() {
    int e = blockIdx.x;
    int i = e / Nn, jn = e % Nn;
    __shared__ float sm[32];
    int tid = threadIdx.x;
    float4 agg[Bb];
    float s1 = 0.f, s2 = 0.f;
#pragma unroll
    for (int b = 0; b < Bb; b++) {
        float4 va = ((const float4*)(g_xnode + (long)(b * Nn + i) * 2048))[tid];
        float4 vb = ((const float4*)(g_xnode + (long)(b * Nn + jn) * 2048 + 512))[tid];
        float4 vw = ((const float4*)(g_xw + (long)(b * Ee + e) * Cch))[tid];
        float4 v = f4add(f4add(va, vb), vw);
        agg[b] = v;
        s1 += v.x + v.y + v.z + v.w;
        s2 += v.x * v.x + v.y * v.y + v.z * v.z + v.w * v.w;
    }
    s1 = block_reduce_sum(s1, sm);
    s2 = block_reduce_sum(s2, sm);
    float cnt = (float)(Bb * Cch);
    float m = s1 / cnt;
    float r = rsqrtf(fmaxf(s2 / cnt - m * m, 0.f) + EPS_);
#pragma unroll
    for (int b = 0; b < Bb; b++) {
        float4* fe = (float4*)(g_fe + (long)(b * Ee + e) * Cch);
        float4 f = fe[tid], v = agg[b];
        f.x += fmaxf((v.x - m) * r, 0.f);
        f.y += fmaxf((v.y - m) * r, 0.f);
        f.z += fmaxf((v.z - m) * r, 0.f);
        f.w += fmaxf((v.w - m) * r, 0.f);
        fe[tid] = f;
    }
}

__global__ void softmax_msg_kernel() {
    int bi = blockIdx.x;
    int b = bi / Nn, i = bi % Nn;
    int tid = threadIdx.x;
    float4 v[Nn];
    float4 mx = {-1e30f, -1e30f, -1e30f, -1e30f};
#pragma unroll
    for (int jn = 0; jn < Nn; jn++) {
        float4 ed = ((const float4*)(g_fe + (long)(b * Ee + i * Nn + jn) * Cch))[tid];
        float4 s;
        s.x = 1.f / (1.f + expf(-ed.x));
        s.y = 1.f / (1.f + expf(-ed.y));
        s.z = 1.f / (1.f + expf(-ed.z));
        s.w = 1.f / (1.f + expf(-ed.w));
        v[jn] = s;
        mx.x = fmaxf(mx.x, s.x); mx.y = fmaxf(mx.y, s.y);
        mx.z = fmaxf(mx.z, s.z); mx.w = fmaxf(mx.w, s.w);
    }
    float4 sum = {0.f, 0.f, 0.f, 0.f};
#pragma unroll
    for (int jn = 0; jn < Nn; jn++) {
        v[jn].x = expf(v[jn].x - mx.x); v[jn].y = expf(v[jn].y - mx.y);
        v[jn].z = expf(v[jn].z - mx.z); v[jn].w = expf(v[jn].w - mx.w);
        sum = f4add(sum, v[jn]);
    }
    float4 acc = {0.f, 0.f, 0.f, 0.f};
#pragma unroll
    for (int jn = 0; jn < Nn; jn++) {
        float4 u = ((const float4*)(g_xnode + (long)(b * Nn + jn) * 2048 + 1536))[tid];
        acc.x += v[jn].x * u.x; acc.y += v[jn].y * u.y;
        acc.z += v[jn].z * u.z; acc.w += v[jn].w * u.w;
    }
    float4 o;
    o.x = acc.x / (sum.x * (float)Nn); o.y = acc.y / (sum.y * (float)Nn);
    o.z = acc.z / (sum.z * (float)Nn); o.w = acc.w / (sum.w * (float)Nn);
    ((float4*)(g_msg + (long)(b * Nn + i) * Cch))[tid] = o;
}

__global__ void node_bn_kernel() {
    int n = blockIdx.x;
    __shared__ float sm[32];
    int tid = threadIdx.x;
    float4 t[Bb];
    float s1 = 0.f, s2 = 0.f;
#pragma unroll
    for (int b = 0; b < Bb; b++) {
        float4 xu = ((const float4*)(g_xnode + (long)(b * Nn + n) * 2048 + 1024))[tid];
        float4 ms = ((const float4*)(g_msg + (long)(b * Nn + n) * Cch))[tid];
        float4 v = f4add(xu, ms);
        t[b] = v;
        s1 += v.x + v.y + v.z + v.w;
        s2 += v.x * v.x + v.y * v.y + v.z * v.z + v.w * v.w;
    }
    s1 = block_reduce_sum(s1, sm);
    s2 = block_reduce_sum(s2, sm);
    float cnt = (float)(Bb * Cch);
    float m = s1 / cnt;
    float r = rsqrtf(fmaxf(s2 / cnt - m * m, 0.f) + EPS_);
#pragma unroll
    for (int b = 0; b < Bb; b++) {
        float4* fv = (float4*)(g_fv + (long)(b * Nn + n) * Cch);
        float4 f = fv[tid], v = t[b];
        f.x = fmaxf(f.x + (v.x - m) * r, 0.f);
        f.y = fmaxf(f.y + (v.y - m) * r, 0.f);
        f.z = fmaxf(f.z + (v.z - m) * r, 0.f);
        f.w = fmaxf(f.w + (v.w - m) * r, 0.f);
        fv[tid] = f;
    }
}

// ---------------- classifier heads -------------------------------------------
__global__ void cls_kernel(const float* __restrict__ sc_w, float* __restrict__ out) {
    int bn = blockIdx.x;
    int n = bn % Nn;
    __shared__ float sm[32];
    int tid = threadIdx.x;
    float sf = 0.f, ff = 0.f, ss = 0.f;
    for (int c = tid; c < Cch; c += 128) {
        float f = g_fv[(long)bn * Cch + c];
        float s = fmaxf(sc_w[n * Cch + c], 0.f);
        sf += f * s; ff += f * f; ss += s * s;
    }
    sf = block_reduce_sum(sf, sm);
    ff = block_reduce_sum(ff, sm);
    ss = block_reduce_sum(ss, sm);
    if (tid == 0)
        out[bn] = sf / (fmaxf(sqrtf(ff), 1e-12f) * fmaxf(sqrtf(ss), 1e-12f));
}

__global__ void edgefc_kernel(const float* __restrict__ w, const float* __restrict__ bias,
                              float* __restrict__ out) {
    int row = blockIdx.x;
    int tid = threadIdx.x;
    int k = tid >> 5, lane = tid & 31;
    const float* f = g_fe + (long)row * Cch;
    float dot = 0.f;
    for (int c = lane; c < Cch; c += 32) dot += f[c] * w[c * 4 + k];
#pragma unroll
    for (int o = 16; o; o >>= 1) dot += __shfl_xor_sync(0xffffffffu, dot, o);
    if (lane == 0) out[96 + row * 4 + k] = dot + bias[k];
}

// ---------------- host driver -------------------------------------------------
extern "C" void kernel_launch(void* const* d_in, const int* in_sizes, int n_in,
                              void* d_out, int out_size) {
    const float* x      = (const float*)d_in[0];
    const float* Wc     = (const float*)d_in[1];
    const float* fam_wq = (const float*)d_in[3];
    const float* fam_bq = (const float*)d_in[4];
    const float* fam_wk = (const float*)d_in[5];
    const float* fam_wv = (const float*)d_in[7];
    const float* fam_bv = (const float*)d_in[8];
    const float* arm_wq = (const float*)d_in[9];
    const float* arm_bq = (const float*)d_in[10];
    const float* arm_wk = (const float*)d_in[11];
    const float* arm_bk = (const float*)d_in[12];
    const float* arm_wv = (const float*)d_in[13];
    const float* arm_bv = (const float*)d_in[14];
    const float* ep_w   = (const float*)d_in[15];
    const float* ep_b   = (const float*)d_in[16];
    const float* gw[10];
    for (int t = 0; t < 10; t++) gw[t] = (const float*)d_in[17 + t];
    const float* sc_w   = (const float*)d_in[27];
    const float* efc_w  = (const float*)d_in[28];
    const float* efc_b  = (const float*)d_in[29];
    float* out = (float*)d_out;

    float *p_h, *p_q1, *p_k1, *p_v1, *p_S1, *p_P, *p_f1, *p_QK2, *p_Vp, *p_Wvp, *p_bvp;
    float *p_wqk, *p_bqk, *p_S, *p_MV, *p_fv, *p_fe, *p_wnA, *p_wnB, *p_xnode, *p_xw;
    cudaGetSymbolAddress((void**)&p_h, g_h);
    cudaGetSymbolAddress((void**)&p_q1, g_q1);
    cudaGetSymbolAddress((void**)&p_k1, g_k1);
    cudaGetSymbolAddress((void**)&p_v1, g_v1);
    cudaGetSymbolAddress((void**)&p_S1, g_S1);
    cudaGetSymbolAddress((void**)&p_P, g_P);
    cudaGetSymbolAddress((void**)&p_f1, g_feat1);
    cudaGetSymbolAddress((void**)&p_QK2, g_QK2);
    cudaGetSymbolAddress((void**)&p_Vp, g_Vp);
    cudaGetSymbolAddress((void**)&p_Wvp, g_Wvp);
    cudaGetSymbolAddress((void**)&p_bvp, g_bvp);
    cudaGetSymbolAddress((void**)&p_wqk, g_wqk);
    cudaGetSymbolAddress((void**)&p_bqk, g_bqk);
    cudaGetSymbolAddress((void**)&p_S, g_S);
    cudaGetSymbolAddress((void**)&p_MV, g_MV);
    cudaGetSymbolAddress((void**)&p_fv, g_fv);
    cudaGetSymbolAddress((void**)&p_fe, g_fe);
    cudaGetSymbolAddress((void**)&p_wnA, g_wnodeA);
    cudaGetSymbolAddress((void**)&p_wnB, g_wnodeB);
    cudaGetSymbolAddress((void**)&p_xnode, g_xnode);
    cudaGetSymbolAddress((void**)&p_xw, g_xw);

    static cudaStream_t s1 = nullptr, s2 = nullptr;
    static cudaEvent_t evRoot, evPackQK, evK1, evV1, evWvpB, evFv, evFeat1,
                       evMV, evMask, evXn1, evNB1, evXn2;
    if (!s1) {
        cudaStreamCreateWithFlags(&s1, cudaStreamNonBlocking);
        cudaStreamCreateWithFlags(&s2, cudaStreamNonBlocking);
        cudaEventCreateWithFlags(&evRoot, cudaEventDisableTiming);
        cudaEventCreateWithFlags(&evPackQK, cudaEventDisableTiming);
        cudaEventCreateWithFlags(&evK1, cudaEventDisableTiming);
        cudaEventCreateWithFlags(&evV1, cudaEventDisableTiming);
        cudaEventCreateWithFlags(&evWvpB, cudaEventDisableTiming);
        cudaEventCreateWithFlags(&evFv, cudaEventDisableTiming);
        cudaEventCreateWithFlags(&evFeat1, cudaEventDisableTiming);
        cudaEventCreateWithFlags(&evMV, cudaEventDisableTiming);
        cudaEventCreateWithFlags(&evMask, cudaEventDisableTiming);
        cudaEventCreateWithFlags(&evXn1, cudaEventDisableTiming);
        cudaEventCreateWithFlags(&evNB1, cudaEventDisableTiming);
        cudaEventCreateWithFlags(&evXn2, cudaEventDisableTiming);
        cudaFuncSetAttribute(gemm_tc, cudaFuncAttributeMaxDynamicSharedMemorySize, GEMM_SMEM);
    }
    cudaStream_t s0 = 0;

    cudaEventRecord(evRoot, s0);

    // ---- s1: packing + K/V projections of attn1 ----
    cudaStreamWaitEvent(s1, evRoot, 0);
    pack_qk_kernel<<<1024, 256, 0, s1>>>(arm_wq, arm_wk, arm_bq, arm_bk);
    cudaEventRecord(evPackQK, s1);
    gemm_tc<<<dim3(2, 4, 1), 256, GEMM_SMEM, s1>>>(x, fam_wk, nullptr, p_k1, ND, Hh, Cch,
                                           Cch, Hh, Hh, 0, 0, 0, 0, 0, 0, 1, 0);
    cudaEventRecord(evK1, s1);
    gemm_tc<<<dim3(4, 4, 1), 256, GEMM_SMEM, s1>>>(x, fam_wv, fam_bv, p_v1, ND, Cch, Cch,
                                           Cch, Cch, Cch, 0, 0, 0, 0, 0, 0, 1, 0);
    cudaEventRecord(evV1, s1);

    // ---- s2: Wvp/bvp + node-weight packs ----
    cudaStreamWaitEvent(s2, evRoot, 0);
    gemm_tc<<<dim3(4, 4, 1), 256, GEMM_SMEM, s2>>>(arm_wv, ep_w, nullptr, p_Wvp, Cch, Cch, Cch,
                                           Cch, Cch, Cch, 0, 0, 0, 0, 0, 0, 1, 0);
    bvp_kernel<<<1, 512, 0, s2>>>(arm_bv, ep_w);
    cudaEventRecord(evWvpB, s2);
    pack_node_kernel<<<4096, 256, 0, s2>>>(gw[0], gw[1], gw[3], gw[4], p_wnA);
    pack_node_kernel<<<4096, 256, 0, s2>>>(gw[5], gw[6], gw[8], gw[9], p_wnB);

    // ---- s0 main chain: h -> BN1 ----
    gemm_tc<<<dim3(4, 4, 12), 256, GEMM_SMEM, s0>>>(x, Wc, nullptr, p_h, ND, Cch, Cch,
                                            Cch, Cch, Cch,
                                            0, 0, (long)Cch * Cch, 0, (long)ND * Cch, 0, 1, 0);
    bn1_stats_kernel<<<dim3(12, 8), 256, 0, s0>>>();
    bn1_apply_kernel<<<dim3(12, 8), 128, 0, s0>>>();
    cudaEventRecord(evFv, s0);

    // ---- s2: mask + xnode L1 ----
    cudaStreamWaitEvent(s2, evFv, 0);
    mask_kernel<<<Bb, 256, 0, s2>>>();
    cudaEventRecord(evMask, s2);
    gemm_tc<<<dim3(16, 1, 1), 256, GEMM_SMEM, s2>>>(p_fv, p_wnA, nullptr, p_xnode,
                                            Bb * Nn, 2048, Cch, Cch, 2048, 2048,
                                            0, 0, 0, 0, 0, 0, 1, 0);
    cudaEventRecord(evXn1, s2);

    // ---- s0: attn1 ----
    gemm_tc<<<dim3(2, 37, 1), 256, GEMM_SMEM, s0>>>(p_h, fam_wq, fam_bq, p_q1, RQ, Hh, Cch,
                                            Cch, Hh, Hh, 0, 0, 0, 0, 0, 0, 1, 0);
    cudaStreamWaitEvent(s0, evK1, 0);
    gemm_tc<<<dim3(1, 1, 96), 256, GEMM_SMEM, s0>>>(p_q1, p_k1, nullptr, p_S1, Dd, Dd, Hh,
                                            Hh, Hh, Dd,
                                            (long)8 * Dd * Hh, (long)Dd * Hh,
                                            0, (long)Dd * Hh,
                                            (long)8 * Dd * Dd, (long)Dd * Dd, 8, 1);
    softmaxP_kernel<<<96, 256, 0, s0>>>();
    cudaStreamWaitEvent(s0, evV1, 0);
    gemm_tc<<<dim3(4, 1, 96), 256, GEMM_SMEM, s0>>>(p_P, p_v1, nullptr, p_f1, Dd, Cch, 64,
                                            64, Cch, Cch,
                                            (long)8 * Dd * 64, (long)Dd * 64,
                                            0, (long)Dd * Cch,
                                            (long)Dd * Cch, (long)Nn * Dd * Cch, 8, 0);
    cudaEventRecord(evFeat1, s0);

    // ---- s1: Vp + MV Gram ----
    cudaStreamWaitEvent(s1, evFeat1, 0);
    cudaStreamWaitEvent(s1, evWvpB, 0);
    gemm_tc<<<dim3(4, 37, 1), 256, GEMM_SMEM, s1>>>(p_f1, p_Wvp, p_bvp, p_Vp, RQ, Cch, Cch,
                                            Cch, Cch, Cch, 0, 0, 0, 0, 0, 0, 1, 0);
    gemm64_kernel<<<dim3(1, 1, 96), 256, 0, s1>>>(p_Vp, p_Vp, nullptr, p_MV,
                                                  Dd, Dd, Cch, Cch, Cch, Dd,
                                                  (long)Dd * Cch, (long)Dd * Cch, (long)Dd * Dd, 1);
    cudaEventRecord(evMV, s1);

    // ---- s0: QK2 -> S -> pg -> zbar -> edge ----
    cudaStreamWaitEvent(s0, evPackQK, 0);
    gemm_tc<<<dim3(4, 37, 1), 256, GEMM_SMEM, s0>>>(p_f1, p_wqk, p_bqk, p_QK2, RQ, Cch, Cch,
                                            Cch, Cch, Cch, 0, 0, 0, 0, 0, 0, 1, 0);
    gemm_tc<<<dim3(5, 5, 8), 256, GEMM_SMEM, s0>>>(p_QK2, p_QK2 + 256, nullptr, p_S, SQ, SQ, Hh,
                                           Cch, Cch, SQ,
                                           (long)SQ * Cch, 0, (long)SQ * Cch, 0,
                                           (long)SQ * SQ, 0, 1, 1);
    cudaStreamWaitEvent(s0, evMV, 0);
    pg_kernel<<<dim3(Ee, Bb), 256, 0, s0>>>();
    zbar_stats_kernel<<<dim3(Nn, Bb), 512, 0, s0>>>(ep_b);
    cudaStreamWaitEvent(s0, evMask, 0);
    edge_bn_mask_kernel<<<Ee, 128, 0, s0>>>();

    // ---- GNN layer 1 ----
    gemm_tc<<<dim3(4, 9, 1), 256, GEMM_SMEM, s0>>>(p_fe, gw[2], nullptr, p_xw,
                                           Bb * Ee, Cch, Cch, Cch, Cch, Cch,
                                           0, 0, 0, 0, 0, 0, 1, 0);
    cudaStreamWaitEvent(s0, evXn1, 0);
    agg_bn_kernel<<<Ee, 128, 0, s0>>>();
    softmax_msg_kernel<<<Bb * Nn, 128, 0, s0>>>();
    node_bn_kernel<<<Nn, 128, 0, s0>>>();
    cudaEventRecord(evNB1, s0);

    // ---- GNN layer 2 ----
    cudaStreamWaitEvent(s1, evNB1, 0);
    gemm_tc<<<dim3(16, 1, 1), 256, GEMM_SMEM, s1>>>(p_fv, p_wnB, nullptr, p_xnode,
                                            Bb * Nn, 2048, Cch, Cch, 2048, 2048,
                                            0, 0, 0, 0, 0, 0, 1, 0);
    cudaEventRecord(evXn2, s1);
    gemm_tc<<<dim3(4, 9, 1), 256, GEMM_SMEM, s0>>>(p_fe, gw[7], nullptr, p_xw,
                                           Bb * Ee, Cch, Cch, Cch, Cch, Cch,
                                           0, 0, 0, 0, 0, 0, 1, 0);
    cudaStreamWaitEvent(s0, evXn2, 0);
    agg_bn_kernel<<<Ee, 128, 0, s0>>>();
    softmax_msg_kernel<<<Bb * Nn, 128, 0, s0>>>();
    node_bn_kernel<<<Nn, 128, 0, s0>>>();

    cls_kernel<<<Bb * Nn, 128, 0, s0>>>(sc_w, out);
    edgefc_kernel<<<Bb * Ee, 128, 0, s0>>>(efc_w, efc_b, out);
}

// round 12
// speedup vs baseline: 5.4347x; 1.0573x over previous
#include <cuda_runtime.h>
#include <math.h>
#include <stdint.h>

// Problem constants
#define Bb   8
#define Dd   49
#define Cch  512
#define Nn   12
#define Hh   256          // C/2
#define Ee   144          // N*N
#define ND   392          // B*D
#define RQ   4704         // N*B*D
#define SQ   588          // N*D (rows per batch in attn2)
#define SCALE_ 0.0625f    // (C/2)^-0.5
#define EPS_  1e-5f

#define GEMM_SMEM 81920   // 4 stages * (A 10240B + B 10240B)

// ---------------- static device scratch (zero-initialized at load) ----------
__device__ float g_h[RQ * Cch];
__device__ float g_q1[RQ * Hh];
__device__ float g_k1[ND * Hh];
__device__ float g_v1[(ND + 16) * Cch];  // padded rows stay 0 (zero-init)
__device__ float g_S1[96 * Dd * Dd];
__device__ float g_P[96 * Dd * 64];
__device__ float g_feat1[RQ * Cch];      // rows (b*12+n)*49+d  (b-major)
__device__ float g_QK2[RQ * Cch];        // cols 0-255 = Q2, 256-511 = K2
__device__ float g_Vp[RQ * Cch];
__device__ float g_Wvp[Cch * Cch];
__device__ float g_bvp[Cch];
__device__ float g_wqk[Cch * Cch];
__device__ float g_bqk[Cch];
__device__ float g_S[Bb * SQ * SQ];
__device__ float g_MV[Bb * Nn * Dd * Dd];
__device__ float g_w[Bb * Ee * Dd];
__device__ float g_gram[Bb * Ee];
__device__ float g_fv[Bb * Nn * Cch];
__device__ float g_zbar[Bb * Ee * Cch];
__device__ float g_ps1[Bb * Ee];
__device__ float g_ps2[Bb * Ee];
__device__ float g_bn1m[Nn * Cch];
__device__ float g_bn1r[Nn * Cch];
__device__ float g_mask[Bb * Ee];
__device__ float g_fe[Bb * Ee * Cch];
__device__ float g_wnodeA[Cch * 2048];
__device__ float g_wnodeB[Cch * 2048];
__device__ float g_xnode[Bb * Nn * 2048];
__device__ float g_xw[Bb * Ee * Cch];
__device__ float g_msg[Bb * Nn * Cch];

// ---------------- helpers ----------------------------------------------------
__device__ __forceinline__ float block_reduce_sum(float v, float* sm) {
    int lane = threadIdx.x & 31, w = threadIdx.x >> 5;
#pragma unroll
    for (int o = 16; o; o >>= 1) v += __shfl_xor_sync(0xffffffffu, v, o);
    if (lane == 0) sm[w] = v;
    __syncthreads();
    int nw = (blockDim.x + 31) >> 5;
    float r = 0.f;
    if (threadIdx.x < 32) {
        r = (threadIdx.x < nw) ? sm[threadIdx.x] : 0.f;
#pragma unroll
        for (int o = 16; o; o >>= 1) r += __shfl_xor_sync(0xffffffffu, r, o);
        if (threadIdx.x == 0) sm[0] = r;
    }
    __syncthreads();
    r = sm[0];
    __syncthreads();
    return r;
}

__device__ __forceinline__ void mma_tf32(float* c, const uint32_t* a, const uint32_t* b) {
    asm volatile(
        "mma.sync.aligned.m16n8k8.row.col.f32.tf32.tf32.f32 "
        "{%0,%1,%2,%3}, {%4,%5,%6,%7}, {%8,%9}, {%0,%1,%2,%3};"
        : "+f"(c[0]), "+f"(c[1]), "+f"(c[2]), "+f"(c[3])
        : "r"(a[0]), "r"(a[1]), "r"(a[2]), "r"(a[3]), "r"(b[0]), "r"(b[1]));
}

__device__ __forceinline__ void cp16(uint32_t s, const void* g, int sz) {
    asm volatile("cp.async.ca.shared.global [%0], [%1], 16, %2;"
                 :: "r"(s), "l"(g), "r"(sz));
}

__device__ __forceinline__ float4 f4add(float4 a, float4 b) {
    return make_float4(a.x + b.x, a.y + b.y, a.z + b.z, a.w + b.w);
}

// ---------------- gemm_tc: TF32 TC GEMM, 128x128x16, 4-stage cp.async --------
// Smem fp32: A[m][k] stride 20, B NN [k][n] stride 136, B NT [n][k] stride 20.
// One commit_group per k-tile; wait_group 2 (depth-3 prefetch); 1 sync/tile.
// MMA consumes raw fp32 bits as tf32 (mantissa truncation) — no cvt in loop.
// OOB rows/cols: predicate src-size=0 with pointer clamped in-bounds.
__global__ __launch_bounds__(256, 2) void gemm_tc(
    const float* __restrict__ A, const float* __restrict__ Bm,
    const float* __restrict__ bias, float* __restrict__ Cm,
    int M, int Np, int K, int lda, int ldb, int ldc,
    long sA1, long sA2, long sB1, long sB2, long sC1, long sC2,
    int zdiv, int transB)
{
    const int S = 4;
    extern __shared__ float smem[];
    float* Asm = smem;              // [S][2560]  A: m*20+k
    float* Bsm = smem + S * 2560;   // [S][2560]  B: NN k*136+n / NT n*20+k

    int z = blockIdx.z;
    int zq = z / zdiv, zr = z % zdiv;
    const float* Az = A + zq * sA1 + (long)zr * sA2;
    const float* Bz = Bm + zq * sB1 + (long)zr * sB2;
    float* Cz = Cm + zq * sC1 + (long)zr * sC2;

    int tid = threadIdx.x;
    int row0 = blockIdx.y * 128, col0 = blockIdx.x * 128;
    int warp = tid >> 5, lane = tid & 31;
    int wm = (warp >> 2) * 64, wn = (warp & 3) * 32;
    int gid = lane >> 2, tig = lane & 3;

    float c[4][4][4];
#pragma unroll
    for (int mi = 0; mi < 4; mi++)
#pragma unroll
        for (int ni = 0; ni < 4; ni++)
#pragma unroll
            for (int q = 0; q < 4; q++) c[mi][ni][q] = 0.f;

    int nt = K >> 4;

#define ISSUE(t)                                                               \
    {                                                                          \
        int k0_ = (t) << 4;                                                    \
        float* Ab_ = Asm + ((t) % S) * 2560;                                   \
        float* Bb_ = Bsm + ((t) % S) * 2560;                                   \
        _Pragma("unroll")                                                      \
        for (int cc_ = 0; cc_ < 2; cc_++) {                                    \
            int idx_ = tid * 2 + cc_;                                          \
            int row_ = idx_ >> 2, kq_ = (idx_ & 3) * 4;                        \
            int gr_ = row0 + row_;                                             \
            int ok_ = (gr_ < M);                                               \
            const float* gp_ = Az + (long)(ok_ ? gr_ : 0) * lda + k0_ + kq_;   \
            uint32_t sa_ = (uint32_t)__cvta_generic_to_shared(                 \
                Ab_ + row_ * 20 + kq_);                                        \
            cp16(sa_, gp_, ok_ ? 16 : 0);                                      \
        }                                                                      \
        if (!transB) {                                                         \
            _Pragma("unroll")                                                  \
            for (int cc_ = 0; cc_ < 2; cc_++) {                                \
                int idx_ = tid * 2 + cc_;                                      \
                int kk_ = idx_ >> 5, n4_ = (idx_ & 31) * 4;                    \
                int gc_ = col0 + n4_;                                          \
                int ok_ = (gc_ < Np);                                          \
                const float* gp_ = Bz + (long)(k0_ + kk_) * ldb +              \
                                   (ok_ ? gc_ : 0);                            \
                uint32_t sa_ = (uint32_t)__cvta_generic_to_shared(             \
                    Bb_ + kk_ * 136 + n4_);                                    \
                cp16(sa_, gp_, ok_ ? 16 : 0);                                  \
            }                                                                  \
        } else {                                                               \
            _Pragma("unroll")                                                  \
            for (int cc_ = 0; cc_ < 2; cc_++) {                                \
                int idx_ = tid * 2 + cc_;                                      \
                int row_ = idx_ >> 2, kq_ = (idx_ & 3) * 4;                    \
                int gn_ = col0 + row_;                                         \
                int ok_ = (gn_ < Np);                                          \
                const float* gp_ = Bz + (long)(ok_ ? gn_ : 0) * ldb +          \
                                   k0_ + kq_;                                  \
                uint32_t sa_ = (uint32_t)__cvta_generic_to_shared(             \
                    Bb_ + row_ * 20 + kq_);                                    \
                cp16(sa_, gp_, ok_ ? 16 : 0);                                  \
            }                                                                  \
        }                                                                      \
        asm volatile("cp.async.commit_group;");                                \
    }

    // preload S-1 stages (empty commits keep group counts consistent)
#pragma unroll
    for (int pt = 0; pt < S - 1; pt++) {
        if (pt < nt) ISSUE(pt)
        else asm volatile("cp.async.commit_group;");
    }

    for (int t = 0; t < nt; t++) {
        asm volatile("cp.async.wait_group 2;");  // stage t complete (<=2 outstanding)
        __syncthreads();                          // visible to all; prior compute done
        if (t + S - 1 < nt) ISSUE(t + S - 1)
        else asm volatile("cp.async.commit_group;");

        const float* Apt = Asm + (t % S) * 2560;
        const float* Bpt = Bsm + (t % S) * 2560;
#pragma unroll
        for (int k8i = 0; k8i < 2; k8i++) {
            int kk = k8i * 8 + tig;
            uint32_t af[4][4], bf[4][2];
#pragma unroll
            for (int mi = 0; mi < 4; mi++) {
                int mb = wm + mi * 16 + gid;
                af[mi][0] = __float_as_uint(Apt[mb * 20 + kk]);
                af[mi][2] = __float_as_uint(Apt[mb * 20 + kk + 4]);
                af[mi][1] = __float_as_uint(Apt[(mb + 8) * 20 + kk]);
                af[mi][3] = __float_as_uint(Apt[(mb + 8) * 20 + kk + 4]);
            }
            if (!transB) {
#pragma unroll
                for (int ni = 0; ni < 4; ni++) {
                    int nb = wn + ni * 8 + gid;
                    bf[ni][0] = __float_as_uint(Bpt[kk * 136 + nb]);
                    bf[ni][1] = __float_as_uint(Bpt[(kk + 4) * 136 + nb]);
                }
            } else {
#pragma unroll
                for (int ni = 0; ni < 4; ni++) {
                    int nb = wn + ni * 8 + gid;
                    bf[ni][0] = __float_as_uint(Bpt[nb * 20 + kk]);
                    bf[ni][1] = __float_as_uint(Bpt[nb * 20 + kk + 4]);
                }
            }
#pragma unroll
            for (int mi = 0; mi < 4; mi++)
#pragma unroll
                for (int ni = 0; ni < 4; ni++)
                    mma_tf32(c[mi][ni], af[mi], bf[ni]);
        }
    }
#undef ISSUE

#pragma unroll
    for (int mi = 0; mi < 4; mi++) {
        int r0 = row0 + wm + mi * 16 + gid;
        int r1 = r0 + 8;
#pragma unroll
        for (int ni = 0; ni < 4; ni++) {
            int cb = col0 + wn + ni * 8 + 2 * tig;
            float bv0 = 0.f, bv1 = 0.f;
            if (bias) {
                if (cb < Np) bv0 = bias[cb];
                if (cb + 1 < Np) bv1 = bias[cb + 1];
            }
            if (r0 < M) {
                if (cb < Np)     Cz[(long)r0 * ldc + cb]     = c[mi][ni][0] + bv0;
                if (cb + 1 < Np) Cz[(long)r0 * ldc + cb + 1] = c[mi][ni][1] + bv1;
            }
            if (r1 < M) {
                if (cb < Np)     Cz[(long)r1 * ldc + cb]     = c[mi][ni][2] + bv0;
                if (cb + 1 < Np) Cz[(long)r1 * ldc + cb + 1] = c[mi][ni][3] + bv1;
            }
        }
    }
}

// ---------------- gemm64 (fp32, kept only for the MV Gram) -------------------
__global__ __launch_bounds__(256) void gemm64_kernel(
    const float* __restrict__ A, const float* __restrict__ Bm,
    const float* __restrict__ bias, float* __restrict__ Cm,
    int M, int Np, int K, int lda, int ldb, int ldc,
    long sA, long sB, long sC, int transB)
{
    const float* Az = A + (long)blockIdx.z * sA;
    const float* Bz = Bm + (long)blockIdx.z * sB;
    float* Cz = Cm + (long)blockIdx.z * sC;
    __shared__ float As[16][64];
    __shared__ float Bs[16][64];
    int tid = threadIdx.x;
    int tx = tid & 15, ty = tid >> 4;
    int row0 = blockIdx.y * 64, col0 = blockIdx.x * 64;
    int lr = tid >> 2, lk = (tid & 3) * 4;
    int bkk = tid >> 4, bn = (tid & 15) * 4;
    const float4 z4 = {0.f, 0.f, 0.f, 0.f};
    float acc[4][4];
#pragma unroll
    for (int i = 0; i < 4; i++)
#pragma unroll
        for (int j = 0; j < 4; j++) acc[i][j] = 0.f;

    for (int k0 = 0; k0 < K; k0 += 16) {
        float4 av = z4, bv = z4;
        if (row0 + lr < M) av = *(const float4*)(Az + (long)(row0 + lr) * lda + k0 + lk);
        if (!transB) {
            if (col0 + bn < Np) bv = *(const float4*)(Bz + (long)(k0 + bkk) * ldb + col0 + bn);
        } else {
            if (col0 + lr < Np) bv = *(const float4*)(Bz + (long)(col0 + lr) * ldb + k0 + lk);
        }
        __syncthreads();
        As[lk+0][lr]=av.x; As[lk+1][lr]=av.y; As[lk+2][lr]=av.z; As[lk+3][lr]=av.w;
        if (!transB) {
            *(float4*)&Bs[bkk][bn] = bv;
        } else {
            Bs[lk+0][lr]=bv.x; Bs[lk+1][lr]=bv.y; Bs[lk+2][lr]=bv.z; Bs[lk+3][lr]=bv.w;
        }
        __syncthreads();
#pragma unroll
        for (int kk = 0; kk < 16; kk++) {
            float4 a4 = *(const float4*)&As[kk][ty * 4];
            float4 b4 = *(const float4*)&Bs[kk][tx * 4];
            float a[4] = {a4.x, a4.y, a4.z, a4.w};
            float b[4] = {b4.x, b4.y, b4.z, b4.w};
#pragma unroll
            for (int i = 0; i < 4; i++)
#pragma unroll
                for (int j = 0; j < 4; j++) acc[i][j] += a[i] * b[j];
        }
    }
#pragma unroll
    for (int i = 0; i < 4; i++) {
        int gr = row0 + ty * 4 + i;
        if (gr >= M) continue;
#pragma unroll
        for (int j = 0; j < 4; j++) {
            int gc = col0 + tx * 4 + j;
            if (gc < Np)
                Cz[(long)gr * ldc + gc] = acc[i][j] + (bias ? bias[gc] : 0.f);
        }
    }
}

// ---------------- weight packers ---------------------------------------------
__global__ void pack_qk_kernel(const float* __restrict__ wq, const float* __restrict__ wk,
                               const float* __restrict__ bq, const float* __restrict__ bk) {
    int idx = blockIdx.x * 256 + threadIdx.x;
    int k = idx >> 9, c = idx & 511;
    g_wqk[idx] = (c < 256) ? wq[k * 256 + c] : wk[k * 256 + c - 256];
    if (idx < 512) g_bqk[idx] = (idx < 256) ? bq[idx] : bk[idx - 256];
}

__global__ void pack_node_kernel(const float* __restrict__ wa, const float* __restrict__ wb,
                                 const float* __restrict__ wu, const float* __restrict__ wv,
                                 float* __restrict__ dst) {
    int idx = blockIdx.x * 256 + threadIdx.x;
    int k = idx >> 11, c = idx & 2047;
    const float* src = (c < 512) ? wa : (c < 1024) ? wb : (c < 1536) ? wu : wv;
    dst[idx] = src[k * 512 + (c & 511)];
}

// ---------------- BN1 ---------------------------------------------------------
__global__ void bn1_stats_kernel() {
    int n = blockIdx.x;
    int cl = threadIdx.x & 63;
    int q = threadIdx.x >> 6;
    int c = blockIdx.y * 64 + cl;
    float s1 = 0.f, s2 = 0.f;
    const float* base = g_h + (long)n * ND * Cch + c;
    for (int r = q; r < ND; r += 4) {
        float v = base[(long)r * Cch];
        s1 += v; s2 += v * v;
    }
    __shared__ float sm1[4][64], sm2[4][64];
    sm1[q][cl] = s1; sm2[q][cl] = s2;
    __syncthreads();
    if (q == 0) {
        s1 = sm1[0][cl] + sm1[1][cl] + sm1[2][cl] + sm1[3][cl];
        s2 = sm2[0][cl] + sm2[1][cl] + sm2[2][cl] + sm2[3][cl];
        float m = s1 / (float)ND;
        float var = s2 / (float)ND - m * m;
        g_bn1m[n * Cch + c] = m;
        g_bn1r[n * Cch + c] = rsqrtf(fmaxf(var, 0.f) + EPS_);
    }
}

__global__ void bn1_apply_kernel() {
    int n = blockIdx.x, b = blockIdx.y;
    int c4 = threadIdx.x;
    float4 m = ((const float4*)(g_bn1m + n * Cch))[c4];
    float4 r = ((const float4*)(g_bn1r + n * Cch))[c4];
    float4* hb = (float4*)(g_h + ((long)(n * Bb + b) * Dd) * Cch) + c4;
    float4 acc = {0.f, 0.f, 0.f, 0.f};
    for (int d = 0; d < Dd; d++) {
        float4 h = hb[(long)d * 128];
        float4 u;
        u.x = fmaxf((h.x - m.x) * r.x, 0.f);
        u.y = fmaxf((h.y - m.y) * r.y, 0.f);
        u.z = fmaxf((h.z - m.z) * r.z, 0.f);
        u.w = fmaxf((h.w - m.w) * r.w, 0.f);
        hb[(long)d * 128] = u;
        acc = f4add(acc, u);
    }
    float inv = 1.f / (float)Dd;
    acc.x *= inv; acc.y *= inv; acc.z *= inv; acc.w *= inv;
    ((float4*)(g_fv + (long)(b * Nn + n) * Cch))[c4] = acc;
}

// ---------------- attn1 softmax ----------------------------------------------
__global__ void softmaxP_kernel() {
    int z = blockIdx.x;
    int tid = threadIdx.x, w = tid >> 5, lane = tid & 31;
    const float* Sb = g_S1 + (long)z * Dd * Dd;
    float* Pb = g_P + (long)z * Dd * 64;
    for (int r = w; r < Dd; r += 8) {
        float v0 = (lane < Dd) ? Sb[r * Dd + lane] * SCALE_ : -1e30f;
        float v1 = (lane + 32 < Dd) ? Sb[r * Dd + lane + 32] * SCALE_ : -1e30f;
        float mx = fmaxf(v0, v1);
#pragma unroll
        for (int o = 16; o; o >>= 1) mx = fmaxf(mx, __shfl_xor_sync(0xffffffffu, mx, o));
        float e0 = (lane < Dd) ? expf(v0 - mx) : 0.f;
        float e1 = (lane + 32 < Dd) ? expf(v1 - mx) : 0.f;
        float s = e0 + e1;
#pragma unroll
        for (int o = 16; o; o >>= 1) s += __shfl_xor_sync(0xffffffffu, s, o);
        float inv = 1.f / s;
        if (lane < Dd) Pb[r * 64 + lane] = e0 * inv;
        Pb[r * 64 + lane + 32] = (lane + 32 < Dd) ? e1 * inv : 0.f;
    }
}

__global__ void bvp_kernel(const float* __restrict__ bv, const float* __restrict__ epw) {
    int c = threadIdx.x;
    float s = 0.f;
    for (int k = 0; k < Cch; k++) s += bv[k] * epw[k * Cch + c];
    g_bvp[c] = s;
}

// ---------------- attn2: per-(b,e) softmax + agg weights + Gram term ----------
__global__ void pg_kernel() {
    int e = blockIdx.x, b = blockIdx.y;
    int i = e / Nn, j = e % Nn;
    __shared__ float P[49][50];
    __shared__ float MVs[Dd * Dd];
    __shared__ float gpart[8];
    int tid = threadIdx.x, w = tid >> 5, lane = tid & 31;
    const float* MVg = g_MV + (long)(b * Nn + i) * (Dd * Dd);
    for (int t = tid; t < Dd * Dd; t += 256) MVs[t] = MVg[t];
    const float* Sb = g_S + (long)b * SQ * SQ + (long)(j * Dd) * SQ + i * Dd;
    for (int r = w; r < Dd; r += 8) {
        float v0 = (lane < Dd) ? Sb[r * SQ + lane] * SCALE_ : -1e30f;
        float v1 = (lane + 32 < Dd) ? Sb[r * SQ + lane + 32] * SCALE_ : -1e30f;
        float mx = fmaxf(v0, v1);
#pragma unroll
        for (int o = 16; o; o >>= 1) mx = fmaxf(mx, __shfl_xor_sync(0xffffffffu, mx, o));
        float e0 = (lane < Dd) ? expf(v0 - mx) : 0.f;
        float e1 = (lane + 32 < Dd) ? expf(v1 - mx) : 0.f;
        float s = e0 + e1;
#pragma unroll
        for (int o = 16; o; o >>= 1) s += __shfl_xor_sync(0xffffffffu, s, o);
        float inv = 1.f / s;
        if (lane < Dd) P[r][lane] = e0 * inv;
        if (lane + 32 < Dd) P[r][lane + 32] = e1 * inv;
    }
    __syncthreads();
    if (tid < Dd) {
        float s = 0.f;
        for (int r = 0; r < Dd; r++) s += P[r][tid];
        g_w[((long)b * Ee + e) * Dd + tid] = s * (1.f / (float)Dd);
    }
    float acc = 0.f;
    for (int r = w; r < Dd; r += 8) {
        float t0 = 0.f, t1 = 0.f;
        for (int bbk = 0; bbk < Dd; bbk++) {
            float p = P[r][bbk];
            t0 += MVs[lane * Dd + bbk] * p;
            if (lane + 32 < Dd) t1 += MVs[(lane + 32) * Dd + bbk] * p;
        }
        acc += P[r][lane] * t0;
        if (lane + 32 < Dd) acc += P[r][lane + 32] * t1;
    }
#pragma unroll
    for (int o = 16; o; o >>= 1) acc += __shfl_xor_sync(0xffffffffu, acc, o);
    if (lane == 0) gpart[w] = acc;
    __syncthreads();
    if (tid == 0) {
        float s = 0.f;
        for (int q = 0; q < 8; q++) s += gpart[q];
        g_gram[b * Ee + e] = s;
    }
}

// zbar = w^T Vp + epb ; stats via Gram identity. grid (12,8)=(i,b), block 512.
__global__ void zbar_stats_kernel(const float* __restrict__ ep_b) {
    int i = blockIdx.x, b = blockIdx.y;
    __shared__ float ws[Nn * Dd];
    __shared__ float red[16][26];
    int tid = threadIdx.x, lane = tid & 31, w = tid >> 5;
    for (int t = tid; t < Nn * Dd; t += 512) {
        int j = t / Dd, d2 = t % Dd;
        ws[t] = g_w[((long)b * Ee + i * Nn + j) * Dd + d2];
    }
    __syncthreads();
    float acc[Nn];
#pragma unroll
    for (int j = 0; j < Nn; j++) acc[j] = 0.f;
    const float* Vb = g_Vp + (long)((b * Nn + i) * Dd) * Cch;
    for (int d2 = 0; d2 < Dd; d2++) {
        float v = Vb[(long)d2 * Cch + tid];
#pragma unroll
        for (int j = 0; j < Nn; j++) acc[j] += ws[j * Dd + d2] * v;
    }
    float eb = ep_b[tid];
    float loc[25];
#pragma unroll
    for (int j = 0; j < Nn; j++) {
        float z = acc[j] + eb;
        g_zbar[((long)b * Ee + i * Nn + j) * Cch + tid] = z;
        loc[j] = z;
        loc[Nn + j] = eb * z;
    }
    loc[24] = eb * eb;
#pragma unroll
    for (int k = 0; k < 25; k++) {
        float v = loc[k];
#pragma unroll
        for (int o = 16; o; o >>= 1) v += __shfl_xor_sync(0xffffffffu, v, o);
        if (lane == 0) red[w][k] = v;
    }
    __syncthreads();
    if (tid < Nn) {
        float S = 0.f, T = 0.f, E = 0.f;
#pragma unroll
        for (int q = 0; q < 16; q++) {
            S += red[q][tid]; T += red[q][Nn + tid]; E += red[q][24];
        }
        int e = i * Nn + tid;
        g_ps1[b * Ee + e] = 49.f * S;
        g_ps2[b * Ee + e] = g_gram[b * Ee + e] + 98.f * T - 49.f * E;
    }
}

// ---------------- cosine adjacency mask --------------------------------------
__global__ void mask_kernel() {
    int b = blockIdx.x;
    __shared__ float sinv[Nn];
    __shared__ float adj[Ee];
    __shared__ float dis[Nn];
    int tid = threadIdx.x, w = tid >> 5, lane = tid & 31;
    for (int n = w; n < Nn; n += 8) {
        const float4* f = (const float4*)(g_fv + (long)(b * Nn + n) * Cch);
        float s = 0.f;
        for (int t = lane; t < 128; t += 32) {
            float4 x = f[t];
            s += x.x * x.x + x.y * x.y + x.z * x.z + x.w * x.w;
        }
#pragma unroll
        for (int o = 16; o; o >>= 1) s += __shfl_xor_sync(0xffffffffu, s, o);
        if (lane == 0) sinv[n] = 1.f / fmaxf(sqrtf(s), 1e-12f);
    }
    __syncthreads();
    for (int e = w; e < Ee; e += 8) {
        int i = e / Nn, jn = e % Nn;
        const float4* fi = (const float4*)(g_fv + (long)(b * Nn + i) * Cch);
        const float4* fj = (const float4*)(g_fv + (long)(b * Nn + jn) * Cch);
        float s = 0.f;
        for (int t = lane; t < 128; t += 32) {
            float4 a = fi[t], c = fj[t];
            s += a.x * c.x + a.y * c.y + a.z * c.z + a.w * c.w;
        }
#pragma unroll
        for (int o = 16; o; o >>= 1) s += __shfl_xor_sync(0xffffffffu, s, o);
        if (lane == 0) adj[e] = s * sinv[i] * sinv[jn];
    }
    __syncthreads();
    if (tid < Nn) {
        float s = 0.f;
        for (int jn = 0; jn < Nn; jn++) s += adj[tid * Nn + jn];
        dis[tid] = rsqrtf(s);
    }
    __syncthreads();
    if (tid < Ee) {
        int i = tid / Nn, jn = tid % Nn;
        g_mask[b * Ee + tid] = adj[tid] * dis[i] * dis[jn];
    }
}

// ---------------- edge BN + mask ---------------------------------------------
__global__ void edge_bn_mask_kernel() {
    int e = blockIdx.x;
    __shared__ float mrs[2];
    int tid = threadIdx.x;
    if (tid == 0) {
        float s1 = 0.f, s2 = 0.f;
        for (int b = 0; b < Bb; b++) { s1 += g_ps1[b * Ee + e]; s2 += g_ps2[b * Ee + e]; }
        float cnt = (float)(Bb * Dd * Cch);
        float m = s1 / cnt;
        float v = s2 / cnt - m * m;
        mrs[0] = m;
        mrs[1] = rsqrtf(fmaxf(v, 0.f) + EPS_);
    }
    __syncthreads();
    float m = mrs[0], r = mrs[1];
    for (int b = 0; b < Bb; b++) {
        float mk = g_mask[b * Ee + e] * r;
        const float4* zb = (const float4*)(g_zbar + (long)(b * Ee + e) * Cch);
        float4* fe = (float4*)(g_fe + (long)(b * Ee + e) * Cch);
        float4 z = zb[tid];
        fe[tid] = make_float4((z.x - m) * mk, (z.y - m) * mk, (z.z - m) * mk, (z.w - m) * mk);
    }
}

// ---------------- GNN layer pieces -------------------------------------------
__global__ void agg_bn_kernel() {
    int e = blockIdx.x;
    int i = e / Nn, jn = e % Nn;
    __shared__ float sm[32];
    int tid = threadIdx.x;
    float4 agg[Bb];
    float s1 = 0.f, s2 = 0.f;
#pragma unroll
    for (int b = 0; b < Bb; b++) {
        float4 va = ((const float4*)(g_xnode + (long)(b * Nn + i) * 2048))[tid];
        float4 vb = ((const float4*)(g_xnode + (long)(b * Nn + jn) * 2048 + 512))[tid];
        float4 vw = ((const float4*)(g_xw + (long)(b * Ee + e) * Cch))[tid];
        float4 v = f4add(f4add(va, vb), vw);
        agg[b] = v;
        s1 += v.x + v.y + v.z + v.w;
        s2 += v.x * v.x + v.y * v.y + v.z * v.z + v.w * v.w;
    }
    s1 = block_reduce_sum(s1, sm);
    s2 = block_reduce_sum(s2, sm);
    float cnt = (float)(Bb * Cch);
    float m = s1 / cnt;
    float r = rsqrtf(fmaxf(s2 / cnt - m * m, 0.f) + EPS_);
#pragma unroll
    for (int b = 0; b < Bb; b++) {
        float4* fe = (float4*)(g_fe + (long)(b * Ee + e) * Cch);
        float4 f = fe[tid], v = agg[b];
        f.x += fmaxf((v.x - m) * r, 0.f);
        f.y += fmaxf((v.y - m) * r, 0.f);
        f.z += fmaxf((v.z - m) * r, 0.f);
        f.w += fmaxf((v.w - m) * r, 0.f);
        fe[tid] = f;
    }
}

__global__ void softmax_msg_kernel() {
    int bi = blockIdx.x;
    int b = bi / Nn, i = bi % Nn;
    int tid = threadIdx.x;
    float4 v[Nn];
    float4 mx = {-1e30f, -1e30f, -1e30f, -1e30f};
#pragma unroll
    for (int jn = 0; jn < Nn; jn++) {
        float4 ed = ((const float4*)(g_fe + (long)(b * Ee + i * Nn + jn) * Cch))[tid];
        float4 s;
        s.x = 1.f / (1.f + expf(-ed.x));
        s.y = 1.f / (1.f + expf(-ed.y));
        s.z = 1.f / (1.f + expf(-ed.z));
        s.w = 1.f / (1.f + expf(-ed.w));
        v[jn] = s;
        mx.x = fmaxf(mx.x, s.x); mx.y = fmaxf(mx.y, s.y);
        mx.z = fmaxf(mx.z, s.z); mx.w = fmaxf(mx.w, s.w);
    }
    float4 sum = {0.f, 0.f, 0.f, 0.f};
#pragma unroll
    for (int jn = 0; jn < Nn; jn++) {
        v[jn].x = expf(v[jn].x - mx.x); v[jn].y = expf(v[jn].y - mx.y);
        v[jn].z = expf(v[jn].z - mx.z); v[jn].w = expf(v[jn].w - mx.w);
        sum = f4add(sum, v[jn]);
    }
    float4 acc = {0.f, 0.f, 0.f, 0.f};
#pragma unroll
    for (int jn = 0; jn < Nn; jn++) {
        float4 u = ((const float4*)(g_xnode + (long)(b * Nn + jn) * 2048 + 1536))[tid];
        acc.x += v[jn].x * u.x; acc.y += v[jn].y * u.y;
        acc.z += v[jn].z * u.z; acc.w += v[jn].w * u.w;
    }
    float4 o;
    o.x = acc.x / (sum.x * (float)Nn); o.y = acc.y / (sum.y * (float)Nn);
    o.z = acc.z / (sum.z * (float)Nn); o.w = acc.w / (sum.w * (float)Nn);
    ((float4*)(g_msg + (long)(b * Nn + i) * Cch))[tid] = o;
}

__global__ void node_bn_kernel() {
    int n = blockIdx.x;
    __shared__ float sm[32];
    int tid = threadIdx.x;
    float4 t[Bb];
    float s1 = 0.f, s2 = 0.f;
#pragma unroll
    for (int b = 0; b < Bb; b++) {
        float4 xu = ((const float4*)(g_xnode + (long)(b * Nn + n) * 2048 + 1024))[tid];
        float4 ms = ((const float4*)(g_msg + (long)(b * Nn + n) * Cch))[tid];
        float4 v = f4add(xu, ms);
        t[b] = v;
        s1 += v.x + v.y + v.z + v.w;
        s2 += v.x * v.x + v.y * v.y + v.z * v.z + v.w * v.w;
    }
    s1 = block_reduce_sum(s1, sm);
    s2 = block_reduce_sum(s2, sm);
    float cnt = (float)(Bb * Cch);
    float m = s1 / cnt;
    float r = rsqrtf(fmaxf(s2 / cnt - m * m, 0.f) + EPS_);
#pragma unroll
    for (int b = 0; b < Bb; b++) {
        float4* fv = (float4*)(g_fv + (long)(b * Nn + n) * Cch);
        float4 f = fv[tid], v = t[b];
        f.x = fmaxf(f.x + (v.x - m) * r, 0.f);
        f.y = fmaxf(f.y + (v.y - m) * r, 0.f);
        f.z = fmaxf(f.z + (v.z - m) * r, 0.f);
        f.w = fmaxf(f.w + (v.w - m) * r, 0.f);
        fv[tid] = f;
    }
}

// ---------------- classifier heads -------------------------------------------
__global__ void cls_kernel(const float* __restrict__ sc_w, float* __restrict__ out) {
    int bn = blockIdx.x;
    int n = bn % Nn;
    __shared__ float sm[32];
    int tid = threadIdx.x;
    float sf = 0.f, ff = 0.f, ss = 0.f;
    for (int c = tid; c < Cch; c += 128) {
        float f = g_fv[(long)bn * Cch + c];
        float s = fmaxf(sc_w[n * Cch + c], 0.f);
        sf += f * s; ff += f * f; ss += s * s;
    }
    sf = block_reduce_sum(sf, sm);
    ff = block_reduce_sum(ff, sm);
    ss = block_reduce_sum(ss, sm);
    if (tid == 0)
        out[bn] = sf / (fmaxf(sqrtf(ff), 1e-12f) * fmaxf(sqrtf(ss), 1e-12f));
}

__global__ void edgefc_kernel(const float* __restrict__ w, const float* __restrict__ bias,
                              float* __restrict__ out) {
    int row = blockIdx.x;
    int tid = threadIdx.x;
    int k = tid >> 5, lane = tid & 31;
    const float* f = g_fe + (long)row * Cch;
    float dot = 0.f;
    for (int c = lane; c < Cch; c += 32) dot += f[c] * w[c * 4 + k];
#pragma unroll
    for (int o = 16; o; o >>= 1) dot += __shfl_xor_sync(0xffffffffu, dot, o);
    if (lane == 0) out[96 + row * 4 + k] = dot + bias[k];
}

// ---------------- host driver -------------------------------------------------
extern "C" void kernel_launch(void* const* d_in, const int* in_sizes, int n_in,
                              void* d_out, int out_size) {
    const float* x      = (const float*)d_in[0];
    const float* Wc     = (const float*)d_in[1];
    const float* fam_wq = (const float*)d_in[3];
    const float* fam_bq = (const float*)d_in[4];
    const float* fam_wk = (const float*)d_in[5];
    const float* fam_wv = (const float*)d_in[7];
    const float* fam_bv = (const float*)d_in[8];
    const float* arm_wq = (const float*)d_in[9];
    const float* arm_bq = (const float*)d_in[10];
    const float* arm_wk = (const float*)d_in[11];
    const float* arm_bk = (const float*)d_in[12];
    const float* arm_wv = (const float*)d_in[13];
    const float* arm_bv = (const float*)d_in[14];
    const float* ep_w   = (const float*)d_in[15];
    const float* ep_b   = (const float*)d_in[16];
    const float* gw[10];
    for (int t = 0; t < 10; t++) gw[t] = (const float*)d_in[17 + t];
    const float* sc_w   = (const float*)d_in[27];
    const float* efc_w  = (const float*)d_in[28];
    const float* efc_b  = (const float*)d_in[29];
    float* out = (float*)d_out;

    float *p_h, *p_q1, *p_k1, *p_v1, *p_S1, *p_P, *p_f1, *p_QK2, *p_Vp, *p_Wvp, *p_bvp;
    float *p_wqk, *p_bqk, *p_S, *p_MV, *p_fv, *p_fe, *p_wnA, *p_wnB, *p_xnode, *p_xw;
    cudaGetSymbolAddress((void**)&p_h, g_h);
    cudaGetSymbolAddress((void**)&p_q1, g_q1);
    cudaGetSymbolAddress((void**)&p_k1, g_k1);
    cudaGetSymbolAddress((void**)&p_v1, g_v1);
    cudaGetSymbolAddress((void**)&p_S1, g_S1);
    cudaGetSymbolAddress((void**)&p_P, g_P);
    cudaGetSymbolAddress((void**)&p_f1, g_feat1);
    cudaGetSymbolAddress((void**)&p_QK2, g_QK2);
    cudaGetSymbolAddress((void**)&p_Vp, g_Vp);
    cudaGetSymbolAddress((void**)&p_Wvp, g_Wvp);
    cudaGetSymbolAddress((void**)&p_bvp, g_bvp);
    cudaGetSymbolAddress((void**)&p_wqk, g_wqk);
    cudaGetSymbolAddress((void**)&p_bqk, g_bqk);
    cudaGetSymbolAddress((void**)&p_S, g_S);
    cudaGetSymbolAddress((void**)&p_MV, g_MV);
    cudaGetSymbolAddress((void**)&p_fv, g_fv);
    cudaGetSymbolAddress((void**)&p_fe, g_fe);
    cudaGetSymbolAddress((void**)&p_wnA, g_wnodeA);
    cudaGetSymbolAddress((void**)&p_wnB, g_wnodeB);
    cudaGetSymbolAddress((void**)&p_xnode, g_xnode);
    cudaGetSymbolAddress((void**)&p_xw, g_xw);

    static cudaStream_t s1 = nullptr, s2 = nullptr;
    static cudaEvent_t evRoot, evPackQK, evK1, evV1, evWvpB, evFv, evFeat1,
                       evMV, evMask, evXn1, evNB1, evXn2;
    if (!s1) {
        cudaStreamCreateWithFlags(&s1, cudaStreamNonBlocking);
        cudaStreamCreateWithFlags(&s2, cudaStreamNonBlocking);
        cudaEventCreateWithFlags(&evRoot, cudaEventDisableTiming);
        cudaEventCreateWithFlags(&evPackQK, cudaEventDisableTiming);
        cudaEventCreateWithFlags(&evK1, cudaEventDisableTiming);
        cudaEventCreateWithFlags(&evV1, cudaEventDisableTiming);
        cudaEventCreateWithFlags(&evWvpB, cudaEventDisableTiming);
        cudaEventCreateWithFlags(&evFv, cudaEventDisableTiming);
        cudaEventCreateWithFlags(&evFeat1, cudaEventDisableTiming);
        cudaEventCreateWithFlags(&evMV, cudaEventDisableTiming);
        cudaEventCreateWithFlags(&evMask, cudaEventDisableTiming);
        cudaEventCreateWithFlags(&evXn1, cudaEventDisableTiming);
        cudaEventCreateWithFlags(&evNB1, cudaEventDisableTiming);
        cudaEventCreateWithFlags(&evXn2, cudaEventDisableTiming);
        cudaFuncSetAttribute(gemm_tc, cudaFuncAttributeMaxDynamicSharedMemorySize, GEMM_SMEM);
    }
    cudaStream_t s0 = 0;

    cudaEventRecord(evRoot, s0);

    // ---- s1: packing + K/V projections of attn1 ----
    cudaStreamWaitEvent(s1, evRoot, 0);
    pack_qk_kernel<<<1024, 256, 0, s1>>>(arm_wq, arm_wk, arm_bq, arm_bk);
    cudaEventRecord(evPackQK, s1);
    gemm_tc<<<dim3(2, 4, 1), 256, GEMM_SMEM, s1>>>(x, fam_wk, nullptr, p_k1, ND, Hh, Cch,
                                           Cch, Hh, Hh, 0, 0, 0, 0, 0, 0, 1, 0);
    cudaEventRecord(evK1, s1);
    gemm_tc<<<dim3(4, 4, 1), 256, GEMM_SMEM, s1>>>(x, fam_wv, fam_bv, p_v1, ND, Cch, Cch,
                                           Cch, Cch, Cch, 0, 0, 0, 0, 0, 0, 1, 0);
    cudaEventRecord(evV1, s1);

    // ---- s2: Wvp/bvp + node-weight packs ----
    cudaStreamWaitEvent(s2, evRoot, 0);
    gemm_tc<<<dim3(4, 4, 1), 256, GEMM_SMEM, s2>>>(arm_wv, ep_w, nullptr, p_Wvp, Cch, Cch, Cch,
                                           Cch, Cch, Cch, 0, 0, 0, 0, 0, 0, 1, 0);
    bvp_kernel<<<1, 512, 0, s2>>>(arm_bv, ep_w);
    cudaEventRecord(evWvpB, s2);
    pack_node_kernel<<<4096, 256, 0, s2>>>(gw[0], gw[1], gw[3], gw[4], p_wnA);
    pack_node_kernel<<<4096, 256, 0, s2>>>(gw[5], gw[6], gw[8], gw[9], p_wnB);

    // ---- s0 main chain: h -> BN1 ----
    gemm_tc<<<dim3(4, 4, 12), 256, GEMM_SMEM, s0>>>(x, Wc, nullptr, p_h, ND, Cch, Cch,
                                            Cch, Cch, Cch,
                                            0, 0, (long)Cch * Cch, 0, (long)ND * Cch, 0, 1, 0);
    bn1_stats_kernel<<<dim3(12, 8), 256, 0, s0>>>();
    bn1_apply_kernel<<<dim3(12, 8), 128, 0, s0>>>();
    cudaEventRecord(evFv, s0);

    // ---- s2: mask + xnode L1 ----
    cudaStreamWaitEvent(s2, evFv, 0);
    mask_kernel<<<Bb, 256, 0, s2>>>();
    cudaEventRecord(evMask, s2);
    gemm_tc<<<dim3(16, 1, 1), 256, GEMM_SMEM, s2>>>(p_fv, p_wnA, nullptr, p_xnode,
                                            Bb * Nn, 2048, Cch, Cch, 2048, 2048,
                                            0, 0, 0, 0, 0, 0, 1, 0);
    cudaEventRecord(evXn1, s2);

    // ---- s0: attn1 ----
    gemm_tc<<<dim3(2, 37, 1), 256, GEMM_SMEM, s0>>>(p_h, fam_wq, fam_bq, p_q1, RQ, Hh, Cch,
                                            Cch, Hh, Hh, 0, 0, 0, 0, 0, 0, 1, 0);
    cudaStreamWaitEvent(s0, evK1, 0);
    gemm_tc<<<dim3(1, 1, 96), 256, GEMM_SMEM, s0>>>(p_q1, p_k1, nullptr, p_S1, Dd, Dd, Hh,
                                            Hh, Hh, Dd,
                                            (long)8 * Dd * Hh, (long)Dd * Hh,
                                            0, (long)Dd * Hh,
                                            (long)8 * Dd * Dd, (long)Dd * Dd, 8, 1);
    softmaxP_kernel<<<96, 256, 0, s0>>>();
    cudaStreamWaitEvent(s0, evV1, 0);
    gemm_tc<<<dim3(4, 1, 96), 256, GEMM_SMEM, s0>>>(p_P, p_v1, nullptr, p_f1, Dd, Cch, 64,
                                            64, Cch, Cch,
                                            (long)8 * Dd * 64, (long)Dd * 64,
                                            0, (long)Dd * Cch,
                                            (long)Dd * Cch, (long)Nn * Dd * Cch, 8, 0);
    cudaEventRecord(evFeat1, s0);

    // ---- s1: Vp + MV Gram ----
    cudaStreamWaitEvent(s1, evFeat1, 0);
    cudaStreamWaitEvent(s1, evWvpB, 0);
    gemm_tc<<<dim3(4, 37, 1), 256, GEMM_SMEM, s1>>>(p_f1, p_Wvp, p_bvp, p_Vp, RQ, Cch, Cch,
                                            Cch, Cch, Cch, 0, 0, 0, 0, 0, 0, 1, 0);
    gemm64_kernel<<<dim3(1, 1, 96), 256, 0, s1>>>(p_Vp, p_Vp, nullptr, p_MV,
                                                  Dd, Dd, Cch, Cch, Cch, Dd,
                                                  (long)Dd * Cch, (long)Dd * Cch, (long)Dd * Dd, 1);
    cudaEventRecord(evMV, s1);

    // ---- s0: QK2 -> S -> pg -> zbar -> edge ----
    cudaStreamWaitEvent(s0, evPackQK, 0);
    gemm_tc<<<dim3(4, 37, 1), 256, GEMM_SMEM, s0>>>(p_f1, p_wqk, p_bqk, p_QK2, RQ, Cch, Cch,
                                            Cch, Cch, Cch, 0, 0, 0, 0, 0, 0, 1, 0);
    gemm_tc<<<dim3(5, 5, 8), 256, GEMM_SMEM, s0>>>(p_QK2, p_QK2 + 256, nullptr, p_S, SQ, SQ, Hh,
                                           Cch, Cch, SQ,
                                           (long)SQ * Cch, 0, (long)SQ * Cch, 0,
                                           (long)SQ * SQ, 0, 1, 1);
    cudaStreamWaitEvent(s0, evMV, 0);
    pg_kernel<<<dim3(Ee, Bb), 256, 0, s0>>>();
    zbar_stats_kernel<<<dim3(Nn, Bb), 512, 0, s0>>>(ep_b);
    cudaStreamWaitEvent(s0, evMask, 0);
    edge_bn_mask_kernel<<<Ee, 128, 0, s0>>>();

    // ---- GNN layer 1 ----
    gemm_tc<<<dim3(4, 9, 1), 256, GEMM_SMEM, s0>>>(p_fe, gw[2], nullptr, p_xw,
                                           Bb * Ee, Cch, Cch, Cch, Cch, Cch,
                                           0, 0, 0, 0, 0, 0, 1, 0);
    cudaStreamWaitEvent(s0, evXn1, 0);
    agg_bn_kernel<<<Ee, 128, 0, s0>>>();
    softmax_msg_kernel<<<Bb * Nn, 128, 0, s0>>>();
    node_bn_kernel<<<Nn, 128, 0, s0>>>();
    cudaEventRecord(evNB1, s0);

    // ---- GNN layer 2 ----
    cudaStreamWaitEvent(s1, evNB1, 0);
    gemm_tc<<<dim3(16, 1, 1), 256, GEMM_SMEM, s1>>>(p_fv, p_wnB, nullptr, p_xnode,
                                            Bb * Nn, 2048, Cch, Cch, 2048, 2048,
                                            0, 0, 0, 0, 0, 0, 1, 0);
    cudaEventRecord(evXn2, s1);
    gemm_tc<<<dim3(4, 9, 1), 256, GEMM_SMEM, s0>>>(p_fe, gw[7], nullptr, p_xw,
                                           Bb * Ee, Cch, Cch, Cch, Cch, Cch,
                                           0, 0, 0, 0, 0, 0, 1, 0);
    cudaStreamWaitEvent(s0, evXn2, 0);
    agg_bn_kernel<<<Ee, 128, 0, s0>>>();
    softmax_msg_kernel<<<Bb * Nn, 128, 0, s0>>>();
    node_bn_kernel<<<Nn, 128, 0, s0>>>();

    cls_kernel<<<Bb * Nn, 128, 0, s0>>>(sc_w, out);
    edgefc_kernel<<<Bb * Ee, 128, 0, s0>>>(efc_w, efc_b, out);
}